// round 1
// baseline (speedup 1.0000x reference)
#include <cuda_runtime.h>
#include <math.h>

// ---------------------------------------------------------------------------
// Problem constants
// ---------------------------------------------------------------------------
#define B_    32
#define TS_   16
#define TW_   16
#define SH_   256          // sentence LSTM hidden
#define WH_   512          // word LSTM hidden
#define DH_   1024         // decoder hidden
#define WDIM_ 300
#define CDIM_ 32
#define DIN_  512          // 2*SH
#define DQ_   1024         // 2*WH
#define DECIN_ 1544        // DIN + DQ + 8
#define NSEQ_ (B_*TS_)     // 512
#define NR_   (B_*TS_*TW_) // 8192

#define DEVBUF __device__ __align__(16)

// ---------------------------------------------------------------------------
// Scratch (static device buffers; no dynamic allocation anywhere)
// ---------------------------------------------------------------------------
DEVBUF float g_wembs[NSEQ_ * WDIM_];
DEVBUF float g_pre_s[2][NSEQ_ * 4 * SH_];
DEVBUF float g_sent_h0[NSEQ_ * 2 * SH_];
DEVBUF float g_sent_enc[NSEQ_ * 2 * SH_];
DEVBUF float g_char_in[NR_ * (CDIM_ + DIN_)];
DEVBUF float g_pre_w[2][NR_ * 4 * WH_];
DEVBUF float g_word_h0[NR_ * 2 * WH_];
DEVBUF float g_char_enc[NR_ * 2 * WH_];
DEVBUF float g_q[NR_ * DIN_];
DEVBUF float g_attn_enc[NR_ * DIN_];
DEVBUF float g_final[NR_ * DECIN_];
DEVBUF float g_pre_d[NR_ * 4 * DH_];
DEVBUF float g_dec_out[NR_ * DH_];
DEVBUF float g_hA[B_ * DH_];
DEVBUF float g_hB[B_ * DH_];
DEVBUF float g_cst[B_ * DH_];
// packed recurrent weights: P[k][j][gate] = Wh[(gate*H + j)*H + k]
DEVBUF float g_sWh0P[2][SH_ * SH_ * 4];
DEVBUF float g_sWh1P[2][SH_ * SH_ * 4];
DEVBUF float g_wWh0P[2][WH_ * WH_ * 4];
DEVBUF float g_wWh1P[2][WH_ * WH_ * 4];
DEVBUF float g_dWhP[DH_ * DH_ * 4];
DEVBUF float g_WqT[DIN_ * DQ_];  // [512][1024] = attn_Wq transposed

__device__ __forceinline__ float sigm(float x) { return 1.f / (1.f + expf(-x)); }

// ---------------------------------------------------------------------------
// Weight pack / transpose
// ---------------------------------------------------------------------------
__global__ void pack_wh_kernel(const float* __restrict__ Wh, float* __restrict__ out, int H) {
    int idx = blockIdx.x * 256 + threadIdx.x;
    int tot = 4 * H * H;
    if (idx >= tot) return;
    int g = idx & 3;
    int j = (idx >> 2) % H;
    int k = idx / (4 * H);
    out[idx] = Wh[(g * H + j) * H + k];
}

__global__ void transpose_wq_kernel(const float* __restrict__ Wq, float* __restrict__ out) {
    // Wq: [DQ_(1024), DIN_(512)] -> out [DIN_][DQ_]
    int idx = blockIdx.x * 256 + threadIdx.x;
    if (idx >= DIN_ * DQ_) return;
    int d = idx / DQ_;
    int q = idx % DQ_;
    out[idx] = Wq[q * DIN_ + d];
}

// ---------------------------------------------------------------------------
// Gathers / concat builders
// ---------------------------------------------------------------------------
__global__ void embed_sents_kernel(const int* __restrict__ sents,
                                   const float* __restrict__ word_embs,
                                   float* __restrict__ out) {
    int idx = blockIdx.x * 256 + threadIdx.x;
    if (idx >= NSEQ_ * WDIM_) return;
    int row = idx / WDIM_;
    int d = idx % WDIM_;
    out[idx] = word_embs[(size_t)sents[row] * WDIM_ + d];
}

__global__ void build_char_in_kernel(const int* __restrict__ words,
                                     const float* __restrict__ char_table,
                                     const float* __restrict__ sent_enc,
                                     float* __restrict__ out) {
    int r = blockIdx.x;           // 0..8191 : (b*TS+i)*TW + t
    int n = r / TW_;
    int w = words[r];
    float m = (w != 0) ? 1.f : 0.f;
    for (int col = threadIdx.x; col < CDIM_ + DIN_; col += blockDim.x) {
        float v;
        if (col < CDIM_) v = char_table[w * CDIM_ + col];
        else             v = sent_enc[n * DIN_ + (col - CDIM_)] * m;
        out[(size_t)r * (CDIM_ + DIN_) + col] = v;
    }
}

__global__ void build_final_kernel(const float* __restrict__ attn_enc,
                                   const float* __restrict__ char_enc,
                                   const int* __restrict__ labels,
                                   float* __restrict__ out) {
    int r = blockIdx.x;  // 0..8191, same flattening as (b*256 + i*16 + c)
    for (int col = threadIdx.x; col < DECIN_; col += blockDim.x) {
        float v;
        if (col < DIN_)        v = attn_enc[(size_t)r * DIN_ + col];
        else if (col < DIN_ + DQ_) v = char_enc[(size_t)r * DQ_ + (col - DIN_)];
        else                   v = (float)labels[r * 8 + (col - DIN_ - DQ_)];
        out[(size_t)r * DECIN_ + col] = v;
    }
}

__global__ void zero2_kernel(float* a, float* b, int n) {
    int i = blockIdx.x * 256 + threadIdx.x;
    if (i < n) { a[i] = 0.f; b[i] = 0.f; }
}

// ---------------------------------------------------------------------------
// SGEMM: C[M,N] = A[M,K] @ W[N,K]^T + bias
// BM=128, BN=64, BK=16, 256 threads, 8x4 microtile.
// Requires: M % 128 == 0, N % 64 == 0, K % 4 == 0 (all call sites comply).
// ---------------------------------------------------------------------------
__global__ void sgemm_bias_kernel(const float* __restrict__ A,
                                  const float* __restrict__ W,
                                  const float* __restrict__ bias,
                                  float* __restrict__ C,
                                  int M, int N, int K) {
    __shared__ __align__(16) float As[16][132];
    __shared__ __align__(16) float Ws[16][68];
    int tid = threadIdx.x;
    int m0 = blockIdx.y * 128;
    int n0 = blockIdx.x * 64;

    float acc[8][4];
#pragma unroll
    for (int i = 0; i < 8; ++i)
#pragma unroll
        for (int j = 0; j < 4; ++j) acc[i][j] = 0.f;

    int tm = (tid >> 4) << 3;  // 0..120 step 8
    int tn = (tid & 15) << 2;  // 0..60 step 4

    for (int kt = 0; kt < K; kt += 16) {
        // load A tile: 128 rows x 16 cols as float4
#pragma unroll
        for (int r = 0; r < 2; ++r) {
            int idx = tid + r * 256;      // 0..511
            int row = idx >> 2;
            int kq = idx & 3;
            int kbase = kt + kq * 4;
            float4 v = make_float4(0.f, 0.f, 0.f, 0.f);
            if (kbase < K)
                v = *reinterpret_cast<const float4*>(A + (size_t)(m0 + row) * K + kbase);
            As[kq * 4 + 0][row] = v.x;
            As[kq * 4 + 1][row] = v.y;
            As[kq * 4 + 2][row] = v.z;
            As[kq * 4 + 3][row] = v.w;
        }
        // load W tile: 64 rows x 16 cols
        {
            int row = tid >> 2;
            int kq = tid & 3;
            int kbase = kt + kq * 4;
            float4 v = make_float4(0.f, 0.f, 0.f, 0.f);
            if (kbase < K)
                v = *reinterpret_cast<const float4*>(W + (size_t)(n0 + row) * K + kbase);
            Ws[kq * 4 + 0][row] = v.x;
            Ws[kq * 4 + 1][row] = v.y;
            Ws[kq * 4 + 2][row] = v.z;
            Ws[kq * 4 + 3][row] = v.w;
        }
        __syncthreads();
#pragma unroll
        for (int kk = 0; kk < 16; ++kk) {
            float4 a0 = *reinterpret_cast<const float4*>(&As[kk][tm]);
            float4 a1 = *reinterpret_cast<const float4*>(&As[kk][tm + 4]);
            float4 bv = *reinterpret_cast<const float4*>(&Ws[kk][tn]);
            float av[8] = {a0.x, a0.y, a0.z, a0.w, a1.x, a1.y, a1.z, a1.w};
            float bw[4] = {bv.x, bv.y, bv.z, bv.w};
#pragma unroll
            for (int i = 0; i < 8; ++i)
#pragma unroll
                for (int j = 0; j < 4; ++j) acc[i][j] += av[i] * bw[j];
        }
        __syncthreads();
    }
#pragma unroll
    for (int i = 0; i < 8; ++i) {
        float* crow = C + (size_t)(m0 + tm + i) * N + n0 + tn;
#pragma unroll
        for (int j = 0; j < 4; ++j) {
            float bb = bias ? bias[n0 + tn + j] : 0.f;
            crow[j] = acc[i][j] + bb;
        }
    }
}

// ---------------------------------------------------------------------------
// Bidirectional LSTM recurrence over T steps.
// One block handles BSEQ independent sequences of one direction.
// blockDim.x == H. Thread j owns h-element j (gates i,f,g,o packed in WhP).
// pre: [Nseq, T, 4H] (gate preactivations incl. bias).
// out: [Nseq, T, 2H]; this direction writes columns [dir*H, dir*H+H).
// ---------------------------------------------------------------------------
template <int H, int BSEQ>
__global__ void lstm_rec_kernel(const float* __restrict__ pre0,
                                const float* __restrict__ pre1,
                                const float* __restrict__ WhP0,
                                const float* __restrict__ WhP1,
                                float* __restrict__ out, int T) {
    int dir = blockIdx.y;
    const float* pre = dir ? pre1 : pre0;
    const float4* WhP = reinterpret_cast<const float4*>(dir ? WhP1 : WhP0);
    int n0 = blockIdx.x * BSEQ;
    int j = threadIdx.x;

    __shared__ float sh[BSEQ * H];
    float cc[BSEQ];
    float ai[BSEQ], af[BSEQ], ag[BSEQ], ao[BSEQ];
#pragma unroll
    for (int s = 0; s < BSEQ; ++s) { cc[s] = 0.f; sh[s * H + j] = 0.f; }
    __syncthreads();

    for (int tt = 0; tt < T; ++tt) {
        int t = dir ? (T - 1 - tt) : tt;
#pragma unroll
        for (int s = 0; s < BSEQ; ++s) {
            const float* p = pre + ((size_t)(n0 + s) * T + t) * (4 * H);
            ai[s] = p[j];
            af[s] = p[H + j];
            ag[s] = p[2 * H + j];
            ao[s] = p[3 * H + j];
        }
#pragma unroll 2
        for (int k = 0; k < H; ++k) {
            float4 w = WhP[k * H + j];
#pragma unroll
            for (int s = 0; s < BSEQ; ++s) {
                float hk = sh[s * H + k];
                ai[s] += hk * w.x;
                af[s] += hk * w.y;
                ag[s] += hk * w.z;
                ao[s] += hk * w.w;
            }
        }
        __syncthreads();
#pragma unroll
        for (int s = 0; s < BSEQ; ++s) {
            float c = sigm(af[s]) * cc[s] + sigm(ai[s]) * tanhf(ag[s]);
            float hn = sigm(ao[s]) * tanhf(c);
            cc[s] = c;
            sh[s * H + j] = hn;
            out[((size_t)(n0 + s) * T + t) * (2 * H) + dir * H + j] = hn;
        }
        __syncthreads();
    }
}

// ---------------------------------------------------------------------------
// Decoder LSTM: one timestep. grid (32 j-blocks, 4 batch-groups), 256 threads.
// Thread owns (batch b, h-element j); 4 gates via packed float4 weights.
// Double-buffered h (h_in -> h_out), c owned exclusively.
// ---------------------------------------------------------------------------
__global__ void dec_step_kernel(const float* __restrict__ pre,
                                const float* __restrict__ WhP,
                                const float* __restrict__ h_in,
                                float* __restrict__ h_out,
                                float* __restrict__ c,
                                float* __restrict__ dout, int t) {
    const float4* W4 = reinterpret_cast<const float4*>(WhP);
    int jl = threadIdx.x & 31;
    int bl = threadIdx.x >> 5;
    int j = blockIdx.x * 32 + jl;
    int b = blockIdx.y * 8 + bl;

    const float* p = pre + ((size_t)b * 256 + t) * 4096;
    float ai = p[j], af = p[1024 + j], ag = p[2048 + j], ao = p[3072 + j];

    __shared__ float sh[8 * 256];
    for (int kc = 0; kc < 4; ++kc) {
        __syncthreads();
        for (int x = threadIdx.x; x < 8 * 256; x += 256)
            sh[x] = h_in[(blockIdx.y * 8 + (x >> 8)) * 1024 + kc * 256 + (x & 255)];
        __syncthreads();
        const float* shb = sh + bl * 256;
#pragma unroll 4
        for (int kk = 0; kk < 256; ++kk) {
            float hk = shb[kk];
            float4 w = W4[(kc * 256 + kk) * 1024 + j];
            ai += hk * w.x;
            af += hk * w.y;
            ag += hk * w.z;
            ao += hk * w.w;
        }
    }
    float cv = c[b * 1024 + j];
    cv = sigm(af) * cv + sigm(ai) * tanhf(ag);
    float hn = sigm(ao) * tanhf(cv);
    c[b * 1024 + j] = cv;
    h_out[b * 1024 + j] = hn;
    dout[((size_t)b * 256 + t) * 1024 + j] = hn;
}

// ---------------------------------------------------------------------------
// Attention: per (b,i) block: scores, masked softmax, weighted sum.
// ---------------------------------------------------------------------------
__global__ void attention_kernel(const float* __restrict__ q,
                                 const float* __restrict__ sent_enc,
                                 const int* __restrict__ words,
                                 float* __restrict__ attn_enc,
                                 float* __restrict__ map_out) {
    int bi = blockIdx.x;  // b*16 + i
    int b = bi >> 4;
    int i = bi & 15;
    __shared__ float se[16 * 513];
    __shared__ float sc[16][16];
    __shared__ float mp[16][16];
    __shared__ int kv[16];

    for (int x = threadIdx.x; x < 16 * 512; x += 256) {
        int jj = x >> 9, d = x & 511;
        se[jj * 513 + d] = sent_enc[((size_t)b * 16 + jj) * 512 + d];
    }
    if (threadIdx.x < 16) {
        int jj = threadIdx.x;
        int any = 0;
        for (int tw = 0; tw < 16; ++tw) any |= (words[(b * 16 + jj) * 16 + tw] != 0);
        kv[jj] = any;
    }
    __syncthreads();
    {
        int cdx = threadIdx.x >> 4, jj = threadIdx.x & 15;
        const float* qr = q + ((size_t)bi * 16 + cdx) * 512;
        const float* ser = se + jj * 513;
        float s = 0.f;
#pragma unroll 4
        for (int d = 0; d < 512; ++d) s += qr[d] * ser[d];
        sc[cdx][jj] = s;
    }
    __syncthreads();
    if (threadIdx.x < 16) {
        int cdx = threadIdx.x;
        float v[16];
        float m = -1e30f;
#pragma unroll
        for (int jj = 0; jj < 16; ++jj) {
            bool valid = (kv[jj] != 0) && (jj != i);
            v[jj] = valid ? sc[cdx][jj] : -1e9f;
            m = fmaxf(m, v[jj]);
        }
        float sum = 0.f;
#pragma unroll
        for (int jj = 0; jj < 16; ++jj) { v[jj] = expf(v[jj] - m); sum += v[jj]; }
        float inv = 1.f / sum;
#pragma unroll
        for (int jj = 0; jj < 16; ++jj) mp[cdx][jj] = v[jj] * inv;
    }
    __syncthreads();
    if (map_out != nullptr && threadIdx.x < 256) {
        int x = threadIdx.x;  // 16*16
        map_out[(size_t)bi * 256 + x] = mp[x >> 4][x & 15];
    }
    for (int x = threadIdx.x; x < 16 * 512; x += 256) {
        int cdx = x >> 9, d = x & 511;
        float s = 0.f;
#pragma unroll
        for (int jj = 0; jj < 16; ++jj) s += mp[cdx][jj] * se[jj * 513 + d];
        attn_enc[((size_t)bi * 16 + cdx) * 512 + d] = s;
    }
}

// ---------------------------------------------------------------------------
// Classifier: diac[m, n] = dec_out[m,:] @ cls_W[:, n] + cls_b[n]; n < 15
// ---------------------------------------------------------------------------
__global__ void classifier_kernel(const float* __restrict__ dec_out,
                                  const float* __restrict__ W,
                                  const float* __restrict__ bias,
                                  float* __restrict__ out) {
    int m = blockIdx.x * 16 + (threadIdx.x >> 4);
    int n = threadIdx.x & 15;
    if (n >= 15) return;
    const float* x = dec_out + (size_t)m * 1024;
    float s = bias[n];
#pragma unroll 4
    for (int k = 0; k < 1024; ++k) s += x[k] * W[k * 15 + n];
    out[(size_t)m * 15 + n] = s;
}

// ---------------------------------------------------------------------------
// Host launcher
// ---------------------------------------------------------------------------
static float* symf(const void* s) {
    void* p = nullptr;
    cudaGetSymbolAddress(&p, s);
    return (float*)p;
}

extern "C" void kernel_launch(void* const* d_in, const int* in_sizes, int n_in,
                              void* d_out, int out_size) {
    (void)in_sizes; (void)n_in;
    const int* sents = (const int*)d_in[0];
    const int* words = (const int*)d_in[1];
    const int* labels = (const int*)d_in[2];
    const float* word_embs = (const float*)d_in[3];
    const float* char_table = (const float*)d_in[4];
    const float* sWx0 = (const float*)d_in[5];
    const float* sWh0 = (const float*)d_in[6];
    const float* sb0 = (const float*)d_in[7];
    const float* sWx1 = (const float*)d_in[8];
    const float* sWh1 = (const float*)d_in[9];
    const float* sb1 = (const float*)d_in[10];
    const float* wWx0 = (const float*)d_in[11];
    const float* wWh0 = (const float*)d_in[12];
    const float* wb0 = (const float*)d_in[13];
    const float* wWx1 = (const float*)d_in[14];
    const float* wWh1 = (const float*)d_in[15];
    const float* wb1 = (const float*)d_in[16];
    const float* Wq = (const float*)d_in[17];
    const float* dWx = (const float*)d_in[18];
    const float* dWh = (const float*)d_in[19];
    const float* db = (const float*)d_in[20];
    const float* clsW = (const float*)d_in[21];
    const float* clsb = (const float*)d_in[22];
    float* out = (float*)d_out;

    float* wembs = symf(g_wembs);
    float* pre_s = symf(g_pre_s);
    float* sent_h0 = symf(g_sent_h0);
    float* sent_enc = symf(g_sent_enc);
    float* char_in = symf(g_char_in);
    float* pre_w = symf(g_pre_w);
    float* word_h0 = symf(g_word_h0);
    float* char_enc = symf(g_char_enc);
    float* qbuf = symf(g_q);
    float* attn_enc = symf(g_attn_enc);
    float* finalb = symf(g_final);
    float* pre_d = symf(g_pre_d);
    float* dec_out = symf(g_dec_out);
    float* hA = symf(g_hA);
    float* hB = symf(g_hB);
    float* cst = symf(g_cst);
    float* sWh0P = symf(g_sWh0P);
    float* sWh1P = symf(g_sWh1P);
    float* wWh0P = symf(g_wWh0P);
    float* wWh1P = symf(g_wWh1P);
    float* dWhP = symf(g_dWhP);
    float* WqT = symf(g_WqT);

    const int sPreStride = NSEQ_ * 4 * SH_;      // per-dir sentence pre
    const int wPreStride = NR_ * 4 * WH_;        // per-dir word pre
    const int sWhPStride = SH_ * SH_ * 4;
    const int wWhPStride = WH_ * WH_ * 4;

    // ---- weight packing / transposes ----
    {
        int tot = 4 * SH_ * SH_;
        pack_wh_kernel<<<(tot + 255) / 256, 256>>>(sWh0, sWh0P, SH_);
        pack_wh_kernel<<<(tot + 255) / 256, 256>>>(sWh0 + 4 * SH_ * SH_, sWh0P + sWhPStride, SH_);
        pack_wh_kernel<<<(tot + 255) / 256, 256>>>(sWh1, sWh1P, SH_);
        pack_wh_kernel<<<(tot + 255) / 256, 256>>>(sWh1 + 4 * SH_ * SH_, sWh1P + sWhPStride, SH_);
    }
    {
        int tot = 4 * WH_ * WH_;
        pack_wh_kernel<<<(tot + 255) / 256, 256>>>(wWh0, wWh0P, WH_);
        pack_wh_kernel<<<(tot + 255) / 256, 256>>>(wWh0 + 4 * WH_ * WH_, wWh0P + wWhPStride, WH_);
        pack_wh_kernel<<<(tot + 255) / 256, 256>>>(wWh1, wWh1P, WH_);
        pack_wh_kernel<<<(tot + 255) / 256, 256>>>(wWh1 + 4 * WH_ * WH_, wWh1P + wWhPStride, WH_);
    }
    {
        int tot = 4 * DH_ * DH_;
        pack_wh_kernel<<<(tot + 255) / 256, 256>>>(dWh, dWhP, DH_);
    }
    transpose_wq_kernel<<<(DIN_ * DQ_ + 255) / 256, 256>>>(Wq, WqT);

    // ---- sentence encoder ----
    embed_sents_kernel<<<(NSEQ_ * WDIM_ + 255) / 256, 256>>>(sents, word_embs, wembs);

    // layer 0: pre-gates GEMMs (M=512, N=1024, K=300)
    sgemm_bias_kernel<<<dim3(1024 / 64, 512 / 128), 256>>>(
        wembs, sWx0, sb0, pre_s, 512, 1024, 300);
    sgemm_bias_kernel<<<dim3(1024 / 64, 512 / 128), 256>>>(
        wembs, sWx0 + 4 * SH_ * WDIM_, sb0 + 4 * SH_, pre_s + sPreStride, 512, 1024, 300);
    lstm_rec_kernel<SH_, 8><<<dim3(B_ / 8, 2), SH_>>>(
        pre_s, pre_s + sPreStride, sWh0P, sWh0P + sWhPStride, sent_h0, TS_);

    // layer 1 (K=512)
    sgemm_bias_kernel<<<dim3(1024 / 64, 512 / 128), 256>>>(
        sent_h0, sWx1, sb1, pre_s, 512, 1024, 512);
    sgemm_bias_kernel<<<dim3(1024 / 64, 512 / 128), 256>>>(
        sent_h0, sWx1 + 4 * SH_ * (2 * SH_), sb1 + 4 * SH_, pre_s + sPreStride, 512, 1024, 512);
    lstm_rec_kernel<SH_, 8><<<dim3(B_ / 8, 2), SH_>>>(
        pre_s, pre_s + sPreStride, sWh1P, sWh1P + sWhPStride, sent_enc, TS_);

    // ---- char (word) encoder ----
    build_char_in_kernel<<<NR_, 256>>>(words, char_table, sent_enc, char_in);

    // word layer 0: M=8192, N=2048, K=544
    sgemm_bias_kernel<<<dim3(2048 / 64, 8192 / 128), 256>>>(
        char_in, wWx0, wb0, pre_w, 8192, 2048, 544);
    sgemm_bias_kernel<<<dim3(2048 / 64, 8192 / 128), 256>>>(
        char_in, wWx0 + 4 * WH_ * (CDIM_ + DIN_), wb0 + 4 * WH_, pre_w + wPreStride,
        8192, 2048, 544);
    lstm_rec_kernel<WH_, 8><<<dim3(NSEQ_ / 8, 2), WH_>>>(
        pre_w, pre_w + wPreStride, wWh0P, wWh0P + wWhPStride, word_h0, TW_);

    // word layer 1: K=1024 (reuse pre_w)
    sgemm_bias_kernel<<<dim3(2048 / 64, 8192 / 128), 256>>>(
        word_h0, wWx1, wb1, pre_w, 8192, 2048, 1024);
    sgemm_bias_kernel<<<dim3(2048 / 64, 8192 / 128), 256>>>(
        word_h0, wWx1 + 4 * WH_ * (2 * WH_), wb1 + 4 * WH_, pre_w + wPreStride,
        8192, 2048, 1024);
    lstm_rec_kernel<WH_, 8><<<dim3(NSEQ_ / 8, 2), WH_>>>(
        pre_w, pre_w + wPreStride, wWh1P, wWh1P + wWhPStride, char_enc, TW_);

    // ---- attention ----
    sgemm_bias_kernel<<<dim3(512 / 64, 8192 / 128), 256>>>(
        char_enc, WqT, nullptr, qbuf, 8192, 512, 1024);
    float* map_out = (out_size >= (NR_ * 15 + B_ * TS_ * TW_ * TS_)) ? (out + NR_ * 15) : nullptr;
    attention_kernel<<<NSEQ_, 256>>>(qbuf, sent_enc, words, attn_enc, map_out);

    // ---- decoder ----
    build_final_kernel<<<NR_, 256>>>(attn_enc, char_enc, labels, finalb);
    sgemm_bias_kernel<<<dim3(4096 / 64, 8192 / 128), 256>>>(
        finalb, dWx, db, pre_d, 8192, 4096, 1544);

    zero2_kernel<<<(B_ * DH_ + 255) / 256, 256>>>(hA, cst, B_ * DH_);
    for (int t = 0; t < TS_ * TW_; ++t) {
        float* hi = (t & 1) ? hB : hA;
        float* ho = (t & 1) ? hA : hB;
        dec_step_kernel<<<dim3(32, 4), 256>>>(pre_d, dWhP, hi, ho, cst, dec_out, t);
    }

    classifier_kernel<<<NR_ / 16, 256>>>(dec_out, clsW, clsb, out);
}

// round 2
// speedup vs baseline: 1.0522x; 1.0522x over previous
#include <cuda_runtime.h>
#include <math.h>

// ---------------------------------------------------------------------------
// Problem constants
// ---------------------------------------------------------------------------
#define B_    32
#define TS_   16
#define TW_   16
#define SH_   256          // sentence LSTM hidden
#define WH_   512          // word LSTM hidden
#define DH_   1024         // decoder hidden
#define WDIM_ 300
#define CDIM_ 32
#define DIN_  512          // 2*SH
#define DQ_   1024         // 2*WH
#define DECIN_ 1544        // DIN + DQ + 8
#define NSEQ_ (B_*TS_)     // 512
#define NR_   (B_*TS_*TW_) // 8192

#define DEVBUF __device__ __align__(16)

// ---------------------------------------------------------------------------
// Scratch (static device buffers; no dynamic allocation anywhere)
// ---------------------------------------------------------------------------
DEVBUF float g_wembs[NSEQ_ * WDIM_];
DEVBUF float g_pre_s[NSEQ_ * 2 * 4 * SH_];
DEVBUF float g_sent_h0[NSEQ_ * 2 * SH_];
DEVBUF float g_sent_enc[NSEQ_ * 2 * SH_];
DEVBUF float g_char_in[NR_ * (CDIM_ + DIN_)];
DEVBUF float g_pre_w[NR_ * 2 * 4 * WH_];
DEVBUF float g_word_h0[NR_ * 2 * WH_];
DEVBUF float g_char_enc[NR_ * 2 * WH_];
DEVBUF float g_q[NR_ * DIN_];
DEVBUF float g_attn_enc[NR_ * DIN_];
DEVBUF float g_final[NR_ * DECIN_];
DEVBUF float g_pre_d[NR_ * 4 * DH_];
DEVBUF float g_dec_out[NR_ * DH_];
DEVBUF float g_hA[B_ * DH_];
DEVBUF float g_hB[B_ * DH_];
DEVBUF float g_cst[B_ * DH_];
// packed recurrent weights: P[k][j][gate] = Wh[(gate*H + j)*H + k]
DEVBUF float g_sWh0P[2][SH_ * SH_ * 4];
DEVBUF float g_sWh1P[2][SH_ * SH_ * 4];
DEVBUF float g_wWh0P[2][WH_ * WH_ * 4];
DEVBUF float g_wWh1P[2][WH_ * WH_ * 4];
DEVBUF float g_dWhP[DH_ * DH_ * 4];
DEVBUF float g_WqT[DIN_ * DQ_];  // [512][1024] = attn_Wq transposed

__device__ __forceinline__ float sigm(float x) { return 1.f / (1.f + expf(-x)); }

// ---------------------------------------------------------------------------
// Weight pack / transpose
// ---------------------------------------------------------------------------
__global__ void pack_wh_kernel(const float* __restrict__ Wh, float* __restrict__ out, int H) {
    int idx = blockIdx.x * 256 + threadIdx.x;
    int tot = 4 * H * H;
    if (idx >= tot) return;
    int g = idx & 3;
    int j = (idx >> 2) % H;
    int k = idx / (4 * H);
    out[idx] = Wh[(g * H + j) * H + k];
}

__global__ void transpose_wq_kernel(const float* __restrict__ Wq, float* __restrict__ out) {
    // Wq: [DQ_(1024), DIN_(512)] -> out [DIN_][DQ_]
    int idx = blockIdx.x * 256 + threadIdx.x;
    if (idx >= DIN_ * DQ_) return;
    int d = idx / DQ_;
    int q = idx % DQ_;
    out[idx] = Wq[q * DIN_ + d];
}

// ---------------------------------------------------------------------------
// Gathers / concat builders
// ---------------------------------------------------------------------------
__global__ void embed_sents_kernel(const int* __restrict__ sents,
                                   const float* __restrict__ word_embs,
                                   float* __restrict__ out) {
    int idx = blockIdx.x * 256 + threadIdx.x;
    if (idx >= NSEQ_ * WDIM_) return;
    int row = idx / WDIM_;
    int d = idx % WDIM_;
    out[idx] = word_embs[(size_t)sents[row] * WDIM_ + d];
}

__global__ void build_char_in_kernel(const int* __restrict__ words,
                                     const float* __restrict__ char_table,
                                     const float* __restrict__ sent_enc,
                                     float* __restrict__ out) {
    int r = blockIdx.x;           // 0..8191 : (b*TS+i)*TW + t
    int n = r / TW_;
    int w = words[r];
    float m = (w != 0) ? 1.f : 0.f;
    for (int col = threadIdx.x; col < CDIM_ + DIN_; col += blockDim.x) {
        float v;
        if (col < CDIM_) v = char_table[w * CDIM_ + col];
        else             v = sent_enc[n * DIN_ + (col - CDIM_)] * m;
        out[(size_t)r * (CDIM_ + DIN_) + col] = v;
    }
}

__global__ void build_final_kernel(const float* __restrict__ attn_enc,
                                   const float* __restrict__ char_enc,
                                   const int* __restrict__ labels,
                                   float* __restrict__ out) {
    int r = blockIdx.x;  // 0..8191, same flattening as (b*256 + i*16 + c)
    for (int col = threadIdx.x; col < DECIN_; col += blockDim.x) {
        float v;
        if (col < DIN_)        v = attn_enc[(size_t)r * DIN_ + col];
        else if (col < DIN_ + DQ_) v = char_enc[(size_t)r * DQ_ + (col - DIN_)];
        else                   v = (float)labels[r * 8 + (col - DIN_ - DQ_)];
        out[(size_t)r * DECIN_ + col] = v;
    }
}

__global__ void zero2_kernel(float* a, float* b, int n) {
    int i = blockIdx.x * 256 + threadIdx.x;
    if (i < n) { a[i] = 0.f; b[i] = 0.f; }
}

// ---------------------------------------------------------------------------
// SGEMM: C[M,N] = A[M,K] @ W[N,K]^T + bias
// BM=128, BN=128, BK=8, 256 threads, 8x8 microtile (split 4+4 fragments),
// double-buffered smem. Requires M%128==0, N%128==0, K%4==0.
// ---------------------------------------------------------------------------
__global__ void __launch_bounds__(256) sgemm128_kernel(
    const float* __restrict__ A, const float* __restrict__ W,
    const float* __restrict__ bias, float* __restrict__ C,
    int M, int N, int K) {
    __shared__ __align__(16) float As[2][8][132];
    __shared__ __align__(16) float Bs[2][8][132];
    int tid = threadIdx.x;
    int m0 = blockIdx.y * 128;
    int n0 = blockIdx.x * 128;

    // global load mapping: each thread loads one float4 of A and one of W
    int grow = tid >> 1;            // 0..127
    int gk = (tid & 1) * 4;         // 0 or 4
    const float* Ap = A + (size_t)(m0 + grow) * K + gk;
    const float* Wp = W + (size_t)(n0 + grow) * K + gk;

    int tm4 = (tid >> 4) * 4;       // 0..60
    int tn4 = (tid & 15) * 4;       // 0..60

    float acc[8][8];
#pragma unroll
    for (int i = 0; i < 8; ++i)
#pragma unroll
        for (int j = 0; j < 8; ++j) acc[i][j] = 0.f;

    int nk = (K + 7) / 8;

    float4 pa, pb;
    // prologue load (kt = 0)
    pa = (gk < K) ? *reinterpret_cast<const float4*>(Ap)
                  : make_float4(0.f, 0.f, 0.f, 0.f);
    pb = (gk < K) ? *reinterpret_cast<const float4*>(Wp)
                  : make_float4(0.f, 0.f, 0.f, 0.f);
    As[0][gk + 0][grow] = pa.x; As[0][gk + 1][grow] = pa.y;
    As[0][gk + 2][grow] = pa.z; As[0][gk + 3][grow] = pa.w;
    Bs[0][gk + 0][grow] = pb.x; Bs[0][gk + 1][grow] = pb.y;
    Bs[0][gk + 2][grow] = pb.z; Bs[0][gk + 3][grow] = pb.w;
    __syncthreads();

    for (int it = 0; it < nk; ++it) {
        int buf = it & 1;
        bool more = (it + 1) < nk;
        if (more) {
            int kt = (it + 1) * 8;
            pa = (kt + gk < K) ? *reinterpret_cast<const float4*>(Ap + kt)
                               : make_float4(0.f, 0.f, 0.f, 0.f);
            pb = (kt + gk < K) ? *reinterpret_cast<const float4*>(Wp + kt)
                               : make_float4(0.f, 0.f, 0.f, 0.f);
        }
#pragma unroll
        for (int kk = 0; kk < 8; ++kk) {
            float4 a0 = *reinterpret_cast<const float4*>(&As[buf][kk][tm4]);
            float4 a1 = *reinterpret_cast<const float4*>(&As[buf][kk][tm4 + 64]);
            float4 b0 = *reinterpret_cast<const float4*>(&Bs[buf][kk][tn4]);
            float4 b1 = *reinterpret_cast<const float4*>(&Bs[buf][kk][tn4 + 64]);
            float av[8] = {a0.x, a0.y, a0.z, a0.w, a1.x, a1.y, a1.z, a1.w};
            float bv[8] = {b0.x, b0.y, b0.z, b0.w, b1.x, b1.y, b1.z, b1.w};
#pragma unroll
            for (int i = 0; i < 8; ++i)
#pragma unroll
                for (int j = 0; j < 8; ++j) acc[i][j] += av[i] * bv[j];
        }
        if (more) {
            int nb = buf ^ 1;
            As[nb][gk + 0][grow] = pa.x; As[nb][gk + 1][grow] = pa.y;
            As[nb][gk + 2][grow] = pa.z; As[nb][gk + 3][grow] = pa.w;
            Bs[nb][gk + 0][grow] = pb.x; Bs[nb][gk + 1][grow] = pb.y;
            Bs[nb][gk + 2][grow] = pb.z; Bs[nb][gk + 3][grow] = pb.w;
        }
        __syncthreads();
    }

    // epilogue
    float bb0[4] = {0.f, 0.f, 0.f, 0.f}, bb1[4] = {0.f, 0.f, 0.f, 0.f};
    if (bias) {
#pragma unroll
        for (int j = 0; j < 4; ++j) {
            bb0[j] = bias[n0 + tn4 + j];
            bb1[j] = bias[n0 + tn4 + 64 + j];
        }
    }
#pragma unroll
    for (int i = 0; i < 8; ++i) {
        int r = m0 + tm4 + (i & 3) + ((i >> 2) << 6);
        float4 v0 = make_float4(acc[i][0] + bb0[0], acc[i][1] + bb0[1],
                                acc[i][2] + bb0[2], acc[i][3] + bb0[3]);
        float4 v1 = make_float4(acc[i][4] + bb1[0], acc[i][5] + bb1[1],
                                acc[i][6] + bb1[2], acc[i][7] + bb1[3]);
        *reinterpret_cast<float4*>(C + (size_t)r * N + n0 + tn4) = v0;
        *reinterpret_cast<float4*>(C + (size_t)r * N + n0 + tn4 + 64) = v1;
    }
}

// ---------------------------------------------------------------------------
// Bidirectional LSTM recurrence over T steps.
// One block handles BSEQ sequences of one direction; blockDim.x == H.
// pre layout: [n][t][2][4H] (both dirs fused from one GEMM).
// h state in smem, layout [k][s] with padded stride PS.
// out: [n][t][2H], this direction writes cols [dir*H, dir*H+H).
// ---------------------------------------------------------------------------
template <int H, int BSEQ, int PS>
__global__ void lstm_rec_kernel(const float* __restrict__ pre,
                                const float* __restrict__ WhP, int whStride,
                                float* __restrict__ out, int T) {
    int dir = blockIdx.y;
    const float4* W4 = reinterpret_cast<const float4*>(WhP + (size_t)dir * whStride);
    int n0 = blockIdx.x * BSEQ;
    int j = threadIdx.x;

    __shared__ __align__(16) float sh[H * PS];
    float cc[BSEQ];
    float ai[BSEQ], af[BSEQ], ag[BSEQ], ao[BSEQ];
#pragma unroll
    for (int s = 0; s < BSEQ; ++s) { cc[s] = 0.f; sh[j * PS + s] = 0.f; }
    __syncthreads();

    for (int tt = 0; tt < T; ++tt) {
        int t = dir ? (T - 1 - tt) : tt;
#pragma unroll
        for (int s = 0; s < BSEQ; ++s) {
            const float* p = pre + (((size_t)(n0 + s) * T + t) * 2 + dir) * (4 * H);
            ai[s] = p[j];
            af[s] = p[H + j];
            ag[s] = p[2 * H + j];
            ao[s] = p[3 * H + j];
        }
#pragma unroll 4
        for (int k = 0; k < H; ++k) {
            float4 w = W4[k * H + j];
            if constexpr (BSEQ == 8) {
                float4 h0 = *reinterpret_cast<const float4*>(&sh[k * PS]);
                float4 h1 = *reinterpret_cast<const float4*>(&sh[k * PS + 4]);
                float hv[8] = {h0.x, h0.y, h0.z, h0.w, h1.x, h1.y, h1.z, h1.w};
#pragma unroll
                for (int s = 0; s < 8; ++s) {
                    ai[s] += hv[s] * w.x;
                    af[s] += hv[s] * w.y;
                    ag[s] += hv[s] * w.z;
                    ao[s] += hv[s] * w.w;
                }
            } else {
#pragma unroll
                for (int s = 0; s < BSEQ; ++s) {
                    float hk = sh[k * PS + s];
                    ai[s] += hk * w.x;
                    af[s] += hk * w.y;
                    ag[s] += hk * w.z;
                    ao[s] += hk * w.w;
                }
            }
        }
        __syncthreads();
#pragma unroll
        for (int s = 0; s < BSEQ; ++s) {
            float c = sigm(af[s]) * cc[s] + sigm(ai[s]) * tanhf(ag[s]);
            float hn = sigm(ao[s]) * tanhf(c);
            cc[s] = c;
            sh[j * PS + s] = hn;
            out[(((size_t)(n0 + s) * T + t)) * (2 * H) + dir * H + j] = hn;
        }
        __syncthreads();
    }
}

// ---------------------------------------------------------------------------
// Decoder LSTM: one timestep. grid (32 j-blocks, 4 batch-groups), 256 threads.
// ---------------------------------------------------------------------------
__global__ void dec_step_kernel(const float* __restrict__ pre,
                                const float* __restrict__ WhP,
                                const float* __restrict__ h_in,
                                float* __restrict__ h_out,
                                float* __restrict__ c,
                                float* __restrict__ dout, int t) {
    const float4* W4 = reinterpret_cast<const float4*>(WhP);
    int jl = threadIdx.x & 31;
    int bl = threadIdx.x >> 5;
    int j = blockIdx.x * 32 + jl;
    int b = blockIdx.y * 8 + bl;

    const float* p = pre + ((size_t)b * 256 + t) * 4096;
    float ai = p[j], af = p[1024 + j], ag = p[2048 + j], ao = p[3072 + j];

    __shared__ float sh[8 * 256];
    for (int kc = 0; kc < 4; ++kc) {
        __syncthreads();
        for (int x = threadIdx.x; x < 8 * 256; x += 256)
            sh[x] = h_in[(blockIdx.y * 8 + (x >> 8)) * 1024 + kc * 256 + (x & 255)];
        __syncthreads();
        const float* shb = sh + bl * 256;
#pragma unroll 4
        for (int kk = 0; kk < 256; ++kk) {
            float hk = shb[kk];
            float4 w = W4[(kc * 256 + kk) * 1024 + j];
            ai += hk * w.x;
            af += hk * w.y;
            ag += hk * w.z;
            ao += hk * w.w;
        }
    }
    float cv = c[b * 1024 + j];
    cv = sigm(af) * cv + sigm(ai) * tanhf(ag);
    float hn = sigm(ao) * tanhf(cv);
    c[b * 1024 + j] = cv;
    h_out[b * 1024 + j] = hn;
    dout[((size_t)b * 256 + t) * 1024 + j] = hn;
}

// ---------------------------------------------------------------------------
// Attention: per (b,i) block: scores, masked softmax, weighted sum.
// ---------------------------------------------------------------------------
__global__ void attention_kernel(const float* __restrict__ q,
                                 const float* __restrict__ sent_enc,
                                 const int* __restrict__ words,
                                 float* __restrict__ attn_enc,
                                 float* __restrict__ map_out) {
    int bi = blockIdx.x;  // b*16 + i
    int b = bi >> 4;
    int i = bi & 15;
    __shared__ float se[16 * 513];
    __shared__ float sc[16][16];
    __shared__ float mp[16][16];
    __shared__ int kv[16];

    for (int x = threadIdx.x; x < 16 * 512; x += 256) {
        int jj = x >> 9, d = x & 511;
        se[jj * 513 + d] = sent_enc[((size_t)b * 16 + jj) * 512 + d];
    }
    if (threadIdx.x < 16) {
        int jj = threadIdx.x;
        int any = 0;
        for (int tw = 0; tw < 16; ++tw) any |= (words[(b * 16 + jj) * 16 + tw] != 0);
        kv[jj] = any;
    }
    __syncthreads();
    {
        int cdx = threadIdx.x >> 4, jj = threadIdx.x & 15;
        const float* qr = q + ((size_t)bi * 16 + cdx) * 512;
        const float* ser = se + jj * 513;
        float s = 0.f;
#pragma unroll 4
        for (int d = 0; d < 512; ++d) s += qr[d] * ser[d];
        sc[cdx][jj] = s;
    }
    __syncthreads();
    if (threadIdx.x < 16) {
        int cdx = threadIdx.x;
        float v[16];
        float m = -1e30f;
#pragma unroll
        for (int jj = 0; jj < 16; ++jj) {
            bool valid = (kv[jj] != 0) && (jj != i);
            v[jj] = valid ? sc[cdx][jj] : -1e9f;
            m = fmaxf(m, v[jj]);
        }
        float sum = 0.f;
#pragma unroll
        for (int jj = 0; jj < 16; ++jj) { v[jj] = expf(v[jj] - m); sum += v[jj]; }
        float inv = 1.f / sum;
#pragma unroll
        for (int jj = 0; jj < 16; ++jj) mp[cdx][jj] = v[jj] * inv;
    }
    __syncthreads();
    if (map_out != nullptr && threadIdx.x < 256) {
        int x = threadIdx.x;  // 16*16
        map_out[(size_t)bi * 256 + x] = mp[x >> 4][x & 15];
    }
    for (int x = threadIdx.x; x < 16 * 512; x += 256) {
        int cdx = x >> 9, d = x & 511;
        float s = 0.f;
#pragma unroll
        for (int jj = 0; jj < 16; ++jj) s += mp[cdx][jj] * se[jj * 513 + d];
        attn_enc[((size_t)bi * 16 + cdx) * 512 + d] = s;
    }
}

// ---------------------------------------------------------------------------
// Classifier: diac[m, n] = dec_out[m,:] @ cls_W[:, n] + cls_b[n]; n < 15
// ---------------------------------------------------------------------------
__global__ void classifier_kernel(const float* __restrict__ dec_out,
                                  const float* __restrict__ W,
                                  const float* __restrict__ bias,
                                  float* __restrict__ out) {
    int m = blockIdx.x * 16 + (threadIdx.x >> 4);
    int n = threadIdx.x & 15;
    if (n >= 15) return;
    const float* x = dec_out + (size_t)m * 1024;
    float s = bias[n];
#pragma unroll 4
    for (int k = 0; k < 1024; ++k) s += x[k] * W[k * 15 + n];
    out[(size_t)m * 15 + n] = s;
}

// ---------------------------------------------------------------------------
// Host launcher
// ---------------------------------------------------------------------------
static float* symf(const void* s) {
    void* p = nullptr;
    cudaGetSymbolAddress(&p, s);
    return (float*)p;
}

extern "C" void kernel_launch(void* const* d_in, const int* in_sizes, int n_in,
                              void* d_out, int out_size) {
    (void)in_sizes; (void)n_in;
    const int* sents = (const int*)d_in[0];
    const int* words = (const int*)d_in[1];
    const int* labels = (const int*)d_in[2];
    const float* word_embs = (const float*)d_in[3];
    const float* char_table = (const float*)d_in[4];
    const float* sWx0 = (const float*)d_in[5];
    const float* sWh0 = (const float*)d_in[6];
    const float* sb0 = (const float*)d_in[7];
    const float* sWx1 = (const float*)d_in[8];
    const float* sWh1 = (const float*)d_in[9];
    const float* sb1 = (const float*)d_in[10];
    const float* wWx0 = (const float*)d_in[11];
    const float* wWh0 = (const float*)d_in[12];
    const float* wb0 = (const float*)d_in[13];
    const float* wWx1 = (const float*)d_in[14];
    const float* wWh1 = (const float*)d_in[15];
    const float* wb1 = (const float*)d_in[16];
    const float* Wq = (const float*)d_in[17];
    const float* dWx = (const float*)d_in[18];
    const float* dWh = (const float*)d_in[19];
    const float* db = (const float*)d_in[20];
    const float* clsW = (const float*)d_in[21];
    const float* clsb = (const float*)d_in[22];
    float* out = (float*)d_out;

    float* wembs = symf(g_wembs);
    float* pre_s = symf(g_pre_s);
    float* sent_h0 = symf(g_sent_h0);
    float* sent_enc = symf(g_sent_enc);
    float* char_in = symf(g_char_in);
    float* pre_w = symf(g_pre_w);
    float* word_h0 = symf(g_word_h0);
    float* char_enc = symf(g_char_enc);
    float* qbuf = symf(g_q);
    float* attn_enc = symf(g_attn_enc);
    float* finalb = symf(g_final);
    float* pre_d = symf(g_pre_d);
    float* dec_out = symf(g_dec_out);
    float* hA = symf(g_hA);
    float* hB = symf(g_hB);
    float* cst = symf(g_cst);
    float* sWh0P = symf(g_sWh0P);
    float* sWh1P = symf(g_sWh1P);
    float* wWh0P = symf(g_wWh0P);
    float* wWh1P = symf(g_wWh1P);
    float* dWhP = symf(g_dWhP);
    float* WqT = symf(g_WqT);

    const int sWhPStride = SH_ * SH_ * 4;
    const int wWhPStride = WH_ * WH_ * 4;

    // ---- weight packing / transposes ----
    {
        int tot = 4 * SH_ * SH_;
        pack_wh_kernel<<<(tot + 255) / 256, 256>>>(sWh0, sWh0P, SH_);
        pack_wh_kernel<<<(tot + 255) / 256, 256>>>(sWh0 + tot, sWh0P + sWhPStride, SH_);
        pack_wh_kernel<<<(tot + 255) / 256, 256>>>(sWh1, sWh1P, SH_);
        pack_wh_kernel<<<(tot + 255) / 256, 256>>>(sWh1 + tot, sWh1P + sWhPStride, SH_);
    }
    {
        int tot = 4 * WH_ * WH_;
        pack_wh_kernel<<<(tot + 255) / 256, 256>>>(wWh0, wWh0P, WH_);
        pack_wh_kernel<<<(tot + 255) / 256, 256>>>(wWh0 + tot, wWh0P + wWhPStride, WH_);
        pack_wh_kernel<<<(tot + 255) / 256, 256>>>(wWh1, wWh1P, WH_);
        pack_wh_kernel<<<(tot + 255) / 256, 256>>>(wWh1 + tot, wWh1P + wWhPStride, WH_);
    }
    {
        int tot = 4 * DH_ * DH_;
        pack_wh_kernel<<<(tot + 255) / 256, 256>>>(dWh, dWhP, DH_);
    }
    transpose_wq_kernel<<<(DIN_ * DQ_ + 255) / 256, 256>>>(Wq, WqT);

    // ---- sentence encoder ----
    embed_sents_kernel<<<(NSEQ_ * WDIM_ + 255) / 256, 256>>>(sents, word_embs, wembs);

    // layer 0: fused both dirs, M=512, N=2048, K=300
    sgemm128_kernel<<<dim3(2048 / 128, 512 / 128), 256>>>(
        wembs, sWx0, sb0, pre_s, 512, 2048, 300);
    lstm_rec_kernel<SH_, 2, 2><<<dim3(B_ / 2, 2), SH_>>>(
        pre_s, sWh0P, sWhPStride, sent_h0, TS_);

    // layer 1 (K=512)
    sgemm128_kernel<<<dim3(2048 / 128, 512 / 128), 256>>>(
        sent_h0, sWx1, sb1, pre_s, 512, 2048, 512);
    lstm_rec_kernel<SH_, 2, 2><<<dim3(B_ / 2, 2), SH_>>>(
        pre_s, sWh1P, sWhPStride, sent_enc, TS_);

    // ---- char (word) encoder ----
    build_char_in_kernel<<<NR_, 256>>>(words, char_table, sent_enc, char_in);

    // word layer 0: fused dirs, M=8192, N=4096, K=544
    sgemm128_kernel<<<dim3(4096 / 128, 8192 / 128), 256>>>(
        char_in, wWx0, wb0, pre_w, 8192, 4096, 544);
    lstm_rec_kernel<WH_, 8, 12><<<dim3(NSEQ_ / 8, 2), WH_>>>(
        pre_w, wWh0P, wWhPStride, word_h0, TW_);

    // word layer 1: K=1024
    sgemm128_kernel<<<dim3(4096 / 128, 8192 / 128), 256>>>(
        word_h0, wWx1, wb1, pre_w, 8192, 4096, 1024);
    lstm_rec_kernel<WH_, 8, 12><<<dim3(NSEQ_ / 8, 2), WH_>>>(
        pre_w, wWh1P, wWhPStride, char_enc, TW_);

    // ---- attention ----
    sgemm128_kernel<<<dim3(512 / 128, 8192 / 128), 256>>>(
        char_enc, WqT, nullptr, qbuf, 8192, 512, 1024);
    float* map_out = (out_size >= (NR_ * 15 + B_ * TS_ * TW_ * TS_)) ? (out + NR_ * 15) : nullptr;
    attention_kernel<<<NSEQ_, 256>>>(qbuf, sent_enc, words, attn_enc, map_out);

    // ---- decoder ----
    build_final_kernel<<<NR_, 256>>>(attn_enc, char_enc, labels, finalb);
    sgemm128_kernel<<<dim3(4096 / 128, 8192 / 128), 256>>>(
        finalb, dWx, db, pre_d, 8192, 4096, 1544);

    zero2_kernel<<<(B_ * DH_ + 255) / 256, 256>>>(hA, cst, B_ * DH_);
    for (int t = 0; t < TS_ * TW_; ++t) {
        float* hi = (t & 1) ? hB : hA;
        float* ho = (t & 1) ? hA : hB;
        dec_step_kernel<<<dim3(32, 4), 256>>>(pre_d, dWhP, hi, ho, cst, dec_out, t);
    }

    classifier_kernel<<<NR_ / 16, 256>>>(dec_out, clsW, clsb, out);
}

// round 3
// speedup vs baseline: 1.0532x; 1.0009x over previous
#include <cuda_runtime.h>
#include <math.h>

// ---------------------------------------------------------------------------
// Problem constants
// ---------------------------------------------------------------------------
#define B_    32
#define TS_   16
#define TW_   16
#define SH_   256          // sentence LSTM hidden
#define WH_   512          // word LSTM hidden
#define DH_   1024         // decoder hidden
#define WDIM_ 300
#define CDIM_ 32
#define DIN_  512          // 2*SH
#define DQ_   1024         // 2*WH
#define DECIN_ 1544        // DIN + DQ + 8
#define NSEQ_ (B_*TS_)     // 512
#define NR_   (B_*TS_*TW_) // 8192

#define DEVBUF __device__ __align__(16)

// ---------------------------------------------------------------------------
// Scratch (static device buffers; no dynamic allocation anywhere)
// ---------------------------------------------------------------------------
DEVBUF float g_wembs[NSEQ_ * WDIM_];
DEVBUF float g_pre_s[NSEQ_ * 2 * 4 * SH_];
DEVBUF float g_sent_h0[NSEQ_ * 2 * SH_];
DEVBUF float g_sent_enc[NSEQ_ * 2 * SH_];
DEVBUF float g_char_in[NR_ * (CDIM_ + DIN_)];
DEVBUF float g_pre_w[NR_ * 2 * 4 * WH_];
DEVBUF float g_word_h0[NR_ * 2 * WH_];
DEVBUF float g_char_enc[NR_ * 2 * WH_];
DEVBUF float g_q[NR_ * DIN_];
DEVBUF float g_attn_enc[NR_ * DIN_];
DEVBUF float g_final[NR_ * DECIN_];
DEVBUF float g_pre_d[NR_ * 4 * DH_];
DEVBUF float g_dec_out[NR_ * DH_];
DEVBUF float g_hA[B_ * DH_];
DEVBUF float g_hB[B_ * DH_];
DEVBUF float g_cst[B_ * DH_];
// packed recurrent weights: P[k][j][gate] = Wh[(gate*H + j)*H + k]
DEVBUF float g_sWh0P[2][SH_ * SH_ * 4];
DEVBUF float g_sWh1P[2][SH_ * SH_ * 4];
DEVBUF float g_wWh0P[2][WH_ * WH_ * 4];
DEVBUF float g_wWh1P[2][WH_ * WH_ * 4];
DEVBUF float g_dWhP[DH_ * DH_ * 4];
DEVBUF float g_WqT[DIN_ * DQ_];  // [512][1024] = attn_Wq transposed

__device__ __forceinline__ float sigm(float x) { return 1.f / (1.f + expf(-x)); }

// ---------------------------------------------------------------------------
// Weight pack / transpose
// ---------------------------------------------------------------------------
__global__ void pack_wh_kernel(const float* __restrict__ Wh, float* __restrict__ out, int H) {
    int idx = blockIdx.x * 256 + threadIdx.x;
    int tot = 4 * H * H;
    if (idx >= tot) return;
    int g = idx & 3;
    int j = (idx >> 2) % H;
    int k = idx / (4 * H);
    out[idx] = Wh[(g * H + j) * H + k];
}

__global__ void transpose_wq_kernel(const float* __restrict__ Wq, float* __restrict__ out) {
    // Wq: [DQ_(1024), DIN_(512)] -> out [DIN_][DQ_]
    int idx = blockIdx.x * 256 + threadIdx.x;
    if (idx >= DIN_ * DQ_) return;
    int d = idx / DQ_;
    int q = idx % DQ_;
    out[idx] = Wq[q * DIN_ + d];
}

// ---------------------------------------------------------------------------
// Gathers / concat builders
// ---------------------------------------------------------------------------
__global__ void embed_sents_kernel(const int* __restrict__ sents,
                                   const float* __restrict__ word_embs,
                                   float* __restrict__ out) {
    int idx = blockIdx.x * 256 + threadIdx.x;
    if (idx >= NSEQ_ * WDIM_) return;
    int row = idx / WDIM_;
    int d = idx % WDIM_;
    out[idx] = word_embs[(size_t)sents[row] * WDIM_ + d];
}

__global__ void build_char_in_kernel(const int* __restrict__ words,
                                     const float* __restrict__ char_table,
                                     const float* __restrict__ sent_enc,
                                     float* __restrict__ out) {
    int r = blockIdx.x;           // 0..8191 : (b*TS+i)*TW + t
    int n = r / TW_;
    int w = words[r];
    float m = (w != 0) ? 1.f : 0.f;
    for (int col = threadIdx.x; col < CDIM_ + DIN_; col += blockDim.x) {
        float v;
        if (col < CDIM_) v = char_table[w * CDIM_ + col];
        else             v = sent_enc[n * DIN_ + (col - CDIM_)] * m;
        out[(size_t)r * (CDIM_ + DIN_) + col] = v;
    }
}

__global__ void build_final_kernel(const float* __restrict__ attn_enc,
                                   const float* __restrict__ char_enc,
                                   const int* __restrict__ labels,
                                   float* __restrict__ out) {
    int r = blockIdx.x;  // 0..8191, same flattening as (b*256 + i*16 + c)
    for (int col = threadIdx.x; col < DECIN_; col += blockDim.x) {
        float v;
        if (col < DIN_)        v = attn_enc[(size_t)r * DIN_ + col];
        else if (col < DIN_ + DQ_) v = char_enc[(size_t)r * DQ_ + (col - DIN_)];
        else                   v = (float)labels[r * 8 + (col - DIN_ - DQ_)];
        out[(size_t)r * DECIN_ + col] = v;
    }
}

__global__ void zero2_kernel(float* a, float* b, int n) {
    int i = blockIdx.x * 256 + threadIdx.x;
    if (i < n) { a[i] = 0.f; b[i] = 0.f; }
}

// ---------------------------------------------------------------------------
// SGEMM: C[M,N] = A[M,K] @ W[N,K]^T + bias
// BM=128, BN=128, BK=8, 256 threads, 8x8 microtile (split 4+4 fragments),
// double-buffered smem. Requires M%128==0, N%128==0, K%4==0.
// ---------------------------------------------------------------------------
__global__ void __launch_bounds__(256) sgemm128_kernel(
    const float* __restrict__ A, const float* __restrict__ W,
    const float* __restrict__ bias, float* __restrict__ C,
    int M, int N, int K) {
    __shared__ __align__(16) float As[2][8][132];
    __shared__ __align__(16) float Bs[2][8][132];
    int tid = threadIdx.x;
    int m0 = blockIdx.y * 128;
    int n0 = blockIdx.x * 128;

    // global load mapping: each thread loads one float4 of A and one of W
    int grow = tid >> 1;            // 0..127
    int gk = (tid & 1) * 4;         // 0 or 4
    const float* Ap = A + (size_t)(m0 + grow) * K + gk;
    const float* Wp = W + (size_t)(n0 + grow) * K + gk;

    int tm4 = (tid >> 4) * 4;       // 0..60
    int tn4 = (tid & 15) * 4;       // 0..60

    float acc[8][8];
#pragma unroll
    for (int i = 0; i < 8; ++i)
#pragma unroll
        for (int j = 0; j < 8; ++j) acc[i][j] = 0.f;

    int nk = (K + 7) / 8;

    float4 pa, pb;
    // prologue load (kt = 0)
    pa = (gk < K) ? *reinterpret_cast<const float4*>(Ap)
                  : make_float4(0.f, 0.f, 0.f, 0.f);
    pb = (gk < K) ? *reinterpret_cast<const float4*>(Wp)
                  : make_float4(0.f, 0.f, 0.f, 0.f);
    As[0][gk + 0][grow] = pa.x; As[0][gk + 1][grow] = pa.y;
    As[0][gk + 2][grow] = pa.z; As[0][gk + 3][grow] = pa.w;
    Bs[0][gk + 0][grow] = pb.x; Bs[0][gk + 1][grow] = pb.y;
    Bs[0][gk + 2][grow] = pb.z; Bs[0][gk + 3][grow] = pb.w;
    __syncthreads();

    for (int it = 0; it < nk; ++it) {
        int buf = it & 1;
        bool more = (it + 1) < nk;
        if (more) {
            int kt = (it + 1) * 8;
            pa = (kt + gk < K) ? *reinterpret_cast<const float4*>(Ap + kt)
                               : make_float4(0.f, 0.f, 0.f, 0.f);
            pb = (kt + gk < K) ? *reinterpret_cast<const float4*>(Wp + kt)
                               : make_float4(0.f, 0.f, 0.f, 0.f);
        }
#pragma unroll
        for (int kk = 0; kk < 8; ++kk) {
            float4 a0 = *reinterpret_cast<const float4*>(&As[buf][kk][tm4]);
            float4 a1 = *reinterpret_cast<const float4*>(&As[buf][kk][tm4 + 64]);
            float4 b0 = *reinterpret_cast<const float4*>(&Bs[buf][kk][tn4]);
            float4 b1 = *reinterpret_cast<const float4*>(&Bs[buf][kk][tn4 + 64]);
            float av[8] = {a0.x, a0.y, a0.z, a0.w, a1.x, a1.y, a1.z, a1.w};
            float bv[8] = {b0.x, b0.y, b0.z, b0.w, b1.x, b1.y, b1.z, b1.w};
#pragma unroll
            for (int i = 0; i < 8; ++i)
#pragma unroll
                for (int j = 0; j < 8; ++j) acc[i][j] += av[i] * bv[j];
        }
        if (more) {
            int nb = buf ^ 1;
            As[nb][gk + 0][grow] = pa.x; As[nb][gk + 1][grow] = pa.y;
            As[nb][gk + 2][grow] = pa.z; As[nb][gk + 3][grow] = pa.w;
            Bs[nb][gk + 0][grow] = pb.x; Bs[nb][gk + 1][grow] = pb.y;
            Bs[nb][gk + 2][grow] = pb.z; Bs[nb][gk + 3][grow] = pb.w;
        }
        __syncthreads();
    }

    // epilogue
    float bb0[4] = {0.f, 0.f, 0.f, 0.f}, bb1[4] = {0.f, 0.f, 0.f, 0.f};
    if (bias) {
#pragma unroll
        for (int j = 0; j < 4; ++j) {
            bb0[j] = bias[n0 + tn4 + j];
            bb1[j] = bias[n0 + tn4 + 64 + j];
        }
    }
#pragma unroll
    for (int i = 0; i < 8; ++i) {
        int r = m0 + tm4 + (i & 3) + ((i >> 2) << 6);
        float4 v0 = make_float4(acc[i][0] + bb0[0], acc[i][1] + bb0[1],
                                acc[i][2] + bb0[2], acc[i][3] + bb0[3]);
        float4 v1 = make_float4(acc[i][4] + bb1[0], acc[i][5] + bb1[1],
                                acc[i][6] + bb1[2], acc[i][7] + bb1[3]);
        *reinterpret_cast<float4*>(C + (size_t)r * N + n0 + tn4) = v0;
        *reinterpret_cast<float4*>(C + (size_t)r * N + n0 + tn4 + 64) = v1;
    }
}

// ---------------------------------------------------------------------------
// Bidirectional LSTM recurrence over T steps.
// One block handles BSEQ sequences of one direction; blockDim.x == H.
// pre layout: [n][t][2][4H] (both dirs fused from one GEMM).
// h state in smem, layout [k][s] with padded stride PS.
// out: [n][t][2H], this direction writes cols [dir*H, dir*H+H).
// ---------------------------------------------------------------------------
template <int H, int BSEQ, int PS>
__global__ void lstm_rec_kernel(const float* __restrict__ pre,
                                const float* __restrict__ WhP, int whStride,
                                float* __restrict__ out, int T) {
    int dir = blockIdx.y;
    const float4* W4 = reinterpret_cast<const float4*>(WhP + (size_t)dir * whStride);
    int n0 = blockIdx.x * BSEQ;
    int j = threadIdx.x;

    __shared__ __align__(16) float sh[H * PS];
    float cc[BSEQ];
    float ai[BSEQ], af[BSEQ], ag[BSEQ], ao[BSEQ];
#pragma unroll
    for (int s = 0; s < BSEQ; ++s) { cc[s] = 0.f; sh[j * PS + s] = 0.f; }
    __syncthreads();

    for (int tt = 0; tt < T; ++tt) {
        int t = dir ? (T - 1 - tt) : tt;
#pragma unroll
        for (int s = 0; s < BSEQ; ++s) {
            const float* p = pre + (((size_t)(n0 + s) * T + t) * 2 + dir) * (4 * H);
            ai[s] = p[j];
            af[s] = p[H + j];
            ag[s] = p[2 * H + j];
            ao[s] = p[3 * H + j];
        }
#pragma unroll 4
        for (int k = 0; k < H; ++k) {
            float4 w = W4[k * H + j];
            if constexpr (BSEQ == 8) {
                float4 h0 = *reinterpret_cast<const float4*>(&sh[k * PS]);
                float4 h1 = *reinterpret_cast<const float4*>(&sh[k * PS + 4]);
                float hv[8] = {h0.x, h0.y, h0.z, h0.w, h1.x, h1.y, h1.z, h1.w};
#pragma unroll
                for (int s = 0; s < 8; ++s) {
                    ai[s] += hv[s] * w.x;
                    af[s] += hv[s] * w.y;
                    ag[s] += hv[s] * w.z;
                    ao[s] += hv[s] * w.w;
                }
            } else {
#pragma unroll
                for (int s = 0; s < BSEQ; ++s) {
                    float hk = sh[k * PS + s];
                    ai[s] += hk * w.x;
                    af[s] += hk * w.y;
                    ag[s] += hk * w.z;
                    ao[s] += hk * w.w;
                }
            }
        }
        __syncthreads();
#pragma unroll
        for (int s = 0; s < BSEQ; ++s) {
            float c = sigm(af[s]) * cc[s] + sigm(ai[s]) * tanhf(ag[s]);
            float hn = sigm(ao[s]) * tanhf(c);
            cc[s] = c;
            sh[j * PS + s] = hn;
            out[(((size_t)(n0 + s) * T + t)) * (2 * H) + dir * H + j] = hn;
        }
        __syncthreads();
    }
}

// ---------------------------------------------------------------------------
// Decoder LSTM: one timestep. grid (32 j-blocks, 4 batch-groups), 256 threads.
// ---------------------------------------------------------------------------
__global__ void dec_step_kernel(const float* __restrict__ pre,
                                const float* __restrict__ WhP,
                                const float* __restrict__ h_in,
                                float* __restrict__ h_out,
                                float* __restrict__ c,
                                float* __restrict__ dout, int t) {
    const float4* W4 = reinterpret_cast<const float4*>(WhP);
    int jl = threadIdx.x & 31;
    int bl = threadIdx.x >> 5;
    int j = blockIdx.x * 32 + jl;
    int b = blockIdx.y * 8 + bl;

    const float* p = pre + ((size_t)b * 256 + t) * 4096;
    float ai = p[j], af = p[1024 + j], ag = p[2048 + j], ao = p[3072 + j];

    __shared__ float sh[8 * 256];
    for (int kc = 0; kc < 4; ++kc) {
        __syncthreads();
        for (int x = threadIdx.x; x < 8 * 256; x += 256)
            sh[x] = h_in[(blockIdx.y * 8 + (x >> 8)) * 1024 + kc * 256 + (x & 255)];
        __syncthreads();
        const float* shb = sh + bl * 256;
#pragma unroll 4
        for (int kk = 0; kk < 256; ++kk) {
            float hk = shb[kk];
            float4 w = W4[(kc * 256 + kk) * 1024 + j];
            ai += hk * w.x;
            af += hk * w.y;
            ag += hk * w.z;
            ao += hk * w.w;
        }
    }
    float cv = c[b * 1024 + j];
    cv = sigm(af) * cv + sigm(ai) * tanhf(ag);
    float hn = sigm(ao) * tanhf(cv);
    c[b * 1024 + j] = cv;
    h_out[b * 1024 + j] = hn;
    dout[((size_t)b * 256 + t) * 1024 + j] = hn;
}

// ---------------------------------------------------------------------------
// Attention: per (b,i) block: scores, masked softmax, weighted sum.
// ---------------------------------------------------------------------------
__global__ void attention_kernel(const float* __restrict__ q,
                                 const float* __restrict__ sent_enc,
                                 const int* __restrict__ words,
                                 float* __restrict__ attn_enc,
                                 float* __restrict__ map_out) {
    int bi = blockIdx.x;  // b*16 + i
    int b = bi >> 4;
    int i = bi & 15;
    __shared__ float se[16 * 513];
    __shared__ float sc[16][16];
    __shared__ float mp[16][16];
    __shared__ int kv[16];

    for (int x = threadIdx.x; x < 16 * 512; x += 256) {
        int jj = x >> 9, d = x & 511;
        se[jj * 513 + d] = sent_enc[((size_t)b * 16 + jj) * 512 + d];
    }
    if (threadIdx.x < 16) {
        int jj = threadIdx.x;
        int any = 0;
        for (int tw = 0; tw < 16; ++tw) any |= (words[(b * 16 + jj) * 16 + tw] != 0);
        kv[jj] = any;
    }
    __syncthreads();
    {
        int cdx = threadIdx.x >> 4, jj = threadIdx.x & 15;
        const float* qr = q + ((size_t)bi * 16 + cdx) * 512;
        const float* ser = se + jj * 513;
        float s = 0.f;
#pragma unroll 4
        for (int d = 0; d < 512; ++d) s += qr[d] * ser[d];
        sc[cdx][jj] = s;
    }
    __syncthreads();
    if (threadIdx.x < 16) {
        int cdx = threadIdx.x;
        float v[16];
        float m = -1e30f;
#pragma unroll
        for (int jj = 0; jj < 16; ++jj) {
            bool valid = (kv[jj] != 0) && (jj != i);
            v[jj] = valid ? sc[cdx][jj] : -1e9f;
            m = fmaxf(m, v[jj]);
        }
        float sum = 0.f;
#pragma unroll
        for (int jj = 0; jj < 16; ++jj) { v[jj] = expf(v[jj] - m); sum += v[jj]; }
        float inv = 1.f / sum;
#pragma unroll
        for (int jj = 0; jj < 16; ++jj) mp[cdx][jj] = v[jj] * inv;
    }
    __syncthreads();
    if (map_out != nullptr && threadIdx.x < 256) {
        int x = threadIdx.x;  // 16*16
        map_out[(size_t)bi * 256 + x] = mp[x >> 4][x & 15];
    }
    for (int x = threadIdx.x; x < 16 * 512; x += 256) {
        int cdx = x >> 9, d = x & 511;
        float s = 0.f;
#pragma unroll
        for (int jj = 0; jj < 16; ++jj) s += mp[cdx][jj] * se[jj * 513 + d];
        attn_enc[((size_t)bi * 16 + cdx) * 512 + d] = s;
    }
}

// ---------------------------------------------------------------------------
// Classifier: diac[m, n] = dec_out[m,:] @ cls_W[:, n] + cls_b[n]; n < 15
// ---------------------------------------------------------------------------
__global__ void classifier_kernel(const float* __restrict__ dec_out,
                                  const float* __restrict__ W,
                                  const float* __restrict__ bias,
                                  float* __restrict__ out) {
    int m = blockIdx.x * 16 + (threadIdx.x >> 4);
    int n = threadIdx.x & 15;
    if (n >= 15) return;
    const float* x = dec_out + (size_t)m * 1024;
    float s = bias[n];
#pragma unroll 4
    for (int k = 0; k < 1024; ++k) s += x[k] * W[k * 15 + n];
    out[(size_t)m * 15 + n] = s;
}

// ---------------------------------------------------------------------------
// Host launcher
// ---------------------------------------------------------------------------
static float* symf(const void* s) {
    void* p = nullptr;
    cudaGetSymbolAddress(&p, s);
    return (float*)p;
}

extern "C" void kernel_launch(void* const* d_in, const int* in_sizes, int n_in,
                              void* d_out, int out_size) {
    (void)in_sizes; (void)n_in;
    const int* sents = (const int*)d_in[0];
    const int* words = (const int*)d_in[1];
    const int* labels = (const int*)d_in[2];
    const float* word_embs = (const float*)d_in[3];
    const float* char_table = (const float*)d_in[4];
    const float* sWx0 = (const float*)d_in[5];
    const float* sWh0 = (const float*)d_in[6];
    const float* sb0 = (const float*)d_in[7];
    const float* sWx1 = (const float*)d_in[8];
    const float* sWh1 = (const float*)d_in[9];
    const float* sb1 = (const float*)d_in[10];
    const float* wWx0 = (const float*)d_in[11];
    const float* wWh0 = (const float*)d_in[12];
    const float* wb0 = (const float*)d_in[13];
    const float* wWx1 = (const float*)d_in[14];
    const float* wWh1 = (const float*)d_in[15];
    const float* wb1 = (const float*)d_in[16];
    const float* Wq = (const float*)d_in[17];
    const float* dWx = (const float*)d_in[18];
    const float* dWh = (const float*)d_in[19];
    const float* db = (const float*)d_in[20];
    const float* clsW = (const float*)d_in[21];
    const float* clsb = (const float*)d_in[22];
    float* out = (float*)d_out;

    float* wembs = symf(g_wembs);
    float* pre_s = symf(g_pre_s);
    float* sent_h0 = symf(g_sent_h0);
    float* sent_enc = symf(g_sent_enc);
    float* char_in = symf(g_char_in);
    float* pre_w = symf(g_pre_w);
    float* word_h0 = symf(g_word_h0);
    float* char_enc = symf(g_char_enc);
    float* qbuf = symf(g_q);
    float* attn_enc = symf(g_attn_enc);
    float* finalb = symf(g_final);
    float* pre_d = symf(g_pre_d);
    float* dec_out = symf(g_dec_out);
    float* hA = symf(g_hA);
    float* hB = symf(g_hB);
    float* cst = symf(g_cst);
    float* sWh0P = symf(g_sWh0P);
    float* sWh1P = symf(g_sWh1P);
    float* wWh0P = symf(g_wWh0P);
    float* wWh1P = symf(g_wWh1P);
    float* dWhP = symf(g_dWhP);
    float* WqT = symf(g_WqT);

    const int sWhPStride = SH_ * SH_ * 4;
    const int wWhPStride = WH_ * WH_ * 4;

    // ---- weight packing / transposes ----
    {
        int tot = 4 * SH_ * SH_;
        pack_wh_kernel<<<(tot + 255) / 256, 256>>>(sWh0, sWh0P, SH_);
        pack_wh_kernel<<<(tot + 255) / 256, 256>>>(sWh0 + tot, sWh0P + sWhPStride, SH_);
        pack_wh_kernel<<<(tot + 255) / 256, 256>>>(sWh1, sWh1P, SH_);
        pack_wh_kernel<<<(tot + 255) / 256, 256>>>(sWh1 + tot, sWh1P + sWhPStride, SH_);
    }
    {
        int tot = 4 * WH_ * WH_;
        pack_wh_kernel<<<(tot + 255) / 256, 256>>>(wWh0, wWh0P, WH_);
        pack_wh_kernel<<<(tot + 255) / 256, 256>>>(wWh0 + tot, wWh0P + wWhPStride, WH_);
        pack_wh_kernel<<<(tot + 255) / 256, 256>>>(wWh1, wWh1P, WH_);
        pack_wh_kernel<<<(tot + 255) / 256, 256>>>(wWh1 + tot, wWh1P + wWhPStride, WH_);
    }
    {
        int tot = 4 * DH_ * DH_;
        pack_wh_kernel<<<(tot + 255) / 256, 256>>>(dWh, dWhP, DH_);
    }
    transpose_wq_kernel<<<(DIN_ * DQ_ + 255) / 256, 256>>>(Wq, WqT);

    // ---- sentence encoder ----
    embed_sents_kernel<<<(NSEQ_ * WDIM_ + 255) / 256, 256>>>(sents, word_embs, wembs);

    // layer 0: fused both dirs, M=512, N=2048, K=300
    sgemm128_kernel<<<dim3(2048 / 128, 512 / 128), 256>>>(
        wembs, sWx0, sb0, pre_s, 512, 2048, 300);
    lstm_rec_kernel<SH_, 2, 2><<<dim3(B_ / 2, 2), SH_>>>(
        pre_s, sWh0P, sWhPStride, sent_h0, TS_);

    // layer 1 (K=512)
    sgemm128_kernel<<<dim3(2048 / 128, 512 / 128), 256>>>(
        sent_h0, sWx1, sb1, pre_s, 512, 2048, 512);
    lstm_rec_kernel<SH_, 2, 2><<<dim3(B_ / 2, 2), SH_>>>(
        pre_s, sWh1P, sWhPStride, sent_enc, TS_);

    // ---- char (word) encoder ----
    build_char_in_kernel<<<NR_, 256>>>(words, char_table, sent_enc, char_in);

    // word layer 0: fused dirs, M=8192, N=4096, K=544
    sgemm128_kernel<<<dim3(4096 / 128, 8192 / 128), 256>>>(
        char_in, wWx0, wb0, pre_w, 8192, 4096, 544);
    lstm_rec_kernel<WH_, 8, 12><<<dim3(NSEQ_ / 8, 2), WH_>>>(
        pre_w, wWh0P, wWhPStride, word_h0, TW_);

    // word layer 1: K=1024
    sgemm128_kernel<<<dim3(4096 / 128, 8192 / 128), 256>>>(
        word_h0, wWx1, wb1, pre_w, 8192, 4096, 1024);
    lstm_rec_kernel<WH_, 8, 12><<<dim3(NSEQ_ / 8, 2), WH_>>>(
        pre_w, wWh1P, wWhPStride, char_enc, TW_);

    // ---- attention ----
    sgemm128_kernel<<<dim3(512 / 128, 8192 / 128), 256>>>(
        char_enc, WqT, nullptr, qbuf, 8192, 512, 1024);
    float* map_out = (out_size >= (NR_ * 15 + B_ * TS_ * TW_ * TS_)) ? (out + NR_ * 15) : nullptr;
    attention_kernel<<<NSEQ_, 256>>>(qbuf, sent_enc, words, attn_enc, map_out);

    // ---- decoder ----
    build_final_kernel<<<NR_, 256>>>(attn_enc, char_enc, labels, finalb);
    sgemm128_kernel<<<dim3(4096 / 128, 8192 / 128), 256>>>(
        finalb, dWx, db, pre_d, 8192, 4096, 1544);

    zero2_kernel<<<(B_ * DH_ + 255) / 256, 256>>>(hA, cst, B_ * DH_);
    for (int t = 0; t < TS_ * TW_; ++t) {
        float* hi = (t & 1) ? hB : hA;
        float* ho = (t & 1) ? hA : hB;
        dec_step_kernel<<<dim3(32, 4), 256>>>(pre_d, dWhP, hi, ho, cst, dec_out, t);
    }

    classifier_kernel<<<NR_ / 16, 256>>>(dec_out, clsW, clsb, out);
}

// round 5
// speedup vs baseline: 1.1623x; 1.1036x over previous
#include <cuda_runtime.h>
#include <cuda_bf16.h>
#include <math.h>
#include <stdint.h>

#define B_ 32
#define SH_ 256
#define WH_ 512
#define DH_ 1024
#define NSEQ_ 512
#define NR_ 8192
#define NCH_W0 9
#define NCH_W1 16
#define NCH_Q 16
#define NCH_DEC 25
#define TILE_BYTES 16384
#define PAIR_BYTES 32768
#define TG_SMEM 131072

#define DEVBUF __device__ __align__(16)
DEVBUF float g_wembs[NSEQ_ * 300];
DEVBUF float g_pre_s[NSEQ_ * 2048];
DEVBUF float g_sent_h0[NSEQ_ * 512];
DEVBUF float g_sent_enc[NSEQ_ * 512];
DEVBUF float g_pre_w[NR_ * 4096];
DEVBUF float g_word_h0[NR_ * 1024];
DEVBUF float g_char_enc[NR_ * 1024];
DEVBUF float g_q[NR_ * 512];
DEVBUF float g_attn_enc[NR_ * 512];
DEVBUF float g_pre_d[NR_ * 4096];
DEVBUF float g_dec_out[NR_ * 1024];
DEVBUF float g_hA[B_ * DH_];
DEVBUF float g_hB[B_ * DH_];
DEVBUF float g_cst[B_ * DH_];
DEVBUF float g_sWh0P[2 * SH_ * SH_ * 4];
DEVBUF float g_sWh1P[2 * SH_ * SH_ * 4];
DEVBUF float g_wWh0P[2 * WH_ * WH_ * 4];
DEVBUF float g_wWh1P[2 * WH_ * WH_ * 4];
DEVBUF float g_dWhP[DH_ * DH_ * 4];
DEVBUF unsigned char g_stageA[64ul * 25 * PAIR_BYTES];
DEVBUF unsigned char g_stB_w0[32ul * NCH_W0 * PAIR_BYTES];
DEVBUF unsigned char g_stB_w1[32ul * NCH_W1 * PAIR_BYTES];
DEVBUF unsigned char g_stB_q[4ul * NCH_Q * PAIR_BYTES];
DEVBUF unsigned char g_stB_dec[32ul * NCH_DEC * PAIR_BYTES];

__device__ __forceinline__ float sigm(float x) { return 1.f / (1.f + expf(-x)); }
__device__ __forceinline__ unsigned swz(unsigned o) { return o ^ ((o >> 3) & 0x70); }

__device__ __forceinline__ uint32_t smem_u32(const void* p) {
    uint32_t a;
    asm("{ .reg .u64 t; cvta.to.shared.u64 t, %1; cvt.u32.u64 %0, t; }" : "=r"(a) : "l"(p));
    return a;
}
__device__ __forceinline__ void cp_async16(uint32_t dst, const void* src) {
    asm volatile("cp.async.cg.shared.global [%0], [%1], 16;" :: "r"(dst), "l"(src) : "memory");
}
__device__ __forceinline__ void cp_commit() {
    asm volatile("cp.async.commit_group;" ::: "memory");
}
template <int N>
__device__ __forceinline__ void cp_wait() {
    asm volatile("cp.async.wait_group %0;" :: "n"(N) : "memory");
}
__device__ __forceinline__ void ldm_x4(uint32_t* r, uint32_t addr) {
    asm volatile("ldmatrix.sync.aligned.m8n8.x4.shared.b16 {%0,%1,%2,%3}, [%4];"
                 : "=r"(r[0]), "=r"(r[1]), "=r"(r[2]), "=r"(r[3]) : "r"(addr));
}
__device__ __forceinline__ void mma16816(float* d, const uint32_t* a, const uint32_t* b) {
    asm volatile(
        "mma.sync.aligned.m16n8k16.row.col.f32.bf16.bf16.f32 "
        "{%0,%1,%2,%3},{%4,%5,%6,%7},{%8,%9},{%0,%1,%2,%3};"
        : "+f"(d[0]), "+f"(d[1]), "+f"(d[2]), "+f"(d[3])
        : "r"(a[0]), "r"(a[1]), "r"(a[2]), "r"(a[3]), "r"(b[0]), "r"(b[1]));
}

// ---- bf16 split store into swizzled staging ----
__device__ __forceinline__ void split_store_pair(unsigned char* st, int nCh, int blk,
                                                 int row, int kp, float v0, float v1) {
    int chunk = kp >> 6, kin = kp & 63;
    size_t base = ((size_t)(blk * nCh + chunk)) * PAIR_BYTES;
    unsigned so = swz((unsigned)(row * 128 + kin * 2));
    __nv_bfloat16 h0 = __float2bfloat16(v0), h1 = __float2bfloat16(v1);
    __nv_bfloat16 l0 = __float2bfloat16(v0 - __bfloat162float(h0));
    __nv_bfloat16 l1 = __float2bfloat16(v1 - __bfloat162float(h1));
    *(unsigned*)(st + base + so) =
        (unsigned)__bfloat16_as_ushort(h0) | ((unsigned)__bfloat16_as_ushort(h1) << 16);
    *(unsigned*)(st + base + TILE_BYTES + so) =
        (unsigned)__bfloat16_as_ushort(l0) | ((unsigned)__bfloat16_as_ushort(l1) << 16);
}

// ---- prep kernel ----
__device__ __forceinline__ void pack_region(const float* Wh, float* out, int H, long r) {
    long per = 4L * H * H;
    int dir = (int)(r / per);
    long s = r % per;
    int g = (int)(s & 3), jj = (int)((s >> 2) % H), k = (int)(s / (4 * H));
    out[dir * per + s] = Wh[dir * per + (size_t)(g * H + jj) * H + k];
}
#define R_SWH 524288L
#define R_WWH 2097152L
#define R_DWH 4194304L
#define R_BW0 1179648L
#define R_BW1 2097152L
#define R_BQ 262144L
#define R_BDEC 3276800L
#define R_CEMB 131072L
#define R_PAD 131072L
#define R_EMB 153600L
#define PREP_BLOCKS 65112

__global__ void prep_kernel(const float* __restrict__ sWh0, const float* __restrict__ sWh1,
                            const float* __restrict__ wWh0, const float* __restrict__ wWh1,
                            const float* __restrict__ dWh, const float* __restrict__ wWx0,
                            const float* __restrict__ wWx1, const float* __restrict__ Wq,
                            const float* __restrict__ dWx, const int* __restrict__ words,
                            const float* __restrict__ char_table, const int* __restrict__ sents,
                            const float* __restrict__ word_embs) {
    long idx = (long)blockIdx.x * 256 + threadIdx.x;
    if (idx < R_SWH) { pack_region(sWh0, g_sWh0P, SH_, idx); return; }
    idx -= R_SWH;
    if (idx < R_SWH) { pack_region(sWh1, g_sWh1P, SH_, idx); return; }
    idx -= R_SWH;
    if (idx < R_WWH) { pack_region(wWh0, g_wWh0P, WH_, idx); return; }
    idx -= R_WWH;
    if (idx < R_WWH) { pack_region(wWh1, g_wWh1P, WH_, idx); return; }
    idx -= R_WWH;
    if (idx < R_DWH) {
        int g = (int)(idx & 3), jj = (int)((idx >> 2) % DH_), k = (int)(idx / (4 * DH_));
        g_dWhP[idx] = dWh[(size_t)(g * DH_ + jj) * DH_ + k];
        return;
    }
    idx -= R_DWH;
    if (idx < R_BW0) {
        int n = (int)(idx / 288), kp = 2 * (int)(idx % 288);
        float v0 = (kp < 544) ? wWx0[(size_t)n * 544 + kp] : 0.f;
        float v1 = (kp + 1 < 544) ? wWx0[(size_t)n * 544 + kp + 1] : 0.f;
        split_store_pair(g_stB_w0, NCH_W0, n >> 7, n & 127, kp, v0, v1);
        return;
    }
    idx -= R_BW0;
    if (idx < R_BW1) {
        int n = (int)(idx / 512), kp = 2 * (int)(idx % 512);
        split_store_pair(g_stB_w1, NCH_W1, n >> 7, n & 127, kp,
                         wWx1[(size_t)n * 1024 + kp], wWx1[(size_t)n * 1024 + kp + 1]);
        return;
    }
    idx -= R_BW1;
    if (idx < R_BQ) {
        int n = (int)(idx / 512), kp = 2 * (int)(idx % 512);
        split_store_pair(g_stB_q, NCH_Q, n >> 7, n & 127, kp,
                         Wq[(size_t)kp * 512 + n], Wq[(size_t)(kp + 1) * 512 + n]);
        return;
    }
    idx -= R_BQ;
    if (idx < R_BDEC) {
        int n = (int)(idx / 800), kp = 2 * (int)(idx % 800);
        float v0 = (kp < 1544) ? dWx[(size_t)n * 1544 + kp] : 0.f;
        float v1 = (kp + 1 < 1544) ? dWx[(size_t)n * 1544 + kp + 1] : 0.f;
        split_store_pair(g_stB_dec, NCH_DEC, n >> 7, n & 127, kp, v0, v1);
        return;
    }
    idx -= R_BDEC;
    if (idx < R_CEMB) {
        int r = (int)(idx / 16), kp = 2 * (int)(idx % 16);
        int w = words[r];
        split_store_pair(g_stageA, NCH_W0, r >> 7, r & 127, kp,
                         char_table[w * 32 + kp], char_table[w * 32 + kp + 1]);
        return;
    }
    idx -= R_CEMB;
    if (idx < R_PAD) {
        int r = (int)(idx / 16), kp = 544 + 2 * (int)(idx % 16);
        split_store_pair(g_stageA, NCH_W0, r >> 7, r & 127, kp, 0.f, 0.f);
        return;
    }
    idx -= R_PAD;
    if (idx < R_EMB) {
        int r = (int)(idx / 300), d = (int)(idx % 300);
        g_wembs[r * 300 + d] = word_embs[(size_t)sents[r] * 300 + d];
    }
}

__global__ void splitA_kernel(const float* __restrict__ src, int K, int nCh) {
    long idx = (long)blockIdx.x * 256 + threadIdx.x;
    int ppr = K >> 1;
    int r = (int)(idx / ppr), kp = 2 * (int)(idx % ppr);
    split_store_pair(g_stageA, nCh, r >> 7, r & 127, kp,
                     src[(size_t)r * K + kp], src[(size_t)r * K + kp + 1]);
}

__global__ void build_final_split_kernel(const float* __restrict__ attn_enc,
                                         const float* __restrict__ char_enc,
                                         const int* __restrict__ labels) {
    long idx = (long)blockIdx.x * 256 + threadIdx.x;
    int r = (int)(idx / 800), kp = 2 * (int)(idx % 800);
    float v[2];
#pragma unroll
    for (int u = 0; u < 2; ++u) {
        int c = kp + u;
        float x;
        if (c < 512)       x = attn_enc[(size_t)r * 512 + c];
        else if (c < 1536) x = char_enc[(size_t)r * 1024 + (c - 512)];
        else if (c < 1544) x = (float)labels[r * 8 + (c - 1536)];
        else               x = 0.f;
        v[u] = x;
    }
    split_store_pair(g_stageA, NCH_DEC, r >> 7, r & 127, kp, v[0], v[1]);
}

__global__ void zero2_kernel(float* a, float* b, int n) {
    int i = blockIdx.x * 256 + threadIdx.x;
    if (i < n) { a[i] = 0.f; b[i] = 0.f; }
}

// ---- HMMA GEMM: C[M,N] = A@W^T (+bias), split-bf16 (3 passes) ----
// grid (N/128, M/128), 256 thr (8 warps, 64x32 warp tiles), cp.async dbuf.
__global__ void __launch_bounds__(256) tgemm_kernel(
    const unsigned char* __restrict__ stA, const unsigned char* __restrict__ stB,
    const float* __restrict__ bias, float* __restrict__ C, int N, int nCh) {
    extern __shared__ unsigned char smraw[];
    uint32_t smb = smem_u32(smraw);
    uint32_t ab = (smb + 1023) & ~1023u;
    int tid = threadIdx.x, lane = tid & 31, wid = tid >> 5;
    int wm = wid & 1, wn = wid >> 1;
    int nb = blockIdx.x, mb = blockIdx.y;

    float acc[4][4][4];
#pragma unroll
    for (int i = 0; i < 4; ++i)
#pragma unroll
        for (int j = 0; j < 4; ++j)
#pragma unroll
            for (int k = 0; k < 4; ++k) acc[i][j][k] = 0.f;

    // ldmatrix lane-row bases
    int ar = (lane & 7) + ((lane >> 3) & 1) * 8;   // + wm*64 + mf*16
    int ac = (lane >> 4) * 16;                      // + ks*32
    int br = (lane & 7) + ((lane >> 4) & 1) * 8;   // + wn*32 + nf2*16
    int bc = ((lane >> 3) & 1) * 16;                // + ks*32

    auto issue = [&](int c) {
        uint32_t dst = ab + (c & 1) * 65536;
        const unsigned char* sA = stA + ((size_t)mb * nCh + c) * PAIR_BYTES;
        const unsigned char* sB = stB + ((size_t)nb * nCh + c) * PAIR_BYTES;
#pragma unroll
        for (int i = 0; i < 8; ++i)
            cp_async16(dst + (tid + i * 256) * 16, sA + (tid + i * 256) * 16);
#pragma unroll
        for (int i = 0; i < 8; ++i)
            cp_async16(dst + 32768 + (tid + i * 256) * 16, sB + (tid + i * 256) * 16);
        cp_commit();
    };

    issue(0);
    for (int c = 0; c < nCh; ++c) {
        if (c + 1 < nCh) { issue(c + 1); cp_wait<1>(); }
        else             { cp_wait<0>(); }
        __syncthreads();
        uint32_t base = ab + (c & 1) * 65536;
#pragma unroll
        for (int ks = 0; ks < 4; ++ks) {
            uint32_t ah[4][4], al[4][4], bh[2][4], bl[2][4];
#pragma unroll
            for (int mf = 0; mf < 4; ++mf) {
                uint32_t off = swz((unsigned)((wm * 64 + mf * 16 + ar) * 128 + ac + ks * 32));
                ldm_x4(ah[mf], base + off);
                ldm_x4(al[mf], base + 16384 + off);
            }
#pragma unroll
            for (int nf2 = 0; nf2 < 2; ++nf2) {
                uint32_t off = swz((unsigned)((wn * 32 + nf2 * 16 + br) * 128 + bc + ks * 32));
                ldm_x4(bh[nf2], base + 32768 + off);
                ldm_x4(bl[nf2], base + 49152 + off);
            }
#pragma unroll
            for (int mf = 0; mf < 4; ++mf)
#pragma unroll
                for (int nf = 0; nf < 4; ++nf) {
                    mma16816(acc[mf][nf], ah[mf], &bh[nf >> 1][(nf & 1) * 2]);
                    mma16816(acc[mf][nf], ah[mf], &bl[nf >> 1][(nf & 1) * 2]);
                    mma16816(acc[mf][nf], al[mf], &bh[nf >> 1][(nf & 1) * 2]);
                }
        }
        __syncthreads();
    }

    // epilogue: direct fragment stores (float2)
#pragma unroll
    for (int mf = 0; mf < 4; ++mf) {
#pragma unroll
        for (int nf = 0; nf < 4; ++nf) {
            int row = mb * 128 + wm * 64 + mf * 16 + (lane >> 2);
            int col = nb * 128 + wn * 32 + nf * 8 + (lane & 3) * 2;
            float b0 = bias ? bias[col] : 0.f;
            float b1 = bias ? bias[col + 1] : 0.f;
            float2 v0 = make_float2(acc[mf][nf][0] + b0, acc[mf][nf][1] + b1);
            float2 v1 = make_float2(acc[mf][nf][2] + b0, acc[mf][nf][3] + b1);
            *(float2*)(C + (size_t)row * N + col) = v0;
            *(float2*)(C + (size_t)(row + 8) * N + col) = v1;
        }
    }
}

// ---- SIMT SGEMM (small sentence layers) ----
__global__ void __launch_bounds__(256) sgemm128_kernel(
    const float* __restrict__ A, const float* __restrict__ W,
    const float* __restrict__ bias, float* __restrict__ C, int M, int N, int K) {
    __shared__ __align__(16) float As[2][8][132];
    __shared__ __align__(16) float Bs[2][8][132];
    int tid = threadIdx.x;
    int m0 = blockIdx.y * 128, n0 = blockIdx.x * 128;
    int grow = tid >> 1, gk = (tid & 1) * 4;
    const float* Ap = A + (size_t)(m0 + grow) * K + gk;
    const float* Wp = W + (size_t)(n0 + grow) * K + gk;
    int tm4 = (tid >> 4) * 4, tn4 = (tid & 15) * 4;
    float acc[8][8];
#pragma unroll
    for (int i = 0; i < 8; ++i)
#pragma unroll
        for (int j = 0; j < 8; ++j) acc[i][j] = 0.f;
    int nk = (K + 7) / 8;
    float4 pa, pb;
    pa = (gk < K) ? *(const float4*)Ap : make_float4(0, 0, 0, 0);
    pb = (gk < K) ? *(const float4*)Wp : make_float4(0, 0, 0, 0);
    As[0][gk + 0][grow] = pa.x; As[0][gk + 1][grow] = pa.y;
    As[0][gk + 2][grow] = pa.z; As[0][gk + 3][grow] = pa.w;
    Bs[0][gk + 0][grow] = pb.x; Bs[0][gk + 1][grow] = pb.y;
    Bs[0][gk + 2][grow] = pb.z; Bs[0][gk + 3][grow] = pb.w;
    __syncthreads();
    for (int it = 0; it < nk; ++it) {
        int buf = it & 1;
        bool more = (it + 1) < nk;
        if (more) {
            int kt = (it + 1) * 8;
            pa = (kt + gk < K) ? *(const float4*)(Ap + kt) : make_float4(0, 0, 0, 0);
            pb = (kt + gk < K) ? *(const float4*)(Wp + kt) : make_float4(0, 0, 0, 0);
        }
#pragma unroll
        for (int kk = 0; kk < 8; ++kk) {
            float4 a0 = *(const float4*)&As[buf][kk][tm4];
            float4 a1 = *(const float4*)&As[buf][kk][tm4 + 64];
            float4 b0 = *(const float4*)&Bs[buf][kk][tn4];
            float4 b1 = *(const float4*)&Bs[buf][kk][tn4 + 64];
            float av[8] = {a0.x, a0.y, a0.z, a0.w, a1.x, a1.y, a1.z, a1.w};
            float bv[8] = {b0.x, b0.y, b0.z, b0.w, b1.x, b1.y, b1.z, b1.w};
#pragma unroll
            for (int i = 0; i < 8; ++i)
#pragma unroll
                for (int j = 0; j < 8; ++j) acc[i][j] += av[i] * bv[j];
        }
        if (more) {
            int nb2 = buf ^ 1;
            As[nb2][gk + 0][grow] = pa.x; As[nb2][gk + 1][grow] = pa.y;
            As[nb2][gk + 2][grow] = pa.z; As[nb2][gk + 3][grow] = pa.w;
            Bs[nb2][gk + 0][grow] = pb.x; Bs[nb2][gk + 1][grow] = pb.y;
            Bs[nb2][gk + 2][grow] = pb.z; Bs[nb2][gk + 3][grow] = pb.w;
        }
        __syncthreads();
    }
    float bb0[4] = {0, 0, 0, 0}, bb1[4] = {0, 0, 0, 0};
    if (bias) {
#pragma unroll
        for (int j = 0; j < 4; ++j) { bb0[j] = bias[n0 + tn4 + j]; bb1[j] = bias[n0 + tn4 + 64 + j]; }
    }
#pragma unroll
    for (int i = 0; i < 8; ++i) {
        int r = m0 + tm4 + (i & 3) + ((i >> 2) << 6);
        float4 v0 = make_float4(acc[i][0] + bb0[0], acc[i][1] + bb0[1], acc[i][2] + bb0[2], acc[i][3] + bb0[3]);
        float4 v1 = make_float4(acc[i][4] + bb1[0], acc[i][5] + bb1[1], acc[i][6] + bb1[2], acc[i][7] + bb1[3]);
        *(float4*)(C + (size_t)r * N + n0 + tn4) = v0;
        *(float4*)(C + (size_t)r * N + n0 + tn4 + 64) = v1;
    }
}

// ---- BiLSTM recurrence; STAGE fuses char-input staging ----
template <int H, int BSEQ, int PS, bool STAGE>
__global__ void lstm_rec_kernel(const float* __restrict__ pre,
                                const float* __restrict__ WhP, int whStride,
                                float* __restrict__ out, int T,
                                const int* __restrict__ words) {
    int dir = blockIdx.y;
    const float4* W4 = (const float4*)(WhP + (size_t)dir * whStride);
    int n0 = blockIdx.x * BSEQ;
    int j = threadIdx.x;
    __shared__ __align__(16) float sh[H * PS];
    __shared__ float wm[BSEQ * 256];
    float cc[BSEQ], ai[BSEQ], af[BSEQ], ag[BSEQ], ao[BSEQ];
#pragma unroll
    for (int s = 0; s < BSEQ; ++s) { cc[s] = 0.f; sh[j * PS + s] = 0.f; }
    if (STAGE) {
        for (int x = threadIdx.x; x < BSEQ * 256; x += H)
            wm[x] = (words[(n0 + x / 256) * 256 + (x & 255)] != 0) ? 1.f : 0.f;
    }
    __syncthreads();
    for (int tt = 0; tt < T; ++tt) {
        int t = dir ? (T - 1 - tt) : tt;
#pragma unroll
        for (int s = 0; s < BSEQ; ++s) {
            const float* p = pre + (((size_t)(n0 + s) * T + t) * 2 + dir) * (4 * H);
            ai[s] = p[j]; af[s] = p[H + j]; ag[s] = p[2 * H + j]; ao[s] = p[3 * H + j];
        }
#pragma unroll 4
        for (int k = 0; k < H; ++k) {
            float4 w = W4[k * H + j];
            if constexpr (BSEQ == 8) {
                float4 h0 = *(const float4*)&sh[k * PS];
                float4 h1 = *(const float4*)&sh[k * PS + 4];
                float hv[8] = {h0.x, h0.y, h0.z, h0.w, h1.x, h1.y, h1.z, h1.w};
#pragma unroll
                for (int s = 0; s < 8; ++s) {
                    ai[s] += hv[s] * w.x; af[s] += hv[s] * w.y;
                    ag[s] += hv[s] * w.z; ao[s] += hv[s] * w.w;
                }
            } else {
#pragma unroll
                for (int s = 0; s < BSEQ; ++s) {
                    float hk = sh[k * PS + s];
                    ai[s] += hk * w.x; af[s] += hk * w.y;
                    ag[s] += hk * w.z; ao[s] += hk * w.w;
                }
            }
        }
        __syncthreads();
#pragma unroll
        for (int s = 0; s < BSEQ; ++s) {
            float c = sigm(af[s]) * cc[s] + sigm(ai[s]) * tanhf(ag[s]);
            float hn = sigm(ao[s]) * tanhf(c);
            cc[s] = c;
            sh[j * PS + s] = hn;
            out[(((size_t)(n0 + s) * T + t)) * (2 * H) + dir * H + j] = hn;
            if constexpr (STAGE) {
                float v1 = __shfl_down_sync(0xffffffffu, hn, 1);
                if (!(j & 1)) {
                    int kp = 32 + dir * H + j;
                    int rb = ((n0 + s) * 16 + t) * 16;
                    int blk = rb >> 7;
#pragma unroll
                    for (int tw = 0; tw < 16; ++tw) {
                        float m = wm[s * 256 + t * 16 + tw];
                        split_store_pair(g_stageA, NCH_W0, blk, (rb & 127) + tw, kp, hn * m, v1 * m);
                    }
                }
            }
        }
        __syncthreads();
    }
}

// ---- decoder step ----
__global__ void dec_step_kernel(const float* __restrict__ pre, const float* __restrict__ WhP,
                                const float* __restrict__ h_in, float* __restrict__ h_out,
                                float* __restrict__ c, float* __restrict__ dout, int t) {
    const float4* W4 = (const float4*)WhP;
    int jl = threadIdx.x & 31, bl = threadIdx.x >> 5;
    int j = blockIdx.x * 32 + jl, b = blockIdx.y * 8 + bl;
    const float* p = pre + ((size_t)b * 256 + t) * 4096;
    float ai = p[j], af = p[1024 + j], ag = p[2048 + j], ao = p[3072 + j];
    __shared__ float sh[8 * 256];
    for (int kc = 0; kc < 4; ++kc) {
        __syncthreads();
        for (int x = threadIdx.x; x < 8 * 256; x += 256)
            sh[x] = h_in[(blockIdx.y * 8 + (x >> 8)) * 1024 + kc * 256 + (x & 255)];
        __syncthreads();
        const float* shb = sh + bl * 256;
#pragma unroll 4
        for (int kk = 0; kk < 256; ++kk) {
            float hk = shb[kk];
            float4 w = W4[(kc * 256 + kk) * 1024 + j];
            ai += hk * w.x; af += hk * w.y; ag += hk * w.z; ao += hk * w.w;
        }
    }
    float cv = c[b * 1024 + j];
    cv = sigm(af) * cv + sigm(ai) * tanhf(ag);
    float hn = sigm(ao) * tanhf(cv);
    c[b * 1024 + j] = cv;
    h_out[b * 1024 + j] = hn;
    dout[((size_t)b * 256 + t) * 1024 + j] = hn;
}

// ---- attention ----
__global__ void attention_kernel(const float* __restrict__ q, const float* __restrict__ sent_enc,
                                 const int* __restrict__ words, float* __restrict__ attn_enc,
                                 float* __restrict__ map_out) {
    int bi = blockIdx.x, b = bi >> 4, i = bi & 15;
    __shared__ float se[16 * 513];
    __shared__ float sc[16][16];
    __shared__ float mp[16][16];
    __shared__ int kv[16];
    for (int x = threadIdx.x; x < 16 * 512; x += 256) {
        int jj = x >> 9, d = x & 511;
        se[jj * 513 + d] = sent_enc[((size_t)b * 16 + jj) * 512 + d];
    }
    if (threadIdx.x < 16) {
        int jj = threadIdx.x, any = 0;
        for (int tw = 0; tw < 16; ++tw) any |= (words[(b * 16 + jj) * 16 + tw] != 0);
        kv[jj] = any;
    }
    __syncthreads();
    {
        int cdx = threadIdx.x >> 4, jj = threadIdx.x & 15;
        const float* qr = q + ((size_t)bi * 16 + cdx) * 512;
        const float* ser = se + jj * 513;
        float s = 0.f;
#pragma unroll 4
        for (int d = 0; d < 512; ++d) s += qr[d] * ser[d];
        sc[cdx][jj] = s;
    }
    __syncthreads();
    if (threadIdx.x < 16) {
        int cdx = threadIdx.x;
        float v[16], m = -1e30f;
#pragma unroll
        for (int jj = 0; jj < 16; ++jj) {
            bool valid = (kv[jj] != 0) && (jj != i);
            v[jj] = valid ? sc[cdx][jj] : -1e9f;
            m = fmaxf(m, v[jj]);
        }
        float sum = 0.f;
#pragma unroll
        for (int jj = 0; jj < 16; ++jj) { v[jj] = expf(v[jj] - m); sum += v[jj]; }
        float inv = 1.f / sum;
#pragma unroll
        for (int jj = 0; jj < 16; ++jj) mp[cdx][jj] = v[jj] * inv;
    }
    __syncthreads();
    if (map_out != nullptr && threadIdx.x < 256) {
        int x = threadIdx.x;
        map_out[(size_t)bi * 256 + x] = mp[x >> 4][x & 15];
    }
    for (int x = threadIdx.x; x < 16 * 512; x += 256) {
        int cdx = x >> 9, d = x & 511;
        float s = 0.f;
#pragma unroll
        for (int jj = 0; jj < 16; ++jj) s += mp[cdx][jj] * se[jj * 513 + d];
        attn_enc[((size_t)bi * 16 + cdx) * 512 + d] = s;
    }
}

__global__ void classifier_kernel(const float* __restrict__ dec_out, const float* __restrict__ W,
                                  const float* __restrict__ bias, float* __restrict__ out) {
    int m = blockIdx.x * 16 + (threadIdx.x >> 4);
    int n = threadIdx.x & 15;
    if (n >= 15) return;
    const float* x = dec_out + (size_t)m * 1024;
    float s = bias[n];
#pragma unroll 4
    for (int k = 0; k < 1024; ++k) s += x[k] * W[k * 15 + n];
    out[(size_t)m * 15 + n] = s;
}

// ---- host ----
static void* symp(const void* s) { void* p = nullptr; cudaGetSymbolAddress(&p, s); return p; }

extern "C" void kernel_launch(void* const* d_in, const int* in_sizes, int n_in,
                              void* d_out, int out_size) {
    (void)in_sizes; (void)n_in;
    const int* sents = (const int*)d_in[0];
    const int* words = (const int*)d_in[1];
    const int* labels = (const int*)d_in[2];
    const float* word_embs = (const float*)d_in[3];
    const float* char_table = (const float*)d_in[4];
    const float* sWx0 = (const float*)d_in[5];
    const float* sWh0 = (const float*)d_in[6];
    const float* sb0 = (const float*)d_in[7];
    const float* sWx1 = (const float*)d_in[8];
    const float* sWh1 = (const float*)d_in[9];
    const float* sb1 = (const float*)d_in[10];
    const float* wWx0 = (const float*)d_in[11];
    const float* wWh0 = (const float*)d_in[12];
    const float* wb0 = (const float*)d_in[13];
    const float* wWx1 = (const float*)d_in[14];
    const float* wWh1 = (const float*)d_in[15];
    const float* wb1 = (const float*)d_in[16];
    const float* Wq = (const float*)d_in[17];
    const float* dWx = (const float*)d_in[18];
    const float* dWh = (const float*)d_in[19];
    const float* db = (const float*)d_in[20];
    const float* clsW = (const float*)d_in[21];
    const float* clsb = (const float*)d_in[22];
    float* out = (float*)d_out;

    float* wembs = (float*)symp(g_wembs);
    float* pre_s = (float*)symp(g_pre_s);
    float* sent_h0 = (float*)symp(g_sent_h0);
    float* sent_enc = (float*)symp(g_sent_enc);
    float* pre_w = (float*)symp(g_pre_w);
    float* word_h0 = (float*)symp(g_word_h0);
    float* char_enc = (float*)symp(g_char_enc);
    float* qbuf = (float*)symp(g_q);
    float* attn_enc = (float*)symp(g_attn_enc);
    float* pre_d = (float*)symp(g_pre_d);
    float* dec_out = (float*)symp(g_dec_out);
    float* hA = (float*)symp(g_hA);
    float* hB = (float*)symp(g_hB);
    float* cst = (float*)symp(g_cst);
    float* sWh0P = (float*)symp(g_sWh0P);
    float* sWh1P = (float*)symp(g_sWh1P);
    float* wWh0P = (float*)symp(g_wWh0P);
    float* wWh1P = (float*)symp(g_wWh1P);
    float* dWhP = (float*)symp(g_dWhP);
    const unsigned char* stA = (const unsigned char*)symp(g_stageA);
    const unsigned char* stBw0 = (const unsigned char*)symp(g_stB_w0);
    const unsigned char* stBw1 = (const unsigned char*)symp(g_stB_w1);
    const unsigned char* stBq = (const unsigned char*)symp(g_stB_q);
    const unsigned char* stBdec = (const unsigned char*)symp(g_stB_dec);

    cudaFuncSetAttribute(tgemm_kernel, cudaFuncAttributeMaxDynamicSharedMemorySize, TG_SMEM);

    const int sStride = SH_ * SH_ * 4;
    const int wStride = WH_ * WH_ * 4;

    // 0: prep
    prep_kernel<<<PREP_BLOCKS, 256>>>(sWh0, sWh1, wWh0, wWh1, dWh, wWx0, wWx1, Wq, dWx,
                                      words, char_table, sents, word_embs);
    // 1-4: sentence encoder (L1 LSTM also builds char staging)
    sgemm128_kernel<<<dim3(16, 4), 256>>>(wembs, sWx0, sb0, pre_s, 512, 2048, 300);
    lstm_rec_kernel<SH_, 2, 2, false><<<dim3(16, 2), SH_>>>(pre_s, sWh0P, sStride, sent_h0, 16, nullptr);
    sgemm128_kernel<<<dim3(16, 4), 256>>>(sent_h0, sWx1, sb1, pre_s, 512, 2048, 512);
    lstm_rec_kernel<SH_, 2, 2, true><<<dim3(16, 2), SH_>>>(pre_s, sWh1P, sStride, sent_enc, 16, words);
    // 5: word L0 GEMM (HMMA)
    tgemm_kernel<<<dim3(32, 64), 256, TG_SMEM>>>(stA, stBw0, wb0, pre_w, 4096, NCH_W0);
    lstm_rec_kernel<WH_, 8, 12, false><<<dim3(64, 2), WH_>>>(pre_w, wWh0P, wStride, word_h0, 16, nullptr);
    splitA_kernel<<<16384, 256>>>(word_h0, 1024, NCH_W1);
    tgemm_kernel<<<dim3(32, 64), 256, TG_SMEM>>>(stA, stBw1, wb1, pre_w, 4096, NCH_W1);
    lstm_rec_kernel<WH_, 8, 12, false><<<dim3(64, 2), WH_>>>(pre_w, wWh1P, wStride, char_enc, 16, nullptr);
    // attention
    splitA_kernel<<<16384, 256>>>(char_enc, 1024, NCH_Q);
    tgemm_kernel<<<dim3(4, 64), 256, TG_SMEM>>>(stA, stBq, nullptr, qbuf, 512, NCH_Q);
    float* map_out = (out_size >= (NR_ * 15 + 131072)) ? (out + NR_ * 15) : nullptr;
    attention_kernel<<<NSEQ_, 256>>>(qbuf, sent_enc, words, attn_enc, map_out);
    // decoder
    build_final_split_kernel<<<25600, 256>>>(attn_enc, char_enc, labels);
    tgemm_kernel<<<dim3(32, 64), 256, TG_SMEM>>>(stA, stBdec, db, pre_d, 4096, NCH_DEC);
    zero2_kernel<<<128, 256>>>(hA, cst, B_ * DH_);
    for (int t = 0; t < 256; ++t) {
        float* hi = (t & 1) ? hB : hA;
        float* ho = (t & 1) ? hA : hB;
        dec_step_kernel<<<dim3(32, 4), 256>>>(pre_d, dWhP, hi, ho, cst, dec_out, t);
    }
    classifier_kernel<<<NR_ / 16, 256>>>(dec_out, clsW, clsb, out);
}

// round 6
// speedup vs baseline: 4.9930x; 4.2959x over previous
#include <cuda_runtime.h>
#include <cuda_bf16.h>
#include <math.h>
#include <stdint.h>

#define B_ 32
#define SH_ 256
#define WH_ 512
#define DH_ 1024
#define NSEQ_ 512
#define NR_ 8192
#define NCH_W0 9
#define NCH_W1 16
#define NCH_Q 16
#define NCH_DEC 25
#define TILE_BYTES 16384
#define PAIR_BYTES 32768
#define TG_SMEM 131072
#define DEC_SMEM (131072 + 32768)

#define DEVBUF __device__ __align__(16)
DEVBUF float g_wembs[NSEQ_ * 300];
DEVBUF float g_pre_s[NSEQ_ * 2048];
DEVBUF float g_sent_h0[NSEQ_ * 512];
DEVBUF float g_sent_enc[NSEQ_ * 512];
DEVBUF float g_pre_w[NR_ * 4096];
DEVBUF float g_word_h0[NR_ * 1024];
DEVBUF float g_char_enc[NR_ * 1024];
DEVBUF float g_q[NR_ * 512];
DEVBUF float g_attn_enc[NR_ * 512];
DEVBUF float g_pre_d[NR_ * 4096];
DEVBUF float g_dec_out[NR_ * 1024];
DEVBUF float g_sWh0P[2 * SH_ * SH_ * 4];
DEVBUF float g_sWh1P[2 * SH_ * SH_ * 4];
DEVBUF float g_wWh0P[2 * WH_ * WH_ * 4];
DEVBUF float g_wWh1P[2 * WH_ * WH_ * 4];
DEVBUF unsigned char g_stageA[64ul * 25 * PAIR_BYTES];
DEVBUF unsigned char g_stB_w0[32ul * NCH_W0 * PAIR_BYTES];
DEVBUF unsigned char g_stB_w1[32ul * NCH_W1 * PAIR_BYTES];
DEVBUF unsigned char g_stB_q[4ul * NCH_Q * PAIR_BYTES];
DEVBUF unsigned char g_stB_dec[32ul * NCH_DEC * PAIR_BYTES];
DEVBUF unsigned char g_stDWr[32ul * 16 * PAIR_BYTES];   // decoder Wh split tiles
DEVBUF __nv_bfloat16 g_hsplitH[2][B_ * DH_];
DEVBUF __nv_bfloat16 g_hsplitL[2][B_ * DH_];
__device__ unsigned g_bar;

__device__ __forceinline__ float sigm(float x) { return 1.f / (1.f + expf(-x)); }
__device__ __forceinline__ unsigned swz(unsigned o) { return o ^ ((o >> 3) & 0x70); }

__device__ __forceinline__ uint32_t smem_u32(const void* p) {
    uint32_t a;
    asm("{ .reg .u64 t; cvta.to.shared.u64 t, %1; cvt.u32.u64 %0, t; }" : "=r"(a) : "l"(p));
    return a;
}
__device__ __forceinline__ void cp_async16(uint32_t dst, const void* src) {
    asm volatile("cp.async.cg.shared.global [%0], [%1], 16;" :: "r"(dst), "l"(src) : "memory");
}
__device__ __forceinline__ void cp_commit() {
    asm volatile("cp.async.commit_group;" ::: "memory");
}
template <int N>
__device__ __forceinline__ void cp_wait() {
    asm volatile("cp.async.wait_group %0;" :: "n"(N) : "memory");
}
__device__ __forceinline__ void ldm_x4(uint32_t* r, uint32_t addr) {
    asm volatile("ldmatrix.sync.aligned.m8n8.x4.shared.b16 {%0,%1,%2,%3}, [%4];"
                 : "=r"(r[0]), "=r"(r[1]), "=r"(r[2]), "=r"(r[3]) : "r"(addr));
}
__device__ __forceinline__ void mma16816(float* d, const uint32_t* a, const uint32_t* b) {
    asm volatile(
        "mma.sync.aligned.m16n8k16.row.col.f32.bf16.bf16.f32 "
        "{%0,%1,%2,%3},{%4,%5,%6,%7},{%8,%9},{%0,%1,%2,%3};"
        : "+f"(d[0]), "+f"(d[1]), "+f"(d[2]), "+f"(d[3])
        : "r"(a[0]), "r"(a[1]), "r"(a[2]), "r"(a[3]), "r"(b[0]), "r"(b[1]));
}

// ---- bf16 split store into swizzled staging ----
__device__ __forceinline__ void split_store_pair(unsigned char* st, int nCh, int blk,
                                                 int row, int kp, float v0, float v1) {
    int chunk = kp >> 6, kin = kp & 63;
    size_t base = ((size_t)(blk * nCh + chunk)) * PAIR_BYTES;
    unsigned so = swz((unsigned)(row * 128 + kin * 2));
    __nv_bfloat16 h0 = __float2bfloat16(v0), h1 = __float2bfloat16(v1);
    __nv_bfloat16 l0 = __float2bfloat16(v0 - __bfloat162float(h0));
    __nv_bfloat16 l1 = __float2bfloat16(v1 - __bfloat162float(h1));
    *(unsigned*)(st + base + so) =
        (unsigned)__bfloat16_as_ushort(h0) | ((unsigned)__bfloat16_as_ushort(h1) << 16);
    *(unsigned*)(st + base + TILE_BYTES + so) =
        (unsigned)__bfloat16_as_ushort(l0) | ((unsigned)__bfloat16_as_ushort(l1) << 16);
}

// ---- prep ----
__device__ __forceinline__ void pack_region(const float* Wh, float* out, int H, long r) {
    long per = 4L * H * H;
    int dir = (int)(r / per);
    long s = r % per;
    int g = (int)(s & 3), jj = (int)((s >> 2) % H), k = (int)(s / (4 * H));
    out[dir * per + s] = Wh[dir * per + (size_t)(g * H + jj) * H + k];
}
#define R_SWH 524288L
#define R_WWH 2097152L
#define R_DWS 2097152L
#define R_BW0 1179648L
#define R_BW1 2097152L
#define R_BQ 262144L
#define R_BDEC 3276800L
#define R_CEMB 131072L
#define R_PAD 131072L
#define R_EMB 153600L
#define PREP_BLOCKS 56920

__global__ void prep_kernel(const float* __restrict__ sWh0, const float* __restrict__ sWh1,
                            const float* __restrict__ wWh0, const float* __restrict__ wWh1,
                            const float* __restrict__ dWh, const float* __restrict__ wWx0,
                            const float* __restrict__ wWx1, const float* __restrict__ Wq,
                            const float* __restrict__ dWx, const int* __restrict__ words,
                            const float* __restrict__ char_table, const int* __restrict__ sents,
                            const float* __restrict__ word_embs) {
    long idx = (long)blockIdx.x * 256 + threadIdx.x;
    if (idx < R_SWH) { pack_region(sWh0, g_sWh0P, SH_, idx); return; }
    idx -= R_SWH;
    if (idx < R_SWH) { pack_region(sWh1, g_sWh1P, SH_, idx); return; }
    idx -= R_SWH;
    if (idx < R_WWH) { pack_region(wWh0, g_wWh0P, WH_, idx); return; }
    idx -= R_WWH;
    if (idx < R_WWH) { pack_region(wWh1, g_wWh1P, WH_, idx); return; }
    idx -= R_WWH;
    if (idx < R_DWS) {
        int n = (int)(idx / 512), kp = 2 * (int)(idx % 512);
        split_store_pair(g_stDWr, 16, n >> 7, n & 127, kp,
                         dWh[(size_t)n * 1024 + kp], dWh[(size_t)n * 1024 + kp + 1]);
        return;
    }
    idx -= R_DWS;
    if (idx < R_BW0) {
        int n = (int)(idx / 288), kp = 2 * (int)(idx % 288);
        float v0 = (kp < 544) ? wWx0[(size_t)n * 544 + kp] : 0.f;
        float v1 = (kp + 1 < 544) ? wWx0[(size_t)n * 544 + kp + 1] : 0.f;
        split_store_pair(g_stB_w0, NCH_W0, n >> 7, n & 127, kp, v0, v1);
        return;
    }
    idx -= R_BW0;
    if (idx < R_BW1) {
        int n = (int)(idx / 512), kp = 2 * (int)(idx % 512);
        split_store_pair(g_stB_w1, NCH_W1, n >> 7, n & 127, kp,
                         wWx1[(size_t)n * 1024 + kp], wWx1[(size_t)n * 1024 + kp + 1]);
        return;
    }
    idx -= R_BW1;
    if (idx < R_BQ) {
        int n = (int)(idx / 512), kp = 2 * (int)(idx % 512);
        split_store_pair(g_stB_q, NCH_Q, n >> 7, n & 127, kp,
                         Wq[(size_t)kp * 512 + n], Wq[(size_t)(kp + 1) * 512 + n]);
        return;
    }
    idx -= R_BQ;
    if (idx < R_BDEC) {
        int n = (int)(idx / 800), kp = 2 * (int)(idx % 800);
        float v0 = (kp < 1544) ? dWx[(size_t)n * 1544 + kp] : 0.f;
        float v1 = (kp + 1 < 1544) ? dWx[(size_t)n * 1544 + kp + 1] : 0.f;
        split_store_pair(g_stB_dec, NCH_DEC, n >> 7, n & 127, kp, v0, v1);
        return;
    }
    idx -= R_BDEC;
    if (idx < R_CEMB) {
        int r = (int)(idx / 16), kp = 2 * (int)(idx % 16);
        int w = words[r];
        split_store_pair(g_stageA, NCH_W0, r >> 7, r & 127, kp,
                         char_table[w * 32 + kp], char_table[w * 32 + kp + 1]);
        return;
    }
    idx -= R_CEMB;
    if (idx < R_PAD) {
        int r = (int)(idx / 16), kp = 544 + 2 * (int)(idx % 16);
        split_store_pair(g_stageA, NCH_W0, r >> 7, r & 127, kp, 0.f, 0.f);
        return;
    }
    idx -= R_PAD;
    if (idx < R_EMB) {
        int r = (int)(idx / 300), d = (int)(idx % 300);
        g_wembs[r * 300 + d] = word_embs[(size_t)sents[r] * 300 + d];
    }
}

__global__ void splitA_kernel(const float* __restrict__ src, int K, int nCh) {
    long idx = (long)blockIdx.x * 256 + threadIdx.x;
    int ppr = K >> 1;
    int r = (int)(idx / ppr), kp = 2 * (int)(idx % ppr);
    split_store_pair(g_stageA, nCh, r >> 7, r & 127, kp,
                     src[(size_t)r * K + kp], src[(size_t)r * K + kp + 1]);
}

__global__ void build_final_split_kernel(const float* __restrict__ attn_enc,
                                         const float* __restrict__ char_enc,
                                         const int* __restrict__ labels) {
    long idx = (long)blockIdx.x * 256 + threadIdx.x;
    int r = (int)(idx / 800), kp = 2 * (int)(idx % 800);
    float v[2];
#pragma unroll
    for (int u = 0; u < 2; ++u) {
        int c = kp + u;
        float x;
        if (c < 512)       x = attn_enc[(size_t)r * 512 + c];
        else if (c < 1536) x = char_enc[(size_t)r * 1024 + (c - 512)];
        else if (c < 1544) x = (float)labels[r * 8 + (c - 1536)];
        else               x = 0.f;
        v[u] = x;
    }
    split_store_pair(g_stageA, NCH_DEC, r >> 7, r & 127, kp, v[0], v[1]);
}

__global__ void zero_dec_kernel() {
    int i = blockIdx.x * 256 + threadIdx.x;
    if (i < B_ * DH_) {
        g_hsplitH[0][i] = __float2bfloat16(0.f);
        g_hsplitL[0][i] = __float2bfloat16(0.f);
    }
    if (i == 0) g_bar = 0u;
}

// ---- HMMA GEMM: C = A@W^T (+bias), split-bf16 ----
__global__ void __launch_bounds__(256) tgemm_kernel(
    const unsigned char* __restrict__ stA, const unsigned char* __restrict__ stB,
    const float* __restrict__ bias, float* __restrict__ C, int N, int nCh) {
    extern __shared__ unsigned char smraw[];
    uint32_t smb = smem_u32(smraw);
    uint32_t ab = (smb + 1023) & ~1023u;
    int tid = threadIdx.x, lane = tid & 31, wid = tid >> 5;
    int wm = wid & 1, wn = wid >> 1;
    int nb = blockIdx.x, mb = blockIdx.y;

    float acc[4][4][4];
#pragma unroll
    for (int i = 0; i < 4; ++i)
#pragma unroll
        for (int j = 0; j < 4; ++j)
#pragma unroll
            for (int k = 0; k < 4; ++k) acc[i][j][k] = 0.f;

    int ar = (lane & 7) + ((lane >> 3) & 1) * 8;
    int ac = (lane >> 4) * 16;
    int br = (lane & 7) + ((lane >> 4) & 1) * 8;
    int bc = ((lane >> 3) & 1) * 16;

    auto issue = [&](int c) {
        uint32_t dst = ab + (c & 1) * 65536;
        const unsigned char* sA = stA + ((size_t)mb * nCh + c) * PAIR_BYTES;
        const unsigned char* sB = stB + ((size_t)nb * nCh + c) * PAIR_BYTES;
#pragma unroll
        for (int i = 0; i < 8; ++i)
            cp_async16(dst + (tid + i * 256) * 16, sA + (tid + i * 256) * 16);
#pragma unroll
        for (int i = 0; i < 8; ++i)
            cp_async16(dst + 32768 + (tid + i * 256) * 16, sB + (tid + i * 256) * 16);
        cp_commit();
    };

    issue(0);
    for (int c = 0; c < nCh; ++c) {
        if (c + 1 < nCh) { issue(c + 1); cp_wait<1>(); }
        else             { cp_wait<0>(); }
        __syncthreads();
        uint32_t base = ab + (c & 1) * 65536;
#pragma unroll
        for (int ks = 0; ks < 4; ++ks) {
            uint32_t ah[4][4], al[4][4], bh[2][4], bl[2][4];
#pragma unroll
            for (int mf = 0; mf < 4; ++mf) {
                uint32_t off = swz((unsigned)((wm * 64 + mf * 16 + ar) * 128 + ac + ks * 32));
                ldm_x4(ah[mf], base + off);
                ldm_x4(al[mf], base + 16384 + off);
            }
#pragma unroll
            for (int nf2 = 0; nf2 < 2; ++nf2) {
                uint32_t off = swz((unsigned)((wn * 32 + nf2 * 16 + br) * 128 + bc + ks * 32));
                ldm_x4(bh[nf2], base + 32768 + off);
                ldm_x4(bl[nf2], base + 49152 + off);
            }
#pragma unroll
            for (int mf = 0; mf < 4; ++mf)
#pragma unroll
                for (int nf = 0; nf < 4; ++nf) {
                    mma16816(acc[mf][nf], ah[mf], &bh[nf >> 1][(nf & 1) * 2]);
                    mma16816(acc[mf][nf], ah[mf], &bl[nf >> 1][(nf & 1) * 2]);
                    mma16816(acc[mf][nf], al[mf], &bh[nf >> 1][(nf & 1) * 2]);
                }
        }
        __syncthreads();
    }
#pragma unroll
    for (int mf = 0; mf < 4; ++mf) {
#pragma unroll
        for (int nf = 0; nf < 4; ++nf) {
            int row = mb * 128 + wm * 64 + mf * 16 + (lane >> 2);
            int col = nb * 128 + wn * 32 + nf * 8 + (lane & 3) * 2;
            float b0 = bias ? bias[col] : 0.f;
            float b1 = bias ? bias[col + 1] : 0.f;
            float2 v0 = make_float2(acc[mf][nf][0] + b0, acc[mf][nf][1] + b1);
            float2 v1 = make_float2(acc[mf][nf][2] + b0, acc[mf][nf][3] + b1);
            *(float2*)(C + (size_t)row * N + col) = v0;
            *(float2*)(C + (size_t)(row + 8) * N + col) = v1;
        }
    }
}

// ---- persistent HMMA decoder: 128 blocks, grid-sync per step ----
__global__ void __launch_bounds__(256) dec_persist_kernel(
    const float* __restrict__ pre, float* __restrict__ dout) {
    extern __shared__ unsigned char dsm[];
    uint32_t smb = smem_u32(dsm);
    int tid = threadIdx.x, lane = tid & 31, w = tid >> 5;
    int bid = blockIdx.x;

    // Load weight slice once: 16 chunks x [hi 4KB | lo 4KB]; rows = [g0..g3] x 8
    {
        const uint4* src = (const uint4*)g_stDWr;
        uint4* dst = (uint4*)dsm;
#pragma unroll 4
        for (int it = 0; it < 32; ++it) {
            int flat = tid + it * 256;
            int q = flat & 7;
            int ru = flat >> 3;
            int i = ru & 7;
            int hl = (ru >> 3) & 1;
            int g = (ru >> 4) & 3;
            int c = ru >> 6;
            size_t sb = ((((size_t)(g * 8 + (bid >> 4)) * 16 + c) * PAIR_BYTES
                         + (size_t)hl * TILE_BYTES
                         + (size_t)((bid & 15) * 8 + i) * 128) >> 4) + q;
            int db = ((c * 8192 + hl * 4096 + (g * 8 + i) * 128) >> 4) + q;
            dst[db] = src[sb];
        }
    }
    __syncthreads();

    float* red = (float*)(dsm + 131072);
    const unsigned* hHr[2] = {(const unsigned*)&g_hsplitH[0][0], (const unsigned*)&g_hsplitH[1][0]};
    const unsigned* hLr[2] = {(const unsigned*)&g_hsplitL[0][0], (const unsigned*)&g_hsplitL[1][0]};

    int bb = tid >> 3, hh = tid & 7;
    int j = bid * 8 + hh;
    float cc = 0.f;

    int br = (lane & 7) + ((lane >> 4) & 1) * 8;
    int bc = ((lane >> 3) & 1) * 16;
    int k0base = w * 128;

    for (int t = 0; t < 256; ++t) {
        int rb = t & 1;
        float acc[2][4][4];
#pragma unroll
        for (int m = 0; m < 2; ++m)
#pragma unroll
            for (int g = 0; g < 4; ++g)
#pragma unroll
                for (int r4 = 0; r4 < 4; ++r4) acc[m][g][r4] = 0.f;

#pragma unroll 2
        for (int kf = 0; kf < 8; ++kf) {
            int k0 = k0base + kf * 16;
            uint32_t ah[2][4], al[2][4];
#pragma unroll
            for (int m = 0; m < 2; ++m) {
                int base2 = ((m * 16 + (lane >> 2)) * 1024 + k0) / 2 + (lane & 3);
                ah[m][0] = __ldcg(hHr[rb] + base2);
                ah[m][1] = __ldcg(hHr[rb] + base2 + 4096);
                ah[m][2] = __ldcg(hHr[rb] + base2 + 4);
                ah[m][3] = __ldcg(hHr[rb] + base2 + 4100);
                al[m][0] = __ldcg(hLr[rb] + base2);
                al[m][1] = __ldcg(hLr[rb] + base2 + 4096);
                al[m][2] = __ldcg(hLr[rb] + base2 + 4);
                al[m][3] = __ldcg(hLr[rb] + base2 + 4100);
            }
            int chunk = k0 >> 6, kin = k0 & 63;
            uint32_t cbs = smb + chunk * 8192;
            uint32_t bh[2][4], bl[2][4];
#pragma unroll
            for (int nt = 0; nt < 2; ++nt) {
                uint32_t off = swz((unsigned)((nt * 16 + br) * 128 + bc + kin * 2));
                ldm_x4(bh[nt], cbs + off);
                ldm_x4(bl[nt], cbs + 4096 + off);
            }
#pragma unroll
            for (int m = 0; m < 2; ++m)
#pragma unroll
                for (int g = 0; g < 4; ++g) {
                    mma16816(acc[m][g], ah[m], &bh[g >> 1][(g & 1) * 2]);
                    mma16816(acc[m][g], ah[m], &bl[g >> 1][(g & 1) * 2]);
                    mma16816(acc[m][g], al[m], &bh[g >> 1][(g & 1) * 2]);
                }
        }
        // write partials to smem
#pragma unroll
        for (int m = 0; m < 2; ++m)
#pragma unroll
            for (int g = 0; g < 4; ++g)
#pragma unroll
                for (int r4 = 0; r4 < 4; ++r4)
                    red[((w * 2 + m) * 4 + g) * 128 + lane * 4 + r4] = acc[m][g][r4];
        __syncthreads();

        // gather + activation: thread owns (batch bb, hcol hh)
        {
            int r = bb & 15, m = bb >> 4;
            int gl = ((r & 7) << 2) | (hh >> 1);
            int rg = (hh & 1) + 2 * ((r >> 3) & 1);
            float gv[4] = {0.f, 0.f, 0.f, 0.f};
#pragma unroll
            for (int w2 = 0; w2 < 8; ++w2)
#pragma unroll
                for (int g = 0; g < 4; ++g)
                    gv[g] += red[((w2 * 2 + m) * 4 + g) * 128 + gl * 4 + rg];
            const float* p = pre + ((size_t)bb * 256 + t) * 4096 + j;
            float ai = gv[0] + p[0];
            float af = gv[1] + p[1024];
            float agg = gv[2] + p[2048];
            float ao = gv[3] + p[3072];
            cc = sigm(af) * cc + sigm(ai) * tanhf(agg);
            float hn = sigm(ao) * tanhf(cc);
            dout[((size_t)bb * 256 + t) * 1024 + j] = hn;
            __nv_bfloat16 hi = __float2bfloat16(hn);
            __nv_bfloat16 lo = __float2bfloat16(hn - __bfloat162float(hi));
            g_hsplitH[rb ^ 1][bb * 1024 + j] = hi;
            g_hsplitL[rb ^ 1][bb * 1024 + j] = lo;
        }
        __threadfence();
        __syncthreads();
        if (tid == 0) {
            atomicAdd(&g_bar, 1u);
            unsigned tgt = (unsigned)(t + 1) * 128u;
            while (*(volatile unsigned*)&g_bar < tgt) {}
        }
        __syncthreads();
    }
}

// ---- SIMT SGEMM (sentence layers) ----
__global__ void __launch_bounds__(256) sgemm128_kernel(
    const float* __restrict__ A, const float* __restrict__ W,
    const float* __restrict__ bias, float* __restrict__ C, int M, int N, int K) {
    __shared__ __align__(16) float As[2][8][132];
    __shared__ __align__(16) float Bs[2][8][132];
    int tid = threadIdx.x;
    int m0 = blockIdx.y * 128, n0 = blockIdx.x * 128;
    int grow = tid >> 1, gk = (tid & 1) * 4;
    const float* Ap = A + (size_t)(m0 + grow) * K + gk;
    const float* Wp = W + (size_t)(n0 + grow) * K + gk;
    int tm4 = (tid >> 4) * 4, tn4 = (tid & 15) * 4;
    float acc[8][8];
#pragma unroll
    for (int i = 0; i < 8; ++i)
#pragma unroll
        for (int j = 0; j < 8; ++j) acc[i][j] = 0.f;
    int nk = (K + 7) / 8;
    float4 pa, pb;
    pa = (gk < K) ? *(const float4*)Ap : make_float4(0, 0, 0, 0);
    pb = (gk < K) ? *(const float4*)Wp : make_float4(0, 0, 0, 0);
    As[0][gk + 0][grow] = pa.x; As[0][gk + 1][grow] = pa.y;
    As[0][gk + 2][grow] = pa.z; As[0][gk + 3][grow] = pa.w;
    Bs[0][gk + 0][grow] = pb.x; Bs[0][gk + 1][grow] = pb.y;
    Bs[0][gk + 2][grow] = pb.z; Bs[0][gk + 3][grow] = pb.w;
    __syncthreads();
    for (int it = 0; it < nk; ++it) {
        int buf = it & 1;
        bool more = (it + 1) < nk;
        if (more) {
            int kt = (it + 1) * 8;
            pa = (kt + gk < K) ? *(const float4*)(Ap + kt) : make_float4(0, 0, 0, 0);
            pb = (kt + gk < K) ? *(const float4*)(Wp + kt) : make_float4(0, 0, 0, 0);
        }
#pragma unroll
        for (int kk = 0; kk < 8; ++kk) {
            float4 a0 = *(const float4*)&As[buf][kk][tm4];
            float4 a1 = *(const float4*)&As[buf][kk][tm4 + 64];
            float4 b0 = *(const float4*)&Bs[buf][kk][tn4];
            float4 b1 = *(const float4*)&Bs[buf][kk][tn4 + 64];
            float av[8] = {a0.x, a0.y, a0.z, a0.w, a1.x, a1.y, a1.z, a1.w};
            float bv[8] = {b0.x, b0.y, b0.z, b0.w, b1.x, b1.y, b1.z, b1.w};
#pragma unroll
            for (int i = 0; i < 8; ++i)
#pragma unroll
                for (int j = 0; j < 8; ++j) acc[i][j] += av[i] * bv[j];
        }
        if (more) {
            int nb2 = buf ^ 1;
            As[nb2][gk + 0][grow] = pa.x; As[nb2][gk + 1][grow] = pa.y;
            As[nb2][gk + 2][grow] = pa.z; As[nb2][gk + 3][grow] = pa.w;
            Bs[nb2][gk + 0][grow] = pb.x; Bs[nb2][gk + 1][grow] = pb.y;
            Bs[nb2][gk + 2][grow] = pb.z; Bs[nb2][gk + 3][grow] = pb.w;
        }
        __syncthreads();
    }
    float bb0[4] = {0, 0, 0, 0}, bb1[4] = {0, 0, 0, 0};
    if (bias) {
#pragma unroll
        for (int j = 0; j < 4; ++j) { bb0[j] = bias[n0 + tn4 + j]; bb1[j] = bias[n0 + tn4 + 64 + j]; }
    }
#pragma unroll
    for (int i = 0; i < 8; ++i) {
        int r = m0 + tm4 + (i & 3) + ((i >> 2) << 6);
        float4 v0 = make_float4(acc[i][0] + bb0[0], acc[i][1] + bb0[1], acc[i][2] + bb0[2], acc[i][3] + bb0[3]);
        float4 v1 = make_float4(acc[i][4] + bb1[0], acc[i][5] + bb1[1], acc[i][6] + bb1[2], acc[i][7] + bb1[3]);
        *(float4*)(C + (size_t)r * N + n0 + tn4) = v0;
        *(float4*)(C + (size_t)r * N + n0 + tn4 + 64) = v1;
    }
}

// ---- BiLSTM recurrence; STAGE fuses char-input staging ----
template <int H, int BSEQ, int PS, bool STAGE>
__global__ void lstm_rec_kernel(const float* __restrict__ pre,
                                const float* __restrict__ WhP, int whStride,
                                float* __restrict__ out, int T,
                                const int* __restrict__ words) {
    int dir = blockIdx.y;
    const float4* W4 = (const float4*)(WhP + (size_t)dir * whStride);
    int n0 = blockIdx.x * BSEQ;
    int j = threadIdx.x;
    __shared__ __align__(16) float sh[H * PS];
    __shared__ float wm[BSEQ * 256];
    float cc[BSEQ], ai[BSEQ], af[BSEQ], ag[BSEQ], ao[BSEQ];
#pragma unroll
    for (int s = 0; s < BSEQ; ++s) { cc[s] = 0.f; sh[j * PS + s] = 0.f; }
    if (STAGE) {
        for (int x = threadIdx.x; x < BSEQ * 256; x += H)
            wm[x] = (words[(n0 + x / 256) * 256 + (x & 255)] != 0) ? 1.f : 0.f;
    }
    __syncthreads();
    for (int tt = 0; tt < T; ++tt) {
        int t = dir ? (T - 1 - tt) : tt;
#pragma unroll
        for (int s = 0; s < BSEQ; ++s) {
            const float* p = pre + (((size_t)(n0 + s) * T + t) * 2 + dir) * (4 * H);
            ai[s] = p[j]; af[s] = p[H + j]; ag[s] = p[2 * H + j]; ao[s] = p[3 * H + j];
        }
#pragma unroll 4
        for (int k = 0; k < H; ++k) {
            float4 w = W4[k * H + j];
            if constexpr (BSEQ == 8) {
                float4 h0 = *(const float4*)&sh[k * PS];
                float4 h1 = *(const float4*)&sh[k * PS + 4];
                float hv[8] = {h0.x, h0.y, h0.z, h0.w, h1.x, h1.y, h1.z, h1.w};
#pragma unroll
                for (int s = 0; s < 8; ++s) {
                    ai[s] += hv[s] * w.x; af[s] += hv[s] * w.y;
                    ag[s] += hv[s] * w.z; ao[s] += hv[s] * w.w;
                }
            } else {
#pragma unroll
                for (int s = 0; s < BSEQ; ++s) {
                    float hk = sh[k * PS + s];
                    ai[s] += hk * w.x; af[s] += hk * w.y;
                    ag[s] += hk * w.z; ao[s] += hk * w.w;
                }
            }
        }
        __syncthreads();
#pragma unroll
        for (int s = 0; s < BSEQ; ++s) {
            float c = sigm(af[s]) * cc[s] + sigm(ai[s]) * tanhf(ag[s]);
            float hn = sigm(ao[s]) * tanhf(c);
            cc[s] = c;
            sh[j * PS + s] = hn;
            out[(((size_t)(n0 + s) * T + t)) * (2 * H) + dir * H + j] = hn;
            if constexpr (STAGE) {
                float v1 = __shfl_down_sync(0xffffffffu, hn, 1);
                if (!(j & 1)) {
                    int kp = 32 + dir * H + j;
                    int rb = ((n0 + s) * 16 + t) * 16;
                    int blk = rb >> 7;
#pragma unroll
                    for (int tw = 0; tw < 16; ++tw) {
                        float m = wm[s * 256 + t * 16 + tw];
                        split_store_pair(g_stageA, NCH_W0, blk, (rb & 127) + tw, kp, hn * m, v1 * m);
                    }
                }
            }
        }
        __syncthreads();
    }
}

// ---- attention ----
__global__ void attention_kernel(const float* __restrict__ q, const float* __restrict__ sent_enc,
                                 const int* __restrict__ words, float* __restrict__ attn_enc,
                                 float* __restrict__ map_out) {
    int bi = blockIdx.x, b = bi >> 4, i = bi & 15;
    __shared__ float se[16 * 513];
    __shared__ float sc[16][16];
    __shared__ float mp[16][16];
    __shared__ int kv[16];
    for (int x = threadIdx.x; x < 16 * 512; x += 256) {
        int jj = x >> 9, d = x & 511;
        se[jj * 513 + d] = sent_enc[((size_t)b * 16 + jj) * 512 + d];
    }
    if (threadIdx.x < 16) {
        int jj = threadIdx.x, any = 0;
        for (int tw = 0; tw < 16; ++tw) any |= (words[(b * 16 + jj) * 16 + tw] != 0);
        kv[jj] = any;
    }
    __syncthreads();
    {
        int cdx = threadIdx.x >> 4, jj = threadIdx.x & 15;
        const float* qr = q + ((size_t)bi * 16 + cdx) * 512;
        const float* ser = se + jj * 513;
        float s = 0.f;
#pragma unroll 4
        for (int d = 0; d < 512; ++d) s += qr[d] * ser[d];
        sc[cdx][jj] = s;
    }
    __syncthreads();
    if (threadIdx.x < 16) {
        int cdx = threadIdx.x;
        float v[16], m = -1e30f;
#pragma unroll
        for (int jj = 0; jj < 16; ++jj) {
            bool valid = (kv[jj] != 0) && (jj != i);
            v[jj] = valid ? sc[cdx][jj] : -1e9f;
            m = fmaxf(m, v[jj]);
        }
        float sum = 0.f;
#pragma unroll
        for (int jj = 0; jj < 16; ++jj) { v[jj] = expf(v[jj] - m); sum += v[jj]; }
        float inv = 1.f / sum;
#pragma unroll
        for (int jj = 0; jj < 16; ++jj) mp[cdx][jj] = v[jj] * inv;
    }
    __syncthreads();
    if (map_out != nullptr && threadIdx.x < 256) {
        int x = threadIdx.x;
        map_out[(size_t)bi * 256 + x] = mp[x >> 4][x & 15];
    }
    for (int x = threadIdx.x; x < 16 * 512; x += 256) {
        int cdx = x >> 9, d = x & 511;
        float s = 0.f;
#pragma unroll
        for (int jj = 0; jj < 16; ++jj) s += mp[cdx][jj] * se[jj * 513 + d];
        attn_enc[((size_t)bi * 16 + cdx) * 512 + d] = s;
    }
}

__global__ void classifier_kernel(const float* __restrict__ dec_out, const float* __restrict__ W,
                                  const float* __restrict__ bias, float* __restrict__ out) {
    int m = blockIdx.x * 16 + (threadIdx.x >> 4);
    int n = threadIdx.x & 15;
    if (n >= 15) return;
    const float* x = dec_out + (size_t)m * 1024;
    float s = bias[n];
#pragma unroll 4
    for (int k = 0; k < 1024; ++k) s += x[k] * W[k * 15 + n];
    out[(size_t)m * 15 + n] = s;
}

// ---- host ----
static void* symp(const void* s) { void* p = nullptr; cudaGetSymbolAddress(&p, s); return p; }

extern "C" void kernel_launch(void* const* d_in, const int* in_sizes, int n_in,
                              void* d_out, int out_size) {
    (void)in_sizes; (void)n_in;
    const int* sents = (const int*)d_in[0];
    const int* words = (const int*)d_in[1];
    const int* labels = (const int*)d_in[2];
    const float* word_embs = (const float*)d_in[3];
    const float* char_table = (const float*)d_in[4];
    const float* sWx0 = (const float*)d_in[5];
    const float* sWh0 = (const float*)d_in[6];
    const float* sb0 = (const float*)d_in[7];
    const float* sWx1 = (const float*)d_in[8];
    const float* sWh1 = (const float*)d_in[9];
    const float* sb1 = (const float*)d_in[10];
    const float* wWx0 = (const float*)d_in[11];
    const float* wWh0 = (const float*)d_in[12];
    const float* wb0 = (const float*)d_in[13];
    const float* wWx1 = (const float*)d_in[14];
    const float* wWh1 = (const float*)d_in[15];
    const float* wb1 = (const float*)d_in[16];
    const float* Wq = (const float*)d_in[17];
    const float* dWx = (const float*)d_in[18];
    const float* dWh = (const float*)d_in[19];
    const float* db = (const float*)d_in[20];
    const float* clsW = (const float*)d_in[21];
    const float* clsb = (const float*)d_in[22];
    float* out = (float*)d_out;

    float* wembs = (float*)symp(g_wembs);
    float* pre_s = (float*)symp(g_pre_s);
    float* sent_h0 = (float*)symp(g_sent_h0);
    float* sent_enc = (float*)symp(g_sent_enc);
    float* pre_w = (float*)symp(g_pre_w);
    float* word_h0 = (float*)symp(g_word_h0);
    float* char_enc = (float*)symp(g_char_enc);
    float* qbuf = (float*)symp(g_q);
    float* attn_enc = (float*)symp(g_attn_enc);
    float* pre_d = (float*)symp(g_pre_d);
    float* dec_out = (float*)symp(g_dec_out);
    float* sWh0P = (float*)symp(g_sWh0P);
    float* sWh1P = (float*)symp(g_sWh1P);
    float* wWh0P = (float*)symp(g_wWh0P);
    float* wWh1P = (float*)symp(g_wWh1P);
    const unsigned char* stA = (const unsigned char*)symp(g_stageA);
    const unsigned char* stBw0 = (const unsigned char*)symp(g_stB_w0);
    const unsigned char* stBw1 = (const unsigned char*)symp(g_stB_w1);
    const unsigned char* stBq = (const unsigned char*)symp(g_stB_q);
    const unsigned char* stBdec = (const unsigned char*)symp(g_stB_dec);

    cudaFuncSetAttribute(tgemm_kernel, cudaFuncAttributeMaxDynamicSharedMemorySize, TG_SMEM);
    cudaFuncSetAttribute(dec_persist_kernel, cudaFuncAttributeMaxDynamicSharedMemorySize, DEC_SMEM);

    const int sStride = SH_ * SH_ * 4;
    const int wStride = WH_ * WH_ * 4;

    prep_kernel<<<PREP_BLOCKS, 256>>>(sWh0, sWh1, wWh0, wWh1, dWh, wWx0, wWx1, Wq, dWx,
                                      words, char_table, sents, word_embs);
    zero_dec_kernel<<<128, 256>>>();
    sgemm128_kernel<<<dim3(16, 4), 256>>>(wembs, sWx0, sb0, pre_s, 512, 2048, 300);
    lstm_rec_kernel<SH_, 2, 2, false><<<dim3(16, 2), SH_>>>(pre_s, sWh0P, sStride, sent_h0, 16, nullptr);
    sgemm128_kernel<<<dim3(16, 4), 256>>>(sent_h0, sWx1, sb1, pre_s, 512, 2048, 512);
    lstm_rec_kernel<SH_, 2, 2, true><<<dim3(16, 2), SH_>>>(pre_s, sWh1P, sStride, sent_enc, 16, words);
    tgemm_kernel<<<dim3(32, 64), 256, TG_SMEM>>>(stA, stBw0, wb0, pre_w, 4096, NCH_W0);
    lstm_rec_kernel<WH_, 8, 12, false><<<dim3(64, 2), WH_>>>(pre_w, wWh0P, wStride, word_h0, 16, nullptr);
    splitA_kernel<<<16384, 256>>>(word_h0, 1024, NCH_W1);
    tgemm_kernel<<<dim3(32, 64), 256, TG_SMEM>>>(stA, stBw1, wb1, pre_w, 4096, NCH_W1);
    lstm_rec_kernel<WH_, 8, 12, false><<<dim3(64, 2), WH_>>>(pre_w, wWh1P, wStride, char_enc, 16, nullptr);
    splitA_kernel<<<16384, 256>>>(char_enc, 1024, NCH_Q);
    tgemm_kernel<<<dim3(4, 64), 256, TG_SMEM>>>(stA, stBq, nullptr, qbuf, 512, NCH_Q);
    float* map_out = (out_size >= (NR_ * 15 + 131072)) ? (out + NR_ * 15) : nullptr;
    attention_kernel<<<NSEQ_, 256>>>(qbuf, sent_enc, words, attn_enc, map_out);
    build_final_split_kernel<<<25600, 256>>>(attn_enc, char_enc, labels);
    tgemm_kernel<<<dim3(32, 64), 256, TG_SMEM>>>(stA, stBdec, db, pre_d, 4096, NCH_DEC);
    dec_persist_kernel<<<128, 256, DEC_SMEM>>>(pre_d, dec_out);
    classifier_kernel<<<NR_ / 16, 256>>>(dec_out, clsW, clsb, out);
}

// round 7
// speedup vs baseline: 5.7678x; 1.1552x over previous
#include <cuda_runtime.h>
#include <cuda_bf16.h>
#include <math.h>
#include <stdint.h>

#define B_ 32
#define SH_ 256
#define WH_ 512
#define DH_ 1024
#define NSEQ_ 512
#define NR_ 8192
#define NCH_W0 9
#define NCH_W1 16
#define NCH_Q 16
#define NCH_DEC 25
#define TILE_BYTES 16384
#define PAIR_BYTES 32768
#define TG_SMEM 131072
#define DEC_SMEM (131072 + 32768)
#define WR_SMEM (131072 + 2 * 49152)

#define DEVBUF __device__ __align__(16)
DEVBUF float g_wembs[NSEQ_ * 300];
DEVBUF float g_pre_s[NSEQ_ * 2048];
DEVBUF float g_sent_h0[NSEQ_ * 512];
DEVBUF float g_sent_enc[NSEQ_ * 512];
DEVBUF float g_pre_w[NR_ * 4096];
DEVBUF float g_char_enc[NR_ * 1024];
DEVBUF float g_q[NR_ * 512];
DEVBUF float g_attn_enc[NR_ * 512];
DEVBUF float g_pre_d[NR_ * 4096];
DEVBUF float g_dec_out[NR_ * 1024];
DEVBUF float g_sWh0P[2 * SH_ * SH_ * 4];
DEVBUF float g_sWh1P[2 * SH_ * SH_ * 4];
DEVBUF unsigned char g_stageA[64ul * 25 * PAIR_BYTES];
DEVBUF unsigned char g_stB_w0[32ul * NCH_W0 * PAIR_BYTES];
DEVBUF unsigned char g_stB_w1[32ul * NCH_W1 * PAIR_BYTES];
DEVBUF unsigned char g_stB_q[4ul * NCH_Q * PAIR_BYTES];
DEVBUF unsigned char g_stB_dec[32ul * NCH_DEC * PAIR_BYTES];
DEVBUF unsigned char g_stDWr[32ul * 16 * PAIR_BYTES];    // decoder Wh tiles
DEVBUF unsigned char g_stWw[4ul * 16 * 8 * PAIR_BYTES];  // word Wh tiles [layer*2+dir][nt][chunk]
DEVBUF unsigned char g_hstage[128ul * PAIR_BYTES];       // word-rec h staging [(dir*2+buf)*4+mb][chunk]
DEVBUF __nv_bfloat16 g_hsplitH[2][B_ * DH_];
DEVBUF __nv_bfloat16 g_hsplitL[2][B_ * DH_];
__device__ unsigned g_bar;
__device__ unsigned g_bar2;

__device__ __forceinline__ float sigm(float x) { return 1.f / (1.f + expf(-x)); }
__device__ __forceinline__ unsigned swz(unsigned o) { return o ^ ((o >> 3) & 0x70); }

__device__ __forceinline__ uint32_t smem_u32(const void* p) {
    uint32_t a;
    asm("{ .reg .u64 t; cvta.to.shared.u64 t, %1; cvt.u32.u64 %0, t; }" : "=r"(a) : "l"(p));
    return a;
}
__device__ __forceinline__ void cp_async16(uint32_t dst, const void* src) {
    asm volatile("cp.async.cg.shared.global [%0], [%1], 16;" :: "r"(dst), "l"(src) : "memory");
}
__device__ __forceinline__ void cp_commit() {
    asm volatile("cp.async.commit_group;" ::: "memory");
}
template <int N>
__device__ __forceinline__ void cp_wait() {
    asm volatile("cp.async.wait_group %0;" :: "n"(N) : "memory");
}
__device__ __forceinline__ void ldm_x4(uint32_t* r, uint32_t addr) {
    asm volatile("ldmatrix.sync.aligned.m8n8.x4.shared.b16 {%0,%1,%2,%3}, [%4];"
                 : "=r"(r[0]), "=r"(r[1]), "=r"(r[2]), "=r"(r[3]) : "r"(addr));
}
__device__ __forceinline__ void mma16816(float* d, const uint32_t* a, const uint32_t* b) {
    asm volatile(
        "mma.sync.aligned.m16n8k16.row.col.f32.bf16.bf16.f32 "
        "{%0,%1,%2,%3},{%4,%5,%6,%7},{%8,%9},{%0,%1,%2,%3};"
        : "+f"(d[0]), "+f"(d[1]), "+f"(d[2]), "+f"(d[3])
        : "r"(a[0]), "r"(a[1]), "r"(a[2]), "r"(a[3]), "r"(b[0]), "r"(b[1]));
}

// ---- bf16 split stores into swizzled staging ----
__device__ __forceinline__ void split_store_pair(unsigned char* st, int nCh, int blk,
                                                 int row, int kp, float v0, float v1) {
    int chunk = kp >> 6, kin = kp & 63;
    size_t base = ((size_t)(blk * nCh + chunk)) * PAIR_BYTES;
    unsigned so = swz((unsigned)(row * 128 + kin * 2));
    __nv_bfloat16 h0 = __float2bfloat16(v0), h1 = __float2bfloat16(v1);
    __nv_bfloat16 l0 = __float2bfloat16(v0 - __bfloat162float(h0));
    __nv_bfloat16 l1 = __float2bfloat16(v1 - __bfloat162float(h1));
    *(unsigned*)(st + base + so) =
        (unsigned)__bfloat16_as_ushort(h0) | ((unsigned)__bfloat16_as_ushort(h1) << 16);
    *(unsigned*)(st + base + TILE_BYTES + so) =
        (unsigned)__bfloat16_as_ushort(l0) | ((unsigned)__bfloat16_as_ushort(l1) << 16);
}
__device__ __forceinline__ void split_store_half(unsigned char* tileBase, int row, int kin,
                                                 float v) {
    unsigned so = swz((unsigned)(row * 128 + kin * 2));
    __nv_bfloat16 hi = __float2bfloat16(v);
    __nv_bfloat16 lo = __float2bfloat16(v - __bfloat162float(hi));
    *(unsigned short*)(tileBase + so) = __bfloat16_as_ushort(hi);
    *(unsigned short*)(tileBase + TILE_BYTES + so) = __bfloat16_as_ushort(lo);
}

// ---- prep ----
__device__ __forceinline__ void pack_region(const float* Wh, float* out, int H, long r) {
    long per = 4L * H * H;
    int dir = (int)(r / per);
    long s = r % per;
    int g = (int)(s & 3), jj = (int)((s >> 2) % H), k = (int)(s / (4 * H));
    out[dir * per + s] = Wh[dir * per + (size_t)(g * H + jj) * H + k];
}
#define R_SWH 524288L
#define R_DWS 2097152L
#define R_WB 2097152L
#define R_BW0 1179648L
#define R_BW1 2097152L
#define R_BQ 262144L
#define R_BDEC 3276800L
#define R_CEMB 131072L
#define R_PAD 131072L
#define R_EMB 153600L
#define PREP_BLOCKS 48728

__global__ void prep_kernel(const float* __restrict__ sWh0, const float* __restrict__ sWh1,
                            const float* __restrict__ wWh0, const float* __restrict__ wWh1,
                            const float* __restrict__ dWh, const float* __restrict__ wWx0,
                            const float* __restrict__ wWx1, const float* __restrict__ Wq,
                            const float* __restrict__ dWx, const int* __restrict__ words,
                            const float* __restrict__ char_table, const int* __restrict__ sents,
                            const float* __restrict__ word_embs) {
    long idx = (long)blockIdx.x * 256 + threadIdx.x;
    if (idx < R_SWH) { pack_region(sWh0, g_sWh0P, SH_, idx); return; }
    idx -= R_SWH;
    if (idx < R_SWH) { pack_region(sWh1, g_sWh1P, SH_, idx); return; }
    idx -= R_SWH;
    if (idx < R_DWS) {
        int n = (int)(idx / 512), kp = 2 * (int)(idx % 512);
        split_store_pair(g_stDWr, 16, n >> 7, n & 127, kp,
                         dWh[(size_t)n * 1024 + kp], dWh[(size_t)n * 1024 + kp + 1]);
        return;
    }
    idx -= R_DWS;
    if (idx < R_WB) {
        // word Wh tiles: row = (j&31)*4 + g within n-tile j>>5
        int ld = (int)(idx >> 19);            // layer*2 + dir
        long e = idx & ((1L << 19) - 1);
        int r = (int)(e >> 8);                // j*4 + g
        int kp = 2 * (int)(e & 255);
        int g = r & 3, j = r >> 2;
        const float* Ws = (ld >> 1) ? wWh1 : wWh0;
        const float* w = Ws + (size_t)(ld & 1) * 4 * 512 * 512 + (size_t)(g * 512 + j) * 512;
        split_store_pair(g_stWw + (size_t)ld * 16 * 8 * PAIR_BYTES, 8, r >> 7, r & 127, kp,
                         w[kp], w[kp + 1]);
        return;
    }
    idx -= R_WB;
    if (idx < R_BW0) {
        int n = (int)(idx / 288), kp = 2 * (int)(idx % 288);
        float v0 = (kp < 544) ? wWx0[(size_t)n * 544 + kp] : 0.f;
        float v1 = (kp + 1 < 544) ? wWx0[(size_t)n * 544 + kp + 1] : 0.f;
        split_store_pair(g_stB_w0, NCH_W0, n >> 7, n & 127, kp, v0, v1);
        return;
    }
    idx -= R_BW0;
    if (idx < R_BW1) {
        int n = (int)(idx / 512), kp = 2 * (int)(idx % 512);
        split_store_pair(g_stB_w1, NCH_W1, n >> 7, n & 127, kp,
                         wWx1[(size_t)n * 1024 + kp], wWx1[(size_t)n * 1024 + kp + 1]);
        return;
    }
    idx -= R_BW1;
    if (idx < R_BQ) {
        int n = (int)(idx / 512), kp = 2 * (int)(idx % 512);
        split_store_pair(g_stB_q, NCH_Q, n >> 7, n & 127, kp,
                         Wq[(size_t)kp * 512 + n], Wq[(size_t)(kp + 1) * 512 + n]);
        return;
    }
    idx -= R_BQ;
    if (idx < R_BDEC) {
        int n = (int)(idx / 800), kp = 2 * (int)(idx % 800);
        float v0 = (kp < 1544) ? dWx[(size_t)n * 1544 + kp] : 0.f;
        float v1 = (kp + 1 < 1544) ? dWx[(size_t)n * 1544 + kp + 1] : 0.f;
        split_store_pair(g_stB_dec, NCH_DEC, n >> 7, n & 127, kp, v0, v1);
        return;
    }
    idx -= R_BDEC;
    if (idx < R_CEMB) {
        int r = (int)(idx / 16), kp = 2 * (int)(idx % 16);
        int w = words[r];
        split_store_pair(g_stageA, NCH_W0, r >> 7, r & 127, kp,
                         char_table[w * 32 + kp], char_table[w * 32 + kp + 1]);
        return;
    }
    idx -= R_CEMB;
    if (idx < R_PAD) {
        int r = (int)(idx / 16), kp = 544 + 2 * (int)(idx % 16);
        split_store_pair(g_stageA, NCH_W0, r >> 7, r & 127, kp, 0.f, 0.f);
        return;
    }
    idx -= R_PAD;
    if (idx < R_EMB) {
        int r = (int)(idx / 300), d = (int)(idx % 300);
        g_wembs[r * 300 + d] = word_embs[(size_t)sents[r] * 300 + d];
    }
}

__global__ void build_final_split_kernel(const float* __restrict__ attn_enc,
                                         const float* __restrict__ char_enc,
                                         const int* __restrict__ labels) {
    long idx = (long)blockIdx.x * 256 + threadIdx.x;
    int r = (int)(idx / 800), kp = 2 * (int)(idx % 800);
    float v[2];
#pragma unroll
    for (int u = 0; u < 2; ++u) {
        int c = kp + u;
        float x;
        if (c < 512)       x = attn_enc[(size_t)r * 512 + c];
        else if (c < 1536) x = char_enc[(size_t)r * 1024 + (c - 512)];
        else if (c < 1544) x = (float)labels[r * 8 + (c - 1536)];
        else               x = 0.f;
        v[u] = x;
    }
    split_store_pair(g_stageA, NCH_DEC, r >> 7, r & 127, kp, v[0], v[1]);
}

__global__ void zero_dec_kernel() {
    int i = blockIdx.x * 256 + threadIdx.x;
    if (i < B_ * DH_) {
        g_hsplitH[0][i] = __float2bfloat16(0.f);
        g_hsplitL[0][i] = __float2bfloat16(0.f);
    }
    if (i == 0) g_bar = 0u;
}

__global__ void zero_hstage_kernel() {
    int i = blockIdx.x * 256 + threadIdx.x;
    if (i < 131072) {
        int dir = i >> 16, w = i & 65535;
        ((uint4*)(g_hstage + (size_t)dir * 64 * PAIR_BYTES))[w] = make_uint4(0, 0, 0, 0);
    }
    if (i == 0) g_bar2 = 0u;
}

// ---- HMMA GEMM: C = A@W^T (+bias), split-bf16 ----
__global__ void __launch_bounds__(256) tgemm_kernel(
    const unsigned char* __restrict__ stA, const unsigned char* __restrict__ stB,
    const float* __restrict__ bias, float* __restrict__ C, int N, int nCh) {
    extern __shared__ unsigned char smraw[];
    uint32_t smb = smem_u32(smraw);
    uint32_t ab = (smb + 1023) & ~1023u;
    int tid = threadIdx.x, lane = tid & 31, wid = tid >> 5;
    int wm = wid & 1, wn = wid >> 1;
    int nb = blockIdx.x, mb = blockIdx.y;

    float acc[4][4][4];
#pragma unroll
    for (int i = 0; i < 4; ++i)
#pragma unroll
        for (int j = 0; j < 4; ++j)
#pragma unroll
            for (int k = 0; k < 4; ++k) acc[i][j][k] = 0.f;

    int ar = (lane & 7) + ((lane >> 3) & 1) * 8;
    int ac = (lane >> 4) * 16;
    int br = (lane & 7) + ((lane >> 4) & 1) * 8;
    int bc = ((lane >> 3) & 1) * 16;

    auto issue = [&](int c) {
        uint32_t dst = ab + (c & 1) * 65536;
        const unsigned char* sA = stA + ((size_t)mb * nCh + c) * PAIR_BYTES;
        const unsigned char* sB = stB + ((size_t)nb * nCh + c) * PAIR_BYTES;
#pragma unroll
        for (int i = 0; i < 8; ++i)
            cp_async16(dst + (tid + i * 256) * 16, sA + (tid + i * 256) * 16);
#pragma unroll
        for (int i = 0; i < 8; ++i)
            cp_async16(dst + 32768 + (tid + i * 256) * 16, sB + (tid + i * 256) * 16);
        cp_commit();
    };

    issue(0);
    for (int c = 0; c < nCh; ++c) {
        if (c + 1 < nCh) { issue(c + 1); cp_wait<1>(); }
        else             { cp_wait<0>(); }
        __syncthreads();
        uint32_t base = ab + (c & 1) * 65536;
#pragma unroll
        for (int ks = 0; ks < 4; ++ks) {
            uint32_t ah[4][4], al[4][4], bh[2][4], bl[2][4];
#pragma unroll
            for (int mf = 0; mf < 4; ++mf) {
                uint32_t off = swz((unsigned)((wm * 64 + mf * 16 + ar) * 128 + ac + ks * 32));
                ldm_x4(ah[mf], base + off);
                ldm_x4(al[mf], base + 16384 + off);
            }
#pragma unroll
            for (int nf2 = 0; nf2 < 2; ++nf2) {
                uint32_t off = swz((unsigned)((wn * 32 + nf2 * 16 + br) * 128 + bc + ks * 32));
                ldm_x4(bh[nf2], base + 32768 + off);
                ldm_x4(bl[nf2], base + 49152 + off);
            }
#pragma unroll
            for (int mf = 0; mf < 4; ++mf)
#pragma unroll
                for (int nf = 0; nf < 4; ++nf) {
                    mma16816(acc[mf][nf], ah[mf], &bh[nf >> 1][(nf & 1) * 2]);
                    mma16816(acc[mf][nf], ah[mf], &bl[nf >> 1][(nf & 1) * 2]);
                    mma16816(acc[mf][nf], al[mf], &bh[nf >> 1][(nf & 1) * 2]);
                }
        }
        __syncthreads();
    }
#pragma unroll
    for (int mf = 0; mf < 4; ++mf) {
#pragma unroll
        for (int nf = 0; nf < 4; ++nf) {
            int row = mb * 128 + wm * 64 + mf * 16 + (lane >> 2);
            int col = nb * 128 + wn * 32 + nf * 8 + (lane & 3) * 2;
            float b0 = bias ? bias[col] : 0.f;
            float b1 = bias ? bias[col + 1] : 0.f;
            float2 v0 = make_float2(acc[mf][nf][0] + b0, acc[mf][nf][1] + b1);
            float2 v1 = make_float2(acc[mf][nf][2] + b0, acc[mf][nf][3] + b1);
            *(float2*)(C + (size_t)row * N + col) = v0;
            *(float2*)(C + (size_t)(row + 8) * N + col) = v1;
        }
    }
}

// ---- persistent HMMA word-LSTM recurrence ----
// 128 blocks: dir(2) x mb(4: 128 seqs) x nt(16: 32 h-cols, gates interleaved).
// B tile rows = (j&31)*4 + g. Bh cached in smem; Ah/Al/Bl streamed per chunk.
__global__ void __launch_bounds__(256) wordrec_kernel(
    const unsigned char* __restrict__ stW, const float* __restrict__ pre,
    float* __restrict__ outF) {
    extern __shared__ unsigned char dsm[];
    uint32_t smb = smem_u32(dsm);
    int tid = threadIdx.x, lane = tid & 31, wid = tid >> 5;
    int wm = wid & 1, wn = wid >> 1;
    int bid = blockIdx.x;
    int dir = bid >> 6, r6 = bid & 63, mb = r6 >> 4, nt = r6 & 15;

    // cache Bh (8 chunks x 16KB)
    {
        const unsigned char* wb = stW + ((size_t)(dir * 16 + nt)) * 8 * PAIR_BYTES;
        uint4* dst = (uint4*)dsm;
#pragma unroll 4
        for (int i = tid; i < 8192; i += 256) {
            int c = i >> 10, w = i & 1023;
            dst[i] = *(const uint4*)(wb + (size_t)c * PAIR_BYTES + w * 16);
        }
    }
    __syncthreads();

    int ar = (lane & 7) + ((lane >> 3) & 1) * 8;
    int ac = (lane >> 4) * 16;
    int br = (lane & 7) + ((lane >> 4) & 1) * 8;
    int bc = ((lane >> 3) & 1) * 16;

    float cacc[4][4][2];
#pragma unroll
    for (int a = 0; a < 4; ++a)
#pragma unroll
        for (int b = 0; b < 4; ++b) { cacc[a][b][0] = 0.f; cacc[a][b][1] = 0.f; }

    for (int t = 0; t < 16; ++t) {
        int rb = t & 1, wbuf = rb ^ 1;
        int tdir = dir ? (15 - t) : t;

        auto issueW = [&](int c) {
            uint32_t dst = smb + 131072 + (c & 1) * 49152;
            const unsigned char* aSrc =
                g_hstage + (((size_t)((dir * 2 + rb) * 4 + mb)) * 8 + c) * PAIR_BYTES;
            const unsigned char* bSrc =
                stW + (((size_t)(dir * 16 + nt)) * 8 + c) * PAIR_BYTES + TILE_BYTES;
#pragma unroll
            for (int i = 0; i < 8; ++i)
                cp_async16(dst + (tid + i * 256) * 16, aSrc + (tid + i * 256) * 16);
#pragma unroll
            for (int i = 0; i < 4; ++i)
                cp_async16(dst + 32768 + (tid + i * 256) * 16, bSrc + (tid + i * 256) * 16);
            cp_commit();
        };

        float acc[4][4][4];
#pragma unroll
        for (int a = 0; a < 4; ++a)
#pragma unroll
            for (int b = 0; b < 4; ++b)
#pragma unroll
                for (int k = 0; k < 4; ++k) acc[a][b][k] = 0.f;

        issueW(0);
        for (int c = 0; c < 8; ++c) {
            if (c + 1 < 8) { issueW(c + 1); cp_wait<1>(); }
            else           { cp_wait<0>(); }
            __syncthreads();
            uint32_t sb = smb + 131072 + (c & 1) * 49152;
            uint32_t bhb = smb + c * 16384;
#pragma unroll
            for (int ks = 0; ks < 4; ++ks) {
                uint32_t ah[4][4], al[4][4], bh[2][4], bl[2][4];
#pragma unroll
                for (int mf = 0; mf < 4; ++mf) {
                    uint32_t off = swz((unsigned)((wm * 64 + mf * 16 + ar) * 128 + ac + ks * 32));
                    ldm_x4(ah[mf], sb + off);
                    ldm_x4(al[mf], sb + 16384 + off);
                }
#pragma unroll
                for (int nf2 = 0; nf2 < 2; ++nf2) {
                    uint32_t off = swz((unsigned)((wn * 32 + nf2 * 16 + br) * 128 + bc + ks * 32));
                    ldm_x4(bh[nf2], bhb + off);
                    ldm_x4(bl[nf2], sb + 32768 + off);
                }
#pragma unroll
                for (int mf = 0; mf < 4; ++mf)
#pragma unroll
                    for (int nf = 0; nf < 4; ++nf) {
                        mma16816(acc[mf][nf], ah[mf], &bh[nf >> 1][(nf & 1) * 2]);
                        mma16816(acc[mf][nf], ah[mf], &bl[nf >> 1][(nf & 1) * 2]);
                        mma16816(acc[mf][nf], al[mf], &bh[nf >> 1][(nf & 1) * 2]);
                    }
            }
            __syncthreads();
        }

        // epilogue: exchange gate halves, activation, writes
#pragma unroll
        for (int mf = 0; mf < 4; ++mf)
#pragma unroll
            for (int nf = 0; nf < 4; ++nf) {
                float p0 = __shfl_xor_sync(0xffffffffu, acc[mf][nf][0], 1);
                float p1 = __shfl_xor_sync(0xffffffffu, acc[mf][nf][1], 1);
                float p2 = __shfl_xor_sync(0xffffffffu, acc[mf][nf][2], 1);
                float p3 = __shfl_xor_sync(0xffffffffu, acc[mf][nf][3], 1);
                if (!(lane & 1)) {
                    int j = nt * 32 + wn * 8 + nf * 2 + ((lane & 3) >> 1);
                    int r0 = wm * 64 + mf * 16 + (lane >> 2);
#pragma unroll
                    for (int rr = 0; rr < 2; ++rr) {
                        int r = r0 + rr * 8;
                        int n = mb * 128 + r;
                        size_t pb = (size_t)(n * 16 + tdir) * 4096 + dir * 2048 + j;
                        float ai = (rr ? acc[mf][nf][2] : acc[mf][nf][0]) + pre[pb];
                        float af = (rr ? acc[mf][nf][3] : acc[mf][nf][1]) + pre[pb + 512];
                        float ag = (rr ? p2 : p0) + pre[pb + 1024];
                        float ao = (rr ? p3 : p1) + pre[pb + 1536];
                        float cv = cacc[mf][nf][rr];
                        cv = sigm(af) * cv + sigm(ai) * tanhf(ag);
                        float hn = sigm(ao) * tanhf(cv);
                        cacc[mf][nf][rr] = cv;
                        // next-step A staging
                        split_store_half(
                            g_hstage + (((size_t)((dir * 2 + wbuf) * 4 + mb)) * 8 + (j >> 6)) * PAIR_BYTES,
                            r, j & 63, hn);
                        // stageA for next GEMM (nCh=16, K=1024, kp = dir*512+j)
                        int rA = n * 16 + tdir, kp = dir * 512 + j;
                        split_store_half(
                            g_stageA + (((size_t)(rA >> 7) * 16 + (kp >> 6))) * PAIR_BYTES,
                            rA & 127, kp & 63, hn);
                        if (outF) outF[(size_t)rA * 1024 + dir * 512 + j] = hn;
                    }
                }
            }
        __threadfence();
        __syncthreads();
        if (tid == 0) {
            atomicAdd(&g_bar2, 1u);
            unsigned tgt = (unsigned)(t + 1) * 128u;
            while (*(volatile unsigned*)&g_bar2 < tgt) {}
        }
        __syncthreads();
    }
}

// ---- persistent HMMA decoder ----
__global__ void __launch_bounds__(256) dec_persist_kernel(
    const float* __restrict__ pre, float* __restrict__ dout) {
    extern __shared__ unsigned char dsm[];
    uint32_t smb = smem_u32(dsm);
    int tid = threadIdx.x, lane = tid & 31, w = tid >> 5;
    int bid = blockIdx.x;
    {
        const uint4* src = (const uint4*)g_stDWr;
        uint4* dst = (uint4*)dsm;
#pragma unroll 4
        for (int it = 0; it < 32; ++it) {
            int flat = tid + it * 256;
            int q = flat & 7;
            int ru = flat >> 3;
            int i = ru & 7;
            int hl = (ru >> 3) & 1;
            int g = (ru >> 4) & 3;
            int c = ru >> 6;
            size_t sb = ((((size_t)(g * 8 + (bid >> 4)) * 16 + c) * PAIR_BYTES
                         + (size_t)hl * TILE_BYTES
                         + (size_t)((bid & 15) * 8 + i) * 128) >> 4) + q;
            int db = ((c * 8192 + hl * 4096 + (g * 8 + i) * 128) >> 4) + q;
            dst[db] = src[sb];
        }
    }
    __syncthreads();

    float* red = (float*)(dsm + 131072);
    const unsigned* hHr[2] = {(const unsigned*)&g_hsplitH[0][0], (const unsigned*)&g_hsplitH[1][0]};
    const unsigned* hLr[2] = {(const unsigned*)&g_hsplitL[0][0], (const unsigned*)&g_hsplitL[1][0]};

    int bb = tid >> 3, hh = tid & 7;
    int j = bid * 8 + hh;
    float cc = 0.f;

    int br = (lane & 7) + ((lane >> 4) & 1) * 8;
    int bc = ((lane >> 3) & 1) * 16;
    int k0base = w * 128;

    for (int t = 0; t < 256; ++t) {
        int rb = t & 1;
        float acc[2][4][4];
#pragma unroll
        for (int m = 0; m < 2; ++m)
#pragma unroll
            for (int g = 0; g < 4; ++g)
#pragma unroll
                for (int r4 = 0; r4 < 4; ++r4) acc[m][g][r4] = 0.f;

#pragma unroll 2
        for (int kf = 0; kf < 8; ++kf) {
            int k0 = k0base + kf * 16;
            uint32_t ah[2][4], al[2][4];
#pragma unroll
            for (int m = 0; m < 2; ++m) {
                int base2 = ((m * 16 + (lane >> 2)) * 1024 + k0) / 2 + (lane & 3);
                ah[m][0] = __ldcg(hHr[rb] + base2);
                ah[m][1] = __ldcg(hHr[rb] + base2 + 4096);
                ah[m][2] = __ldcg(hHr[rb] + base2 + 4);
                ah[m][3] = __ldcg(hHr[rb] + base2 + 4100);
                al[m][0] = __ldcg(hLr[rb] + base2);
                al[m][1] = __ldcg(hLr[rb] + base2 + 4096);
                al[m][2] = __ldcg(hLr[rb] + base2 + 4);
                al[m][3] = __ldcg(hLr[rb] + base2 + 4100);
            }
            int chunk = k0 >> 6, kin = k0 & 63;
            uint32_t cbs = smb + chunk * 8192;
            uint32_t bh[2][4], bl[2][4];
#pragma unroll
            for (int nt = 0; nt < 2; ++nt) {
                uint32_t off = swz((unsigned)((nt * 16 + br) * 128 + bc + kin * 2));
                ldm_x4(bh[nt], cbs + off);
                ldm_x4(bl[nt], cbs + 4096 + off);
            }
#pragma unroll
            for (int m = 0; m < 2; ++m)
#pragma unroll
                for (int g = 0; g < 4; ++g) {
                    mma16816(acc[m][g], ah[m], &bh[g >> 1][(g & 1) * 2]);
                    mma16816(acc[m][g], ah[m], &bl[g >> 1][(g & 1) * 2]);
                    mma16816(acc[m][g], al[m], &bh[g >> 1][(g & 1) * 2]);
                }
        }
#pragma unroll
        for (int m = 0; m < 2; ++m)
#pragma unroll
            for (int g = 0; g < 4; ++g)
#pragma unroll
                for (int r4 = 0; r4 < 4; ++r4)
                    red[((w * 2 + m) * 4 + g) * 128 + lane * 4 + r4] = acc[m][g][r4];
        __syncthreads();
        {
            int r = bb & 15, m = bb >> 4;
            int gl = ((r & 7) << 2) | (hh >> 1);
            int rg = (hh & 1) + 2 * ((r >> 3) & 1);
            float gv[4] = {0.f, 0.f, 0.f, 0.f};
#pragma unroll
            for (int w2 = 0; w2 < 8; ++w2)
#pragma unroll
                for (int g = 0; g < 4; ++g)
                    gv[g] += red[((w2 * 2 + m) * 4 + g) * 128 + gl * 4 + rg];
            const float* p = pre + ((size_t)bb * 256 + t) * 4096 + j;
            float ai = gv[0] + p[0];
            float af = gv[1] + p[1024];
            float agg = gv[2] + p[2048];
            float ao = gv[3] + p[3072];
            cc = sigm(af) * cc + sigm(ai) * tanhf(agg);
            float hn = sigm(ao) * tanhf(cc);
            dout[((size_t)bb * 256 + t) * 1024 + j] = hn;
            __nv_bfloat16 hi = __float2bfloat16(hn);
            __nv_bfloat16 lo = __float2bfloat16(hn - __bfloat162float(hi));
            g_hsplitH[rb ^ 1][bb * 1024 + j] = hi;
            g_hsplitL[rb ^ 1][bb * 1024 + j] = lo;
        }
        __threadfence();
        __syncthreads();
        if (tid == 0) {
            atomicAdd(&g_bar, 1u);
            unsigned tgt = (unsigned)(t + 1) * 128u;
            while (*(volatile unsigned*)&g_bar < tgt) {}
        }
        __syncthreads();
    }
}

// ---- SIMT SGEMM (sentence layers) ----
__global__ void __launch_bounds__(256) sgemm128_kernel(
    const float* __restrict__ A, const float* __restrict__ W,
    const float* __restrict__ bias, float* __restrict__ C, int M, int N, int K) {
    __shared__ __align__(16) float As[2][8][132];
    __shared__ __align__(16) float Bs[2][8][132];
    int tid = threadIdx.x;
    int m0 = blockIdx.y * 128, n0 = blockIdx.x * 128;
    int grow = tid >> 1, gk = (tid & 1) * 4;
    const float* Ap = A + (size_t)(m0 + grow) * K + gk;
    const float* Wp = W + (size_t)(n0 + grow) * K + gk;
    int tm4 = (tid >> 4) * 4, tn4 = (tid & 15) * 4;
    float acc[8][8];
#pragma unroll
    for (int i = 0; i < 8; ++i)
#pragma unroll
        for (int j = 0; j < 8; ++j) acc[i][j] = 0.f;
    int nk = (K + 7) / 8;
    float4 pa, pb;
    pa = (gk < K) ? *(const float4*)Ap : make_float4(0, 0, 0, 0);
    pb = (gk < K) ? *(const float4*)Wp : make_float4(0, 0, 0, 0);
    As[0][gk + 0][grow] = pa.x; As[0][gk + 1][grow] = pa.y;
    As[0][gk + 2][grow] = pa.z; As[0][gk + 3][grow] = pa.w;
    Bs[0][gk + 0][grow] = pb.x; Bs[0][gk + 1][grow] = pb.y;
    Bs[0][gk + 2][grow] = pb.z; Bs[0][gk + 3][grow] = pb.w;
    __syncthreads();
    for (int it = 0; it < nk; ++it) {
        int buf = it & 1;
        bool more = (it + 1) < nk;
        if (more) {
            int kt = (it + 1) * 8;
            pa = (kt + gk < K) ? *(const float4*)(Ap + kt) : make_float4(0, 0, 0, 0);
            pb = (kt + gk < K) ? *(const float4*)(Wp + kt) : make_float4(0, 0, 0, 0);
        }
#pragma unroll
        for (int kk = 0; kk < 8; ++kk) {
            float4 a0 = *(const float4*)&As[buf][kk][tm4];
            float4 a1 = *(const float4*)&As[buf][kk][tm4 + 64];
            float4 b0 = *(const float4*)&Bs[buf][kk][tn4];
            float4 b1 = *(const float4*)&Bs[buf][kk][tn4 + 64];
            float av[8] = {a0.x, a0.y, a0.z, a0.w, a1.x, a1.y, a1.z, a1.w};
            float bv[8] = {b0.x, b0.y, b0.z, b0.w, b1.x, b1.y, b1.z, b1.w};
#pragma unroll
            for (int i = 0; i < 8; ++i)
#pragma unroll
                for (int j = 0; j < 8; ++j) acc[i][j] += av[i] * bv[j];
        }
        if (more) {
            int nb2 = buf ^ 1;
            As[nb2][gk + 0][grow] = pa.x; As[nb2][gk + 1][grow] = pa.y;
            As[nb2][gk + 2][grow] = pa.z; As[nb2][gk + 3][grow] = pa.w;
            Bs[nb2][gk + 0][grow] = pb.x; Bs[nb2][gk + 1][grow] = pb.y;
            Bs[nb2][gk + 2][grow] = pb.z; Bs[nb2][gk + 3][grow] = pb.w;
        }
        __syncthreads();
    }
    float bb0[4] = {0, 0, 0, 0}, bb1[4] = {0, 0, 0, 0};
    if (bias) {
#pragma unroll
        for (int j = 0; j < 4; ++j) { bb0[j] = bias[n0 + tn4 + j]; bb1[j] = bias[n0 + tn4 + 64 + j]; }
    }
#pragma unroll
    for (int i = 0; i < 8; ++i) {
        int r = m0 + tm4 + (i & 3) + ((i >> 2) << 6);
        float4 v0 = make_float4(acc[i][0] + bb0[0], acc[i][1] + bb0[1], acc[i][2] + bb0[2], acc[i][3] + bb0[3]);
        float4 v1 = make_float4(acc[i][4] + bb1[0], acc[i][5] + bb1[1], acc[i][6] + bb1[2], acc[i][7] + bb1[3]);
        *(float4*)(C + (size_t)r * N + n0 + tn4) = v0;
        *(float4*)(C + (size_t)r * N + n0 + tn4 + 64) = v1;
    }
}

// ---- sentence BiLSTM recurrence; STAGE fuses char-input staging ----
template <int H, int BSEQ, int PS, bool STAGE>
__global__ void lstm_rec_kernel(const float* __restrict__ pre,
                                const float* __restrict__ WhP, int whStride,
                                float* __restrict__ out, int T,
                                const int* __restrict__ words) {
    int dir = blockIdx.y;
    const float4* W4 = (const float4*)(WhP + (size_t)dir * whStride);
    int n0 = blockIdx.x * BSEQ;
    int j = threadIdx.x;
    __shared__ __align__(16) float sh[H * PS];
    __shared__ float wm[BSEQ * 256];
    float cc[BSEQ], ai[BSEQ], af[BSEQ], ag[BSEQ], ao[BSEQ];
#pragma unroll
    for (int s = 0; s < BSEQ; ++s) { cc[s] = 0.f; sh[j * PS + s] = 0.f; }
    if (STAGE) {
        for (int x = threadIdx.x; x < BSEQ * 256; x += H)
            wm[x] = (words[(n0 + x / 256) * 256 + (x & 255)] != 0) ? 1.f : 0.f;
    }
    __syncthreads();
    for (int tt = 0; tt < T; ++tt) {
        int t = dir ? (T - 1 - tt) : tt;
#pragma unroll
        for (int s = 0; s < BSEQ; ++s) {
            const float* p = pre + (((size_t)(n0 + s) * T + t) * 2 + dir) * (4 * H);
            ai[s] = p[j]; af[s] = p[H + j]; ag[s] = p[2 * H + j]; ao[s] = p[3 * H + j];
        }
#pragma unroll 8
        for (int k = 0; k < H; ++k) {
            float4 w = W4[k * H + j];
#pragma unroll
            for (int s = 0; s < BSEQ; ++s) {
                float hk = sh[k * PS + s];
                ai[s] += hk * w.x; af[s] += hk * w.y;
                ag[s] += hk * w.z; ao[s] += hk * w.w;
            }
        }
        __syncthreads();
#pragma unroll
        for (int s = 0; s < BSEQ; ++s) {
            float c = sigm(af[s]) * cc[s] + sigm(ai[s]) * tanhf(ag[s]);
            float hn = sigm(ao[s]) * tanhf(c);
            cc[s] = c;
            sh[j * PS + s] = hn;
            out[(((size_t)(n0 + s) * T + t)) * (2 * H) + dir * H + j] = hn;
            if constexpr (STAGE) {
                float v1 = __shfl_down_sync(0xffffffffu, hn, 1);
                if (!(j & 1)) {
                    int kp = 32 + dir * H + j;
                    int rb = ((n0 + s) * 16 + t) * 16;
                    int blk = rb >> 7;
#pragma unroll
                    for (int tw = 0; tw < 16; ++tw) {
                        float m = wm[s * 256 + t * 16 + tw];
                        split_store_pair(g_stageA, NCH_W0, blk, (rb & 127) + tw, kp, hn * m, v1 * m);
                    }
                }
            }
        }
        __syncthreads();
    }
}

// ---- attention ----
__global__ void attention_kernel(const float* __restrict__ q, const float* __restrict__ sent_enc,
                                 const int* __restrict__ words, float* __restrict__ attn_enc,
                                 float* __restrict__ map_out) {
    int bi = blockIdx.x, b = bi >> 4, i = bi & 15;
    __shared__ float se[16 * 513];
    __shared__ float sc[16][16];
    __shared__ float mp[16][16];
    __shared__ int kv[16];
    for (int x = threadIdx.x; x < 16 * 512; x += 256) {
        int jj = x >> 9, d = x & 511;
        se[jj * 513 + d] = sent_enc[((size_t)b * 16 + jj) * 512 + d];
    }
    if (threadIdx.x < 16) {
        int jj = threadIdx.x, any = 0;
        for (int tw = 0; tw < 16; ++tw) any |= (words[(b * 16 + jj) * 16 + tw] != 0);
        kv[jj] = any;
    }
    __syncthreads();
    {
        int cdx = threadIdx.x >> 4, jj = threadIdx.x & 15;
        const float* qr = q + ((size_t)bi * 16 + cdx) * 512;
        const float* ser = se + jj * 513;
        float s = 0.f;
#pragma unroll 4
        for (int d = 0; d < 512; ++d) s += qr[d] * ser[d];
        sc[cdx][jj] = s;
    }
    __syncthreads();
    if (threadIdx.x < 16) {
        int cdx = threadIdx.x;
        float v[16], m = -1e30f;
#pragma unroll
        for (int jj = 0; jj < 16; ++jj) {
            bool valid = (kv[jj] != 0) && (jj != i);
            v[jj] = valid ? sc[cdx][jj] : -1e9f;
            m = fmaxf(m, v[jj]);
        }
        float sum = 0.f;
#pragma unroll
        for (int jj = 0; jj < 16; ++jj) { v[jj] = expf(v[jj] - m); sum += v[jj]; }
        float inv = 1.f / sum;
#pragma unroll
        for (int jj = 0; jj < 16; ++jj) mp[cdx][jj] = v[jj] * inv;
    }
    __syncthreads();
    if (map_out != nullptr && threadIdx.x < 256) {
        int x = threadIdx.x;
        map_out[(size_t)bi * 256 + x] = mp[x >> 4][x & 15];
    }
    for (int x = threadIdx.x; x < 16 * 512; x += 256) {
        int cdx = x >> 9, d = x & 511;
        float s = 0.f;
#pragma unroll
        for (int jj = 0; jj < 16; ++jj) s += mp[cdx][jj] * se[jj * 513 + d];
        attn_enc[((size_t)bi * 16 + cdx) * 512 + d] = s;
    }
}

__global__ void classifier_kernel(const float* __restrict__ dec_out, const float* __restrict__ W,
                                  const float* __restrict__ bias, float* __restrict__ out) {
    int m = blockIdx.x * 16 + (threadIdx.x >> 4);
    int n = threadIdx.x & 15;
    if (n >= 15) return;
    const float* x = dec_out + (size_t)m * 1024;
    float s = bias[n];
#pragma unroll 4
    for (int k = 0; k < 1024; ++k) s += x[k] * W[k * 15 + n];
    out[(size_t)m * 15 + n] = s;
}

// ---- host ----
static void* symp(const void* s) { void* p = nullptr; cudaGetSymbolAddress(&p, s); return p; }

extern "C" void kernel_launch(void* const* d_in, const int* in_sizes, int n_in,
                              void* d_out, int out_size) {
    (void)in_sizes; (void)n_in;
    const int* sents = (const int*)d_in[0];
    const int* words = (const int*)d_in[1];
    const int* labels = (const int*)d_in[2];
    const float* word_embs = (const float*)d_in[3];
    const float* char_table = (const float*)d_in[4];
    const float* sWx0 = (const float*)d_in[5];
    const float* sWh0 = (const float*)d_in[6];
    const float* sb0 = (const float*)d_in[7];
    const float* sWx1 = (const float*)d_in[8];
    const float* sWh1 = (const float*)d_in[9];
    const float* sb1 = (const float*)d_in[10];
    const float* wWx0 = (const float*)d_in[11];
    const float* wWh0 = (const float*)d_in[12];
    const float* wb0 = (const float*)d_in[13];
    const float* wWx1 = (const float*)d_in[14];
    const float* wWh1 = (const float*)d_in[15];
    const float* wb1 = (const float*)d_in[16];
    const float* Wq = (const float*)d_in[17];
    const float* dWx = (const float*)d_in[18];
    const float* dWh = (const float*)d_in[19];
    const float* db = (const float*)d_in[20];
    const float* clsW = (const float*)d_in[21];
    const float* clsb = (const float*)d_in[22];
    float* out = (float*)d_out;

    float* wembs = (float*)symp(g_wembs);
    float* pre_s = (float*)symp(g_pre_s);
    float* sent_h0 = (float*)symp(g_sent_h0);
    float* sent_enc = (float*)symp(g_sent_enc);
    float* pre_w = (float*)symp(g_pre_w);
    float* char_enc = (float*)symp(g_char_enc);
    float* qbuf = (float*)symp(g_q);
    float* attn_enc = (float*)symp(g_attn_enc);
    float* pre_d = (float*)symp(g_pre_d);
    float* dec_out = (float*)symp(g_dec_out);
    float* sWh0P = (float*)symp(g_sWh0P);
    float* sWh1P = (float*)symp(g_sWh1P);
    const unsigned char* stA = (const unsigned char*)symp(g_stageA);
    const unsigned char* stBw0 = (const unsigned char*)symp(g_stB_w0);
    const unsigned char* stBw1 = (const unsigned char*)symp(g_stB_w1);
    const unsigned char* stBq = (const unsigned char*)symp(g_stB_q);
    const unsigned char* stBdec = (const unsigned char*)symp(g_stB_dec);
    const unsigned char* stWw = (const unsigned char*)symp(g_stWw);

    cudaFuncSetAttribute(tgemm_kernel, cudaFuncAttributeMaxDynamicSharedMemorySize, TG_SMEM);
    cudaFuncSetAttribute(dec_persist_kernel, cudaFuncAttributeMaxDynamicSharedMemorySize, DEC_SMEM);
    cudaFuncSetAttribute(wordrec_kernel, cudaFuncAttributeMaxDynamicSharedMemorySize, WR_SMEM);

    const int sStride = SH_ * SH_ * 4;
    const size_t wwLayer = 2ul * 16 * 8 * PAIR_BYTES;

    prep_kernel<<<PREP_BLOCKS, 256>>>(sWh0, sWh1, wWh0, wWh1, dWh, wWx0, wWx1, Wq, dWx,
                                      words, char_table, sents, word_embs);
    zero_dec_kernel<<<128, 256>>>();
    sgemm128_kernel<<<dim3(16, 4), 256>>>(wembs, sWx0, sb0, pre_s, 512, 2048, 300);
    lstm_rec_kernel<SH_, 2, 2, false><<<dim3(16, 2), SH_>>>(pre_s, sWh0P, sStride, sent_h0, 16, nullptr);
    sgemm128_kernel<<<dim3(16, 4), 256>>>(sent_h0, sWx1, sb1, pre_s, 512, 2048, 512);
    lstm_rec_kernel<SH_, 2, 2, true><<<dim3(16, 2), SH_>>>(pre_s, sWh1P, sStride, sent_enc, 16, words);
    // word layer 0
    tgemm_kernel<<<dim3(32, 64), 256, TG_SMEM>>>(stA, stBw0, wb0, pre_w, 4096, NCH_W0);
    zero_hstage_kernel<<<512, 256>>>();
    wordrec_kernel<<<128, 256, WR_SMEM>>>(stWw, pre_w, nullptr);
    // word layer 1
    tgemm_kernel<<<dim3(32, 64), 256, TG_SMEM>>>(stA, stBw1, wb1, pre_w, 4096, NCH_W1);
    zero_hstage_kernel<<<512, 256>>>();
    wordrec_kernel<<<128, 256, WR_SMEM>>>(stWw + wwLayer, pre_w, char_enc);
    // attention
    tgemm_kernel<<<dim3(4, 64), 256, TG_SMEM>>>(stA, stBq, nullptr, qbuf, 512, NCH_Q);
    float* map_out = (out_size >= (NR_ * 15 + 131072)) ? (out + NR_ * 15) : nullptr;
    attention_kernel<<<NSEQ_, 256>>>(qbuf, sent_enc, words, attn_enc, map_out);
    // decoder
    build_final_split_kernel<<<25600, 256>>>(attn_enc, char_enc, labels);
    tgemm_kernel<<<dim3(32, 64), 256, TG_SMEM>>>(stA, stBdec, db, pre_d, 4096, NCH_DEC);
    dec_persist_kernel<<<128, 256, DEC_SMEM>>>(pre_d, dec_out);
    classifier_kernel<<<NR_ / 16, 256>>>(dec_out, clsW, clsb, out);
}

// round 8
// speedup vs baseline: 5.8051x; 1.0065x over previous
#include <cuda_runtime.h>
#include <cuda_bf16.h>
#include <math.h>
#include <stdint.h>

#define B_ 32
#define SH_ 256
#define WH_ 512
#define DH_ 1024
#define NSEQ_ 512
#define NR_ 8192
#define NCH_W0 9
#define NCH_W1 16
#define NCH_Q 16
#define NCH_DEC 25
#define TILE_BYTES 16384
#define PAIR_BYTES 32768
#define TG_SMEM 131072
#define DEC_SMEM (131072 + 32768)
#define WR_SMEM (131072 + 2 * 49152)

#define DEVBUF __device__ __align__(16)
DEVBUF float g_wembs[NSEQ_ * 300];
DEVBUF float g_pre_s[NSEQ_ * 2048];
DEVBUF float g_sent_h0[NSEQ_ * 512];
DEVBUF float g_sent_enc[NSEQ_ * 512];
DEVBUF float g_pre_w[NR_ * 4096];
DEVBUF float g_q[NR_ * 512];
DEVBUF float g_pre_d[NR_ * 4096];
DEVBUF float g_dec_out[NR_ * 1024];
DEVBUF float g_sWh0P[2 * SH_ * SH_ * 4];
DEVBUF float g_sWh1P[2 * SH_ * SH_ * 4];
DEVBUF float g_clsWT[15 * 1024];
DEVBUF unsigned char g_stageA[64ul * 16 * PAIR_BYTES];
DEVBUF unsigned char g_stageD[64ul * 25 * PAIR_BYTES];
DEVBUF unsigned char g_stB_w0[32ul * NCH_W0 * PAIR_BYTES];
DEVBUF unsigned char g_stB_w1[32ul * NCH_W1 * PAIR_BYTES];
DEVBUF unsigned char g_stB_q[4ul * NCH_Q * PAIR_BYTES];
DEVBUF unsigned char g_stB_dec[32ul * NCH_DEC * PAIR_BYTES];
DEVBUF unsigned char g_stDWr[32ul * 16 * PAIR_BYTES];    // decoder Wh tiles
DEVBUF unsigned char g_stWw[4ul * 16 * 8 * PAIR_BYTES];  // word Wh tiles
DEVBUF unsigned char g_hstage[128ul * PAIR_BYTES];       // word-rec h staging
DEVBUF __nv_bfloat16 g_hsplitH[2][B_ * DH_];
DEVBUF __nv_bfloat16 g_hsplitL[2][B_ * DH_];
__device__ unsigned g_bar;
__device__ unsigned g_bar2;

__device__ __forceinline__ float sigm(float x) { return 1.f / (1.f + expf(-x)); }
__device__ __forceinline__ unsigned swz(unsigned o) { return o ^ ((o >> 3) & 0x70); }

__device__ __forceinline__ uint32_t smem_u32(const void* p) {
    uint32_t a;
    asm("{ .reg .u64 t; cvta.to.shared.u64 t, %1; cvt.u32.u64 %0, t; }" : "=r"(a) : "l"(p));
    return a;
}
__device__ __forceinline__ void cp_async16(uint32_t dst, const void* src) {
    asm volatile("cp.async.cg.shared.global [%0], [%1], 16;" :: "r"(dst), "l"(src) : "memory");
}
__device__ __forceinline__ void cp_commit() {
    asm volatile("cp.async.commit_group;" ::: "memory");
}
template <int N>
__device__ __forceinline__ void cp_wait() {
    asm volatile("cp.async.wait_group %0;" :: "n"(N) : "memory");
}
__device__ __forceinline__ void ldm_x4(uint32_t* r, uint32_t addr) {
    asm volatile("ldmatrix.sync.aligned.m8n8.x4.shared.b16 {%0,%1,%2,%3}, [%4];"
                 : "=r"(r[0]), "=r"(r[1]), "=r"(r[2]), "=r"(r[3]) : "r"(addr));
}
__device__ __forceinline__ void mma16816(float* d, const uint32_t* a, const uint32_t* b) {
    asm volatile(
        "mma.sync.aligned.m16n8k16.row.col.f32.bf16.bf16.f32 "
        "{%0,%1,%2,%3},{%4,%5,%6,%7},{%8,%9},{%0,%1,%2,%3};"
        : "+f"(d[0]), "+f"(d[1]), "+f"(d[2]), "+f"(d[3])
        : "r"(a[0]), "r"(a[1]), "r"(a[2]), "r"(a[3]), "r"(b[0]), "r"(b[1]));
}

// ---- bf16 split stores into swizzled staging ----
__device__ __forceinline__ void split_store_pair(unsigned char* st, int nCh, int blk,
                                                 int row, int kp, float v0, float v1) {
    int chunk = kp >> 6, kin = kp & 63;
    size_t base = ((size_t)(blk * nCh + chunk)) * PAIR_BYTES;
    unsigned so = swz((unsigned)(row * 128 + kin * 2));
    __nv_bfloat16 h0 = __float2bfloat16(v0), h1 = __float2bfloat16(v1);
    __nv_bfloat16 l0 = __float2bfloat16(v0 - __bfloat162float(h0));
    __nv_bfloat16 l1 = __float2bfloat16(v1 - __bfloat162float(h1));
    *(unsigned*)(st + base + so) =
        (unsigned)__bfloat16_as_ushort(h0) | ((unsigned)__bfloat16_as_ushort(h1) << 16);
    *(unsigned*)(st + base + TILE_BYTES + so) =
        (unsigned)__bfloat16_as_ushort(l0) | ((unsigned)__bfloat16_as_ushort(l1) << 16);
}
__device__ __forceinline__ void split_store_half(unsigned char* tileBase, int row, int kin,
                                                 float v) {
    unsigned so = swz((unsigned)(row * 128 + kin * 2));
    __nv_bfloat16 hi = __float2bfloat16(v);
    __nv_bfloat16 lo = __float2bfloat16(v - __bfloat162float(hi));
    *(unsigned short*)(tileBase + so) = __bfloat16_as_ushort(hi);
    *(unsigned short*)(tileBase + TILE_BYTES + so) = __bfloat16_as_ushort(lo);
}

// ---- prep ----
__device__ __forceinline__ void pack_region(const float* Wh, float* out, int H, long r) {
    long per = 4L * H * H;
    int dir = (int)(r / per);
    long s = r % per;
    int g = (int)(s & 3), jj = (int)((s >> 2) % H), k = (int)(s / (4 * H));
    out[dir * per + s] = Wh[dir * per + (size_t)(g * H + jj) * H + k];
}
#define R_SWH 524288L
#define R_DWS 2097152L
#define R_WB 2097152L
#define R_BW0 1179648L
#define R_BW1 2097152L
#define R_BQ 262144L
#define R_BDEC 3276800L
#define R_CEMB 131072L
#define R_PAD 131072L
#define R_EMB 153600L
#define R_DLAB 262144L
#define R_CLS 15360L
#define PREP_BLOCKS 49812

__global__ void prep_kernel(const float* __restrict__ sWh0, const float* __restrict__ sWh1,
                            const float* __restrict__ wWh0, const float* __restrict__ wWh1,
                            const float* __restrict__ dWh, const float* __restrict__ wWx0,
                            const float* __restrict__ wWx1, const float* __restrict__ Wq,
                            const float* __restrict__ dWx, const int* __restrict__ words,
                            const float* __restrict__ char_table, const int* __restrict__ sents,
                            const float* __restrict__ word_embs, const int* __restrict__ labels,
                            const float* __restrict__ clsW) {
    long idx = (long)blockIdx.x * 256 + threadIdx.x;
    if (idx < R_SWH) { pack_region(sWh0, g_sWh0P, SH_, idx); return; }
    idx -= R_SWH;
    if (idx < R_SWH) { pack_region(sWh1, g_sWh1P, SH_, idx); return; }
    idx -= R_SWH;
    if (idx < R_DWS) {
        int n = (int)(idx / 512), kp = 2 * (int)(idx % 512);
        split_store_pair(g_stDWr, 16, n >> 7, n & 127, kp,
                         dWh[(size_t)n * 1024 + kp], dWh[(size_t)n * 1024 + kp + 1]);
        return;
    }
    idx -= R_DWS;
    if (idx < R_WB) {
        int ld = (int)(idx >> 19);
        long e = idx & ((1L << 19) - 1);
        int r = (int)(e >> 8);
        int kp = 2 * (int)(e & 255);
        int g = r & 3, j = r >> 2;
        const float* Ws = (ld >> 1) ? wWh1 : wWh0;
        const float* w = Ws + (size_t)(ld & 1) * 4 * 512 * 512 + (size_t)(g * 512 + j) * 512;
        split_store_pair(g_stWw + (size_t)ld * 16 * 8 * PAIR_BYTES, 8, r >> 7, r & 127, kp,
                         w[kp], w[kp + 1]);
        return;
    }
    idx -= R_WB;
    if (idx < R_BW0) {
        int n = (int)(idx / 288), kp = 2 * (int)(idx % 288);
        float v0 = (kp < 544) ? wWx0[(size_t)n * 544 + kp] : 0.f;
        float v1 = (kp + 1 < 544) ? wWx0[(size_t)n * 544 + kp + 1] : 0.f;
        split_store_pair(g_stB_w0, NCH_W0, n >> 7, n & 127, kp, v0, v1);
        return;
    }
    idx -= R_BW0;
    if (idx < R_BW1) {
        int n = (int)(idx / 512), kp = 2 * (int)(idx % 512);
        split_store_pair(g_stB_w1, NCH_W1, n >> 7, n & 127, kp,
                         wWx1[(size_t)n * 1024 + kp], wWx1[(size_t)n * 1024 + kp + 1]);
        return;
    }
    idx -= R_BW1;
    if (idx < R_BQ) {
        int n = (int)(idx / 512), kp = 2 * (int)(idx % 512);
        split_store_pair(g_stB_q, NCH_Q, n >> 7, n & 127, kp,
                         Wq[(size_t)kp * 512 + n], Wq[(size_t)(kp + 1) * 512 + n]);
        return;
    }
    idx -= R_BQ;
    if (idx < R_BDEC) {
        int n = (int)(idx / 800), kp = 2 * (int)(idx % 800);
        float v0 = (kp < 1544) ? dWx[(size_t)n * 1544 + kp] : 0.f;
        float v1 = (kp + 1 < 1544) ? dWx[(size_t)n * 1544 + kp + 1] : 0.f;
        split_store_pair(g_stB_dec, NCH_DEC, n >> 7, n & 127, kp, v0, v1);
        return;
    }
    idx -= R_BDEC;
    if (idx < R_CEMB) {
        int r = (int)(idx / 16), kp = 2 * (int)(idx % 16);
        int w = words[r];
        split_store_pair(g_stageA, NCH_W0, r >> 7, r & 127, kp,
                         char_table[w * 32 + kp], char_table[w * 32 + kp + 1]);
        return;
    }
    idx -= R_CEMB;
    if (idx < R_PAD) {
        int r = (int)(idx / 16), kp = 544 + 2 * (int)(idx % 16);
        split_store_pair(g_stageA, NCH_W0, r >> 7, r & 127, kp, 0.f, 0.f);
        return;
    }
    idx -= R_PAD;
    if (idx < R_EMB) {
        int r = (int)(idx / 300), d = (int)(idx % 300);
        g_wembs[r * 300 + d] = word_embs[(size_t)sents[r] * 300 + d];
        return;
    }
    idx -= R_EMB;
    if (idx < R_DLAB) {
        // decoder staging: labels cols 1536..1543 + pad to 1599
        int r = (int)(idx / 32), kp = 1536 + 2 * (int)(idx % 32);
        float v0 = (kp < 1544) ? (float)labels[r * 8 + (kp - 1536)] : 0.f;
        float v1 = (kp + 1 < 1544) ? (float)labels[r * 8 + (kp + 1 - 1536)] : 0.f;
        split_store_pair(g_stageD, NCH_DEC, r >> 7, r & 127, kp, v0, v1);
        return;
    }
    idx -= R_DLAB;
    if (idx < R_CLS) {
        int n = (int)(idx / 1024), k = (int)(idx % 1024);
        g_clsWT[n * 1024 + k] = clsW[(size_t)k * 15 + n];
    }
}

__global__ void zero_dec_kernel() {
    int i = blockIdx.x * 256 + threadIdx.x;
    if (i < B_ * DH_) {
        g_hsplitH[0][i] = __float2bfloat16(0.f);
        g_hsplitL[0][i] = __float2bfloat16(0.f);
    }
    if (i == 0) g_bar = 0u;
}

__global__ void zero_hstage_kernel() {
    int i = blockIdx.x * 256 + threadIdx.x;
    if (i < 131072) {
        int dir = i >> 16, w = i & 65535;
        ((uint4*)(g_hstage + (size_t)dir * 64 * PAIR_BYTES))[w] = make_uint4(0, 0, 0, 0);
    }
    if (i == 0) g_bar2 = 0u;
}

// ---- HMMA GEMM: C = A@W^T (+bias), split-bf16 ----
__global__ void __launch_bounds__(256) tgemm_kernel(
    const unsigned char* __restrict__ stA, const unsigned char* __restrict__ stB,
    const float* __restrict__ bias, float* __restrict__ C, int N, int nCh) {
    extern __shared__ unsigned char smraw[];
    uint32_t smb = smem_u32(smraw);
    uint32_t ab = (smb + 1023) & ~1023u;
    int tid = threadIdx.x, lane = tid & 31, wid = tid >> 5;
    int wm = wid & 1, wn = wid >> 1;
    int nb = blockIdx.x, mb = blockIdx.y;

    float acc[4][4][4];
#pragma unroll
    for (int i = 0; i < 4; ++i)
#pragma unroll
        for (int j = 0; j < 4; ++j)
#pragma unroll
            for (int k = 0; k < 4; ++k) acc[i][j][k] = 0.f;

    int ar = (lane & 7) + ((lane >> 3) & 1) * 8;
    int ac = (lane >> 4) * 16;
    int br = (lane & 7) + ((lane >> 4) & 1) * 8;
    int bc = ((lane >> 3) & 1) * 16;

    auto issue = [&](int c) {
        uint32_t dst = ab + (c & 1) * 65536;
        const unsigned char* sA = stA + ((size_t)mb * nCh + c) * PAIR_BYTES;
        const unsigned char* sB = stB + ((size_t)nb * nCh + c) * PAIR_BYTES;
#pragma unroll
        for (int i = 0; i < 8; ++i)
            cp_async16(dst + (tid + i * 256) * 16, sA + (tid + i * 256) * 16);
#pragma unroll
        for (int i = 0; i < 8; ++i)
            cp_async16(dst + 32768 + (tid + i * 256) * 16, sB + (tid + i * 256) * 16);
        cp_commit();
    };

    issue(0);
    for (int c = 0; c < nCh; ++c) {
        if (c + 1 < nCh) { issue(c + 1); cp_wait<1>(); }
        else             { cp_wait<0>(); }
        __syncthreads();
        uint32_t base = ab + (c & 1) * 65536;
#pragma unroll
        for (int ks = 0; ks < 4; ++ks) {
            uint32_t ah[4][4], al[4][4], bh[2][4], bl[2][4];
#pragma unroll
            for (int mf = 0; mf < 4; ++mf) {
                uint32_t off = swz((unsigned)((wm * 64 + mf * 16 + ar) * 128 + ac + ks * 32));
                ldm_x4(ah[mf], base + off);
                ldm_x4(al[mf], base + 16384 + off);
            }
#pragma unroll
            for (int nf2 = 0; nf2 < 2; ++nf2) {
                uint32_t off = swz((unsigned)((wn * 32 + nf2 * 16 + br) * 128 + bc + ks * 32));
                ldm_x4(bh[nf2], base + 32768 + off);
                ldm_x4(bl[nf2], base + 49152 + off);
            }
#pragma unroll
            for (int mf = 0; mf < 4; ++mf)
#pragma unroll
                for (int nf = 0; nf < 4; ++nf) {
                    mma16816(acc[mf][nf], ah[mf], &bh[nf >> 1][(nf & 1) * 2]);
                    mma16816(acc[mf][nf], ah[mf], &bl[nf >> 1][(nf & 1) * 2]);
                    mma16816(acc[mf][nf], al[mf], &bh[nf >> 1][(nf & 1) * 2]);
                }
        }
        __syncthreads();
    }
#pragma unroll
    for (int mf = 0; mf < 4; ++mf) {
#pragma unroll
        for (int nf = 0; nf < 4; ++nf) {
            int row = mb * 128 + wm * 64 + mf * 16 + (lane >> 2);
            int col = nb * 128 + wn * 32 + nf * 8 + (lane & 3) * 2;
            float b0 = bias ? bias[col] : 0.f;
            float b1 = bias ? bias[col + 1] : 0.f;
            float2 v0 = make_float2(acc[mf][nf][0] + b0, acc[mf][nf][1] + b1);
            float2 v1 = make_float2(acc[mf][nf][2] + b0, acc[mf][nf][3] + b1);
            *(float2*)(C + (size_t)row * N + col) = v0;
            *(float2*)(C + (size_t)(row + 8) * N + col) = v1;
        }
    }
}

// ---- persistent HMMA word-LSTM recurrence ----
__global__ void __launch_bounds__(256) wordrec_kernel(
    const unsigned char* __restrict__ stW, const float* __restrict__ pre, int writeDec) {
    extern __shared__ unsigned char dsm[];
    uint32_t smb = smem_u32(dsm);
    int tid = threadIdx.x, lane = tid & 31, wid = tid >> 5;
    int wm = wid & 1, wn = wid >> 1;
    int bid = blockIdx.x;
    int dir = bid >> 6, r6 = bid & 63, mb = r6 >> 4, nt = r6 & 15;

    {
        const unsigned char* wb = stW + ((size_t)(dir * 16 + nt)) * 8 * PAIR_BYTES;
        uint4* dst = (uint4*)dsm;
#pragma unroll 4
        for (int i = tid; i < 8192; i += 256) {
            int c = i >> 10, w = i & 1023;
            dst[i] = *(const uint4*)(wb + (size_t)c * PAIR_BYTES + w * 16);
        }
    }
    __syncthreads();

    int ar = (lane & 7) + ((lane >> 3) & 1) * 8;
    int ac = (lane >> 4) * 16;
    int br = (lane & 7) + ((lane >> 4) & 1) * 8;
    int bc = ((lane >> 3) & 1) * 16;

    float cacc[4][4][2];
#pragma unroll
    for (int a = 0; a < 4; ++a)
#pragma unroll
        for (int b = 0; b < 4; ++b) { cacc[a][b][0] = 0.f; cacc[a][b][1] = 0.f; }

    for (int t = 0; t < 16; ++t) {
        int rb = t & 1, wbuf = rb ^ 1;
        int tdir = dir ? (15 - t) : t;

        auto issueW = [&](int c) {
            uint32_t dst = smb + 131072 + (c & 1) * 49152;
            const unsigned char* aSrc =
                g_hstage + (((size_t)((dir * 2 + rb) * 4 + mb)) * 8 + c) * PAIR_BYTES;
            const unsigned char* bSrc =
                stW + (((size_t)(dir * 16 + nt)) * 8 + c) * PAIR_BYTES + TILE_BYTES;
#pragma unroll
            for (int i = 0; i < 8; ++i)
                cp_async16(dst + (tid + i * 256) * 16, aSrc + (tid + i * 256) * 16);
#pragma unroll
            for (int i = 0; i < 4; ++i)
                cp_async16(dst + 32768 + (tid + i * 256) * 16, bSrc + (tid + i * 256) * 16);
            cp_commit();
        };

        float acc[4][4][4];
#pragma unroll
        for (int a = 0; a < 4; ++a)
#pragma unroll
            for (int b = 0; b < 4; ++b)
#pragma unroll
                for (int k = 0; k < 4; ++k) acc[a][b][k] = 0.f;

        issueW(0);
        for (int c = 0; c < 8; ++c) {
            if (c + 1 < 8) { issueW(c + 1); cp_wait<1>(); }
            else           { cp_wait<0>(); }
            __syncthreads();
            uint32_t sb = smb + 131072 + (c & 1) * 49152;
            uint32_t bhb = smb + c * 16384;
#pragma unroll
            for (int ks = 0; ks < 4; ++ks) {
                uint32_t ah[4][4], al[4][4], bh[2][4], bl[2][4];
#pragma unroll
                for (int mf = 0; mf < 4; ++mf) {
                    uint32_t off = swz((unsigned)((wm * 64 + mf * 16 + ar) * 128 + ac + ks * 32));
                    ldm_x4(ah[mf], sb + off);
                    ldm_x4(al[mf], sb + 16384 + off);
                }
#pragma unroll
                for (int nf2 = 0; nf2 < 2; ++nf2) {
                    uint32_t off = swz((unsigned)((wn * 32 + nf2 * 16 + br) * 128 + bc + ks * 32));
                    ldm_x4(bh[nf2], bhb + off);
                    ldm_x4(bl[nf2], sb + 32768 + off);
                }
#pragma unroll
                for (int mf = 0; mf < 4; ++mf)
#pragma unroll
                    for (int nf = 0; nf < 4; ++nf) {
                        mma16816(acc[mf][nf], ah[mf], &bh[nf >> 1][(nf & 1) * 2]);
                        mma16816(acc[mf][nf], ah[mf], &bl[nf >> 1][(nf & 1) * 2]);
                        mma16816(acc[mf][nf], al[mf], &bh[nf >> 1][(nf & 1) * 2]);
                    }
            }
            __syncthreads();
        }

#pragma unroll
        for (int mf = 0; mf < 4; ++mf)
#pragma unroll
            for (int nf = 0; nf < 4; ++nf) {
                float p0 = __shfl_xor_sync(0xffffffffu, acc[mf][nf][0], 1);
                float p1 = __shfl_xor_sync(0xffffffffu, acc[mf][nf][1], 1);
                float p2 = __shfl_xor_sync(0xffffffffu, acc[mf][nf][2], 1);
                float p3 = __shfl_xor_sync(0xffffffffu, acc[mf][nf][3], 1);
                if (!(lane & 1)) {
                    int j = nt * 32 + wn * 8 + nf * 2 + ((lane & 3) >> 1);
                    int r0 = wm * 64 + mf * 16 + (lane >> 2);
#pragma unroll
                    for (int rr = 0; rr < 2; ++rr) {
                        int r = r0 + rr * 8;
                        int n = mb * 128 + r;
                        size_t pb = (size_t)(n * 16 + tdir) * 4096 + dir * 2048 + j;
                        float ai = (rr ? acc[mf][nf][2] : acc[mf][nf][0]) + pre[pb];
                        float af = (rr ? acc[mf][nf][3] : acc[mf][nf][1]) + pre[pb + 512];
                        float ag = (rr ? p2 : p0) + pre[pb + 1024];
                        float ao = (rr ? p3 : p1) + pre[pb + 1536];
                        float cv = cacc[mf][nf][rr];
                        cv = sigm(af) * cv + sigm(ai) * tanhf(ag);
                        float hn = sigm(ao) * tanhf(cv);
                        cacc[mf][nf][rr] = cv;
                        split_store_half(
                            g_hstage + (((size_t)((dir * 2 + wbuf) * 4 + mb)) * 8 + (j >> 6)) * PAIR_BYTES,
                            r, j & 63, hn);
                        int rA = n * 16 + tdir, kp = dir * 512 + j;
                        split_store_half(
                            g_stageA + (((size_t)(rA >> 7) * 16 + (kp >> 6))) * PAIR_BYTES,
                            rA & 127, kp & 63, hn);
                        if (writeDec) {
                            int kp2 = 512 + kp;
                            split_store_half(
                                g_stageD + (((size_t)(rA >> 7) * 25 + (kp2 >> 6))) * PAIR_BYTES,
                                rA & 127, kp2 & 63, hn);
                        }
                    }
                }
            }
        __threadfence();
        __syncthreads();
        if (tid == 0) {
            atomicAdd(&g_bar2, 1u);
            unsigned tgt = (unsigned)(t + 1) * 128u;
            while (*(volatile unsigned*)&g_bar2 < tgt) {}
        }
        __syncthreads();
    }
}

// ---- persistent HMMA decoder ----
__global__ void __launch_bounds__(256) dec_persist_kernel(
    const float* __restrict__ pre, float* __restrict__ dout) {
    extern __shared__ unsigned char dsm[];
    uint32_t smb = smem_u32(dsm);
    int tid = threadIdx.x, lane = tid & 31, w = tid >> 5;
    int bid = blockIdx.x;
    {
        const uint4* src = (const uint4*)g_stDWr;
        uint4* dst = (uint4*)dsm;
#pragma unroll 4
        for (int it = 0; it < 32; ++it) {
            int flat = tid + it * 256;
            int q = flat & 7;
            int ru = flat >> 3;
            int i = ru & 7;
            int hl = (ru >> 3) & 1;
            int g = (ru >> 4) & 3;
            int c = ru >> 6;
            size_t sb = ((((size_t)(g * 8 + (bid >> 4)) * 16 + c) * PAIR_BYTES
                         + (size_t)hl * TILE_BYTES
                         + (size_t)((bid & 15) * 8 + i) * 128) >> 4) + q;
            int db = ((c * 8192 + hl * 4096 + (g * 8 + i) * 128) >> 4) + q;
            dst[db] = src[sb];
        }
    }
    __syncthreads();

    float* red = (float*)(dsm + 131072);
    const unsigned* hHr[2] = {(const unsigned*)&g_hsplitH[0][0], (const unsigned*)&g_hsplitH[1][0]};
    const unsigned* hLr[2] = {(const unsigned*)&g_hsplitL[0][0], (const unsigned*)&g_hsplitL[1][0]};

    int bb = tid >> 3, hh = tid & 7;
    int j = bid * 8 + hh;
    float cc = 0.f;

    int br = (lane & 7) + ((lane >> 4) & 1) * 8;
    int bc = ((lane >> 3) & 1) * 16;
    int k0base = w * 128;

    for (int t = 0; t < 256; ++t) {
        int rb = t & 1;
        float acc[2][4][4];
#pragma unroll
        for (int m = 0; m < 2; ++m)
#pragma unroll
            for (int g = 0; g < 4; ++g)
#pragma unroll
                for (int r4 = 0; r4 < 4; ++r4) acc[m][g][r4] = 0.f;

#pragma unroll 2
        for (int kf = 0; kf < 8; ++kf) {
            int k0 = k0base + kf * 16;
            uint32_t ah[2][4], al[2][4];
#pragma unroll
            for (int m = 0; m < 2; ++m) {
                int base2 = ((m * 16 + (lane >> 2)) * 1024 + k0) / 2 + (lane & 3);
                ah[m][0] = __ldcg(hHr[rb] + base2);
                ah[m][1] = __ldcg(hHr[rb] + base2 + 4096);
                ah[m][2] = __ldcg(hHr[rb] + base2 + 4);
                ah[m][3] = __ldcg(hHr[rb] + base2 + 4100);
                al[m][0] = __ldcg(hLr[rb] + base2);
                al[m][1] = __ldcg(hLr[rb] + base2 + 4096);
                al[m][2] = __ldcg(hLr[rb] + base2 + 4);
                al[m][3] = __ldcg(hLr[rb] + base2 + 4100);
            }
            int chunk = k0 >> 6, kin = k0 & 63;
            uint32_t cbs = smb + chunk * 8192;
            uint32_t bh[2][4], bl[2][4];
#pragma unroll
            for (int nt = 0; nt < 2; ++nt) {
                uint32_t off = swz((unsigned)((nt * 16 + br) * 128 + bc + kin * 2));
                ldm_x4(bh[nt], cbs + off);
                ldm_x4(bl[nt], cbs + 4096 + off);
            }
#pragma unroll
            for (int m = 0; m < 2; ++m)
#pragma unroll
                for (int g = 0; g < 4; ++g) {
                    mma16816(acc[m][g], ah[m], &bh[g >> 1][(g & 1) * 2]);
                    mma16816(acc[m][g], ah[m], &bl[g >> 1][(g & 1) * 2]);
                    mma16816(acc[m][g], al[m], &bh[g >> 1][(g & 1) * 2]);
                }
        }
#pragma unroll
        for (int m = 0; m < 2; ++m)
#pragma unroll
            for (int g = 0; g < 4; ++g)
#pragma unroll
                for (int r4 = 0; r4 < 4; ++r4)
                    red[((w * 2 + m) * 4 + g) * 128 + lane * 4 + r4] = acc[m][g][r4];
        __syncthreads();
        {
            int r = bb & 15, m = bb >> 4;
            int gl = ((r & 7) << 2) | (hh >> 1);
            int rg = (hh & 1) + 2 * ((r >> 3) & 1);
            float gv[4] = {0.f, 0.f, 0.f, 0.f};
#pragma unroll
            for (int w2 = 0; w2 < 8; ++w2)
#pragma unroll
                for (int g = 0; g < 4; ++g)
                    gv[g] += red[((w2 * 2 + m) * 4 + g) * 128 + gl * 4 + rg];
            const float* p = pre + ((size_t)bb * 256 + t) * 4096 + j;
            float ai = gv[0] + p[0];
            float af = gv[1] + p[1024];
            float agg = gv[2] + p[2048];
            float ao = gv[3] + p[3072];
            cc = sigm(af) * cc + sigm(ai) * tanhf(agg);
            float hn = sigm(ao) * tanhf(cc);
            dout[((size_t)bb * 256 + t) * 1024 + j] = hn;
            __nv_bfloat16 hi = __float2bfloat16(hn);
            __nv_bfloat16 lo = __float2bfloat16(hn - __bfloat162float(hi));
            g_hsplitH[rb ^ 1][bb * 1024 + j] = hi;
            g_hsplitL[rb ^ 1][bb * 1024 + j] = lo;
        }
        __threadfence();
        __syncthreads();
        if (tid == 0) {
            atomicAdd(&g_bar, 1u);
            unsigned tgt = (unsigned)(t + 1) * 128u;
            while (*(volatile unsigned*)&g_bar < tgt) {}
        }
        __syncthreads();
    }
}

// ---- SIMT SGEMM (sentence layers) ----
__global__ void __launch_bounds__(256) sgemm128_kernel(
    const float* __restrict__ A, const float* __restrict__ W,
    const float* __restrict__ bias, float* __restrict__ C, int M, int N, int K) {
    __shared__ __align__(16) float As[2][8][132];
    __shared__ __align__(16) float Bs[2][8][132];
    int tid = threadIdx.x;
    int m0 = blockIdx.y * 128, n0 = blockIdx.x * 128;
    int grow = tid >> 1, gk = (tid & 1) * 4;
    const float* Ap = A + (size_t)(m0 + grow) * K + gk;
    const float* Wp = W + (size_t)(n0 + grow) * K + gk;
    int tm4 = (tid >> 4) * 4, tn4 = (tid & 15) * 4;
    float acc[8][8];
#pragma unroll
    for (int i = 0; i < 8; ++i)
#pragma unroll
        for (int j = 0; j < 8; ++j) acc[i][j] = 0.f;
    int nk = (K + 7) / 8;
    float4 pa, pb;
    pa = (gk < K) ? *(const float4*)Ap : make_float4(0, 0, 0, 0);
    pb = (gk < K) ? *(const float4*)Wp : make_float4(0, 0, 0, 0);
    As[0][gk + 0][grow] = pa.x; As[0][gk + 1][grow] = pa.y;
    As[0][gk + 2][grow] = pa.z; As[0][gk + 3][grow] = pa.w;
    Bs[0][gk + 0][grow] = pb.x; Bs[0][gk + 1][grow] = pb.y;
    Bs[0][gk + 2][grow] = pb.z; Bs[0][gk + 3][grow] = pb.w;
    __syncthreads();
    for (int it = 0; it < nk; ++it) {
        int buf = it & 1;
        bool more = (it + 1) < nk;
        if (more) {
            int kt = (it + 1) * 8;
            pa = (kt + gk < K) ? *(const float4*)(Ap + kt) : make_float4(0, 0, 0, 0);
            pb = (kt + gk < K) ? *(const float4*)(Wp + kt) : make_float4(0, 0, 0, 0);
        }
#pragma unroll
        for (int kk = 0; kk < 8; ++kk) {
            float4 a0 = *(const float4*)&As[buf][kk][tm4];
            float4 a1 = *(const float4*)&As[buf][kk][tm4 + 64];
            float4 b0 = *(const float4*)&Bs[buf][kk][tn4];
            float4 b1 = *(const float4*)&Bs[buf][kk][tn4 + 64];
            float av[8] = {a0.x, a0.y, a0.z, a0.w, a1.x, a1.y, a1.z, a1.w};
            float bv[8] = {b0.x, b0.y, b0.z, b0.w, b1.x, b1.y, b1.z, b1.w};
#pragma unroll
            for (int i = 0; i < 8; ++i)
#pragma unroll
                for (int j = 0; j < 8; ++j) acc[i][j] += av[i] * bv[j];
        }
        if (more) {
            int nb2 = buf ^ 1;
            As[nb2][gk + 0][grow] = pa.x; As[nb2][gk + 1][grow] = pa.y;
            As[nb2][gk + 2][grow] = pa.z; As[nb2][gk + 3][grow] = pa.w;
            Bs[nb2][gk + 0][grow] = pb.x; Bs[nb2][gk + 1][grow] = pb.y;
            Bs[nb2][gk + 2][grow] = pb.z; Bs[nb2][gk + 3][grow] = pb.w;
        }
        __syncthreads();
    }
    float bb0[4] = {0, 0, 0, 0}, bb1[4] = {0, 0, 0, 0};
    if (bias) {
#pragma unroll
        for (int j = 0; j < 4; ++j) { bb0[j] = bias[n0 + tn4 + j]; bb1[j] = bias[n0 + tn4 + 64 + j]; }
    }
#pragma unroll
    for (int i = 0; i < 8; ++i) {
        int r = m0 + tm4 + (i & 3) + ((i >> 2) << 6);
        float4 v0 = make_float4(acc[i][0] + bb0[0], acc[i][1] + bb0[1], acc[i][2] + bb0[2], acc[i][3] + bb0[3]);
        float4 v1 = make_float4(acc[i][4] + bb1[0], acc[i][5] + bb1[1], acc[i][6] + bb1[2], acc[i][7] + bb1[3]);
        *(float4*)(C + (size_t)r * N + n0 + tn4) = v0;
        *(float4*)(C + (size_t)r * N + n0 + tn4 + 64) = v1;
    }
}

// ---- sentence BiLSTM recurrence (explicit 16-deep weight prefetch) ----
template <int H, int BSEQ, int PS, bool STAGE>
__global__ void lstm_rec_kernel(const float* __restrict__ pre,
                                const float* __restrict__ WhP, int whStride,
                                float* __restrict__ out, int T,
                                const int* __restrict__ words) {
    int dir = blockIdx.y;
    const float4* W4 = (const float4*)(WhP + (size_t)dir * whStride);
    int n0 = blockIdx.x * BSEQ;
    int j = threadIdx.x;
    __shared__ __align__(16) float sh[H * PS];
    __shared__ float wm[BSEQ * 256];
    float cc[BSEQ], ai[BSEQ], af[BSEQ], ag[BSEQ], ao[BSEQ];
#pragma unroll
    for (int s = 0; s < BSEQ; ++s) { cc[s] = 0.f; sh[j * PS + s] = 0.f; }
    if (STAGE) {
        for (int x = threadIdx.x; x < BSEQ * 256; x += H)
            wm[x] = (words[(n0 + x / 256) * 256 + (x & 255)] != 0) ? 1.f : 0.f;
    }
    __syncthreads();
    for (int tt = 0; tt < T; ++tt) {
        int t = dir ? (T - 1 - tt) : tt;
#pragma unroll
        for (int s = 0; s < BSEQ; ++s) {
            const float* p = pre + (((size_t)(n0 + s) * T + t) * 2 + dir) * (4 * H);
            ai[s] = p[j]; af[s] = p[H + j]; ag[s] = p[2 * H + j]; ao[s] = p[3 * H + j];
        }
        for (int k0 = 0; k0 < H; k0 += 16) {
            float4 w[16];
#pragma unroll
            for (int u = 0; u < 16; ++u) w[u] = W4[(k0 + u) * H + j];
#pragma unroll
            for (int u = 0; u < 16; ++u) {
#pragma unroll
                for (int s = 0; s < BSEQ; ++s) {
                    float hk = sh[(k0 + u) * PS + s];
                    ai[s] += hk * w[u].x; af[s] += hk * w[u].y;
                    ag[s] += hk * w[u].z; ao[s] += hk * w[u].w;
                }
            }
        }
        __syncthreads();
#pragma unroll
        for (int s = 0; s < BSEQ; ++s) {
            float c = sigm(af[s]) * cc[s] + sigm(ai[s]) * tanhf(ag[s]);
            float hn = sigm(ao[s]) * tanhf(c);
            cc[s] = c;
            sh[j * PS + s] = hn;
            out[(((size_t)(n0 + s) * T + t)) * (2 * H) + dir * H + j] = hn;
            if constexpr (STAGE) {
                float v1 = __shfl_down_sync(0xffffffffu, hn, 1);
                if (!(j & 1)) {
                    int kp = 32 + dir * H + j;
                    int rb = ((n0 + s) * 16 + t) * 16;
                    int blk = rb >> 7;
#pragma unroll
                    for (int tw = 0; tw < 16; ++tw) {
                        float m = wm[s * 256 + t * 16 + tw];
                        split_store_pair(g_stageA, NCH_W0, blk, (rb & 127) + tw, kp, hn * m, v1 * m);
                    }
                }
            }
        }
        __syncthreads();
    }
}

// ---- attention (writes attn split directly into decoder staging) ----
__global__ void attention_kernel(const float* __restrict__ q, const float* __restrict__ sent_enc,
                                 const int* __restrict__ words, float* __restrict__ map_out) {
    int bi = blockIdx.x, b = bi >> 4, i = bi & 15;
    __shared__ float se[16 * 513];
    __shared__ float sc[16][16];
    __shared__ float mp[16][16];
    __shared__ int kv[16];
    for (int x = threadIdx.x; x < 16 * 512; x += 256) {
        int jj = x >> 9, d = x & 511;
        se[jj * 513 + d] = sent_enc[((size_t)b * 16 + jj) * 512 + d];
    }
    if (threadIdx.x < 16) {
        int jj = threadIdx.x, any = 0;
        for (int tw = 0; tw < 16; ++tw) any |= (words[(b * 16 + jj) * 16 + tw] != 0);
        kv[jj] = any;
    }
    __syncthreads();
    {
        int cdx = threadIdx.x >> 4, jj = threadIdx.x & 15;
        const float* qr = q + ((size_t)bi * 16 + cdx) * 512;
        const float* ser = se + jj * 513;
        float s = 0.f;
#pragma unroll 4
        for (int d = 0; d < 512; ++d) s += qr[d] * ser[d];
        sc[cdx][jj] = s;
    }
    __syncthreads();
    if (threadIdx.x < 16) {
        int cdx = threadIdx.x;
        float v[16], m = -1e30f;
#pragma unroll
        for (int jj = 0; jj < 16; ++jj) {
            bool valid = (kv[jj] != 0) && (jj != i);
            v[jj] = valid ? sc[cdx][jj] : -1e9f;
            m = fmaxf(m, v[jj]);
        }
        float sum = 0.f;
#pragma unroll
        for (int jj = 0; jj < 16; ++jj) { v[jj] = expf(v[jj] - m); sum += v[jj]; }
        float inv = 1.f / sum;
#pragma unroll
        for (int jj = 0; jj < 16; ++jj) mp[cdx][jj] = v[jj] * inv;
    }
    __syncthreads();
    if (map_out != nullptr && threadIdx.x < 256) {
        int x = threadIdx.x;
        map_out[(size_t)bi * 256 + x] = mp[x >> 4][x & 15];
    }
    for (int x = threadIdx.x; x < 16 * 512; x += 256) {
        int cdx = x >> 9, d = x & 511;
        float s = 0.f;
#pragma unroll
        for (int jj = 0; jj < 16; ++jj) s += mp[cdx][jj] * se[jj * 513 + d];
        int r = bi * 16 + cdx;
        split_store_half(g_stageD + ((size_t)(r >> 7) * 25 + (d >> 6)) * PAIR_BYTES,
                         r & 127, d & 63, s);
    }
}

__global__ void classifier_kernel(const float* __restrict__ dec_out,
                                  const float* __restrict__ Wt,
                                  const float* __restrict__ bias, float* __restrict__ out) {
    int m = blockIdx.x * 16 + (threadIdx.x >> 4);
    int n = threadIdx.x & 15;
    if (n >= 15) return;
    const float4* x = (const float4*)(dec_out + (size_t)m * 1024);
    const float4* w = (const float4*)(Wt + n * 1024);
    float s = bias[n];
#pragma unroll 8
    for (int k = 0; k < 256; ++k) {
        float4 a = x[k], b = w[k];
        s += a.x * b.x + a.y * b.y + a.z * b.z + a.w * b.w;
    }
    out[(size_t)m * 15 + n] = s;
}

// ---- host ----
static void* symp(const void* s) { void* p = nullptr; cudaGetSymbolAddress(&p, s); return p; }

extern "C" void kernel_launch(void* const* d_in, const int* in_sizes, int n_in,
                              void* d_out, int out_size) {
    (void)in_sizes; (void)n_in;
    const int* sents = (const int*)d_in[0];
    const int* words = (const int*)d_in[1];
    const int* labels = (const int*)d_in[2];
    const float* word_embs = (const float*)d_in[3];
    const float* char_table = (const float*)d_in[4];
    const float* sWx0 = (const float*)d_in[5];
    const float* sWh0 = (const float*)d_in[6];
    const float* sb0 = (const float*)d_in[7];
    const float* sWx1 = (const float*)d_in[8];
    const float* sWh1 = (const float*)d_in[9];
    const float* sb1 = (const float*)d_in[10];
    const float* wWx0 = (const float*)d_in[11];
    const float* wWh0 = (const float*)d_in[12];
    const float* wb0 = (const float*)d_in[13];
    const float* wWx1 = (const float*)d_in[14];
    const float* wWh1 = (const float*)d_in[15];
    const float* wb1 = (const float*)d_in[16];
    const float* Wq = (const float*)d_in[17];
    const float* dWx = (const float*)d_in[18];
    const float* dWh = (const float*)d_in[19];
    const float* db = (const float*)d_in[20];
    const float* clsW = (const float*)d_in[21];
    const float* clsb = (const float*)d_in[22];
    float* out = (float*)d_out;

    float* wembs = (float*)symp(g_wembs);
    float* pre_s = (float*)symp(g_pre_s);
    float* sent_h0 = (float*)symp(g_sent_h0);
    float* sent_enc = (float*)symp(g_sent_enc);
    float* pre_w = (float*)symp(g_pre_w);
    float* qbuf = (float*)symp(g_q);
    float* pre_d = (float*)symp(g_pre_d);
    float* dec_out = (float*)symp(g_dec_out);
    float* sWh0P = (float*)symp(g_sWh0P);
    float* sWh1P = (float*)symp(g_sWh1P);
    float* clsWT = (float*)symp(g_clsWT);
    const unsigned char* stA = (const unsigned char*)symp(g_stageA);
    const unsigned char* stD = (const unsigned char*)symp(g_stageD);
    const unsigned char* stBw0 = (const unsigned char*)symp(g_stB_w0);
    const unsigned char* stBw1 = (const unsigned char*)symp(g_stB_w1);
    const unsigned char* stBq = (const unsigned char*)symp(g_stB_q);
    const unsigned char* stBdec = (const unsigned char*)symp(g_stB_dec);
    const unsigned char* stWw = (const unsigned char*)symp(g_stWw);

    cudaFuncSetAttribute(tgemm_kernel, cudaFuncAttributeMaxDynamicSharedMemorySize, TG_SMEM);
    cudaFuncSetAttribute(dec_persist_kernel, cudaFuncAttributeMaxDynamicSharedMemorySize, DEC_SMEM);
    cudaFuncSetAttribute(wordrec_kernel, cudaFuncAttributeMaxDynamicSharedMemorySize, WR_SMEM);

    const int sStride = SH_ * SH_ * 4;
    const size_t wwLayer = 2ul * 16 * 8 * PAIR_BYTES;

    prep_kernel<<<PREP_BLOCKS, 256>>>(sWh0, sWh1, wWh0, wWh1, dWh, wWx0, wWx1, Wq, dWx,
                                      words, char_table, sents, word_embs, labels, clsW);
    zero_dec_kernel<<<128, 256>>>();
    sgemm128_kernel<<<dim3(16, 4), 256>>>(wembs, sWx0, sb0, pre_s, 512, 2048, 300);
    lstm_rec_kernel<SH_, 2, 2, false><<<dim3(16, 2), SH_>>>(pre_s, sWh0P, sStride, sent_h0, 16, nullptr);
    sgemm128_kernel<<<dim3(16, 4), 256>>>(sent_h0, sWx1, sb1, pre_s, 512, 2048, 512);
    lstm_rec_kernel<SH_, 2, 2, true><<<dim3(16, 2), SH_>>>(pre_s, sWh1P, sStride, sent_enc, 16, words);
    // word layer 0
    tgemm_kernel<<<dim3(32, 64), 256, TG_SMEM>>>(stA, stBw0, wb0, pre_w, 4096, NCH_W0);
    zero_hstage_kernel<<<512, 256>>>();
    wordrec_kernel<<<128, 256, WR_SMEM>>>(stWw, pre_w, 0);
    // word layer 1
    tgemm_kernel<<<dim3(32, 64), 256, TG_SMEM>>>(stA, stBw1, wb1, pre_w, 4096, NCH_W1);
    zero_hstage_kernel<<<512, 256>>>();
    wordrec_kernel<<<128, 256, WR_SMEM>>>(stWw + wwLayer, pre_w, 1);
    // attention
    tgemm_kernel<<<dim3(4, 64), 256, TG_SMEM>>>(stA, stBq, nullptr, qbuf, 512, NCH_Q);
    float* map_out = (out_size >= (NR_ * 15 + 131072)) ? (out + NR_ * 15) : nullptr;
    attention_kernel<<<NSEQ_, 256>>>(qbuf, sent_enc, words, map_out);
    // decoder
    tgemm_kernel<<<dim3(32, 64), 256, TG_SMEM>>>(stD, stBdec, db, pre_d, 4096, NCH_DEC);
    dec_persist_kernel<<<128, 256, DEC_SMEM>>>(pre_d, dec_out);
    classifier_kernel<<<NR_ / 16, 256>>>(dec_out, clsWT, clsb, out);
}

// round 9
// speedup vs baseline: 6.1489x; 1.0592x over previous
#include <cuda_runtime.h>
#include <cuda_bf16.h>
#include <math.h>
#include <stdint.h>

#define B_ 32
#define SH_ 256
#define WH_ 512
#define DH_ 1024
#define NSEQ_ 512
#define NR_ 8192
#define NCH_W0 9
#define NCH_W1 16
#define NCH_Q 16
#define NCH_DEC 25
#define TILE_BYTES 16384
#define PAIR_BYTES 32768
#define TG_SMEM 131072
#define DEC_SMEM (131072 + 32768)
#define WR_SMEM (131072 + 2 * 49152)
#define SR_SMEM (65536 + 16384 + 16384)

#define DEVBUF __device__ __align__(16)
DEVBUF float g_wembs[NSEQ_ * 300];
DEVBUF float g_pre_s[NSEQ_ * 2048];
DEVBUF float g_sent_h0[NSEQ_ * 512];
DEVBUF float g_sent_enc[NSEQ_ * 512];
DEVBUF float g_pre_w[NR_ * 4096];
DEVBUF float g_q[NR_ * 512];
DEVBUF float g_pre_d[NR_ * 4096];
DEVBUF float g_dec_out[NR_ * 1024];
DEVBUF float g_sWh0P[2 * SH_ * SH_ * 4];
DEVBUF float g_sWh1P[2 * SH_ * SH_ * 4];
DEVBUF float g_clsWT[15 * 1024];
DEVBUF float g_shs[2 * 2 * 32 * 256];   // sentence h exchange [buf][dir][s][j]
DEVBUF unsigned char g_stageA[64ul * 16 * PAIR_BYTES];
DEVBUF unsigned char g_stageD[64ul * 25 * PAIR_BYTES];
DEVBUF unsigned char g_stB_w0[32ul * NCH_W0 * PAIR_BYTES];
DEVBUF unsigned char g_stB_w1[32ul * NCH_W1 * PAIR_BYTES];
DEVBUF unsigned char g_stB_q[4ul * NCH_Q * PAIR_BYTES];
DEVBUF unsigned char g_stB_dec[32ul * NCH_DEC * PAIR_BYTES];
DEVBUF unsigned char g_stDWr[32ul * 16 * PAIR_BYTES];
DEVBUF unsigned char g_stWw[4ul * 16 * 8 * PAIR_BYTES];
DEVBUF unsigned char g_hstage[128ul * PAIR_BYTES];
DEVBUF __nv_bfloat16 g_hsplitH[2][B_ * DH_];
DEVBUF __nv_bfloat16 g_hsplitL[2][B_ * DH_];
__device__ unsigned g_bar;
__device__ unsigned g_bar2;
__device__ unsigned g_bar3;

__device__ __forceinline__ float sigm(float x) { return 1.f / (1.f + expf(-x)); }
__device__ __forceinline__ unsigned swz(unsigned o) { return o ^ ((o >> 3) & 0x70); }

__device__ __forceinline__ uint32_t smem_u32(const void* p) {
    uint32_t a;
    asm("{ .reg .u64 t; cvta.to.shared.u64 t, %1; cvt.u32.u64 %0, t; }" : "=r"(a) : "l"(p));
    return a;
}
__device__ __forceinline__ void cp_async16(uint32_t dst, const void* src) {
    asm volatile("cp.async.cg.shared.global [%0], [%1], 16;" :: "r"(dst), "l"(src) : "memory");
}
__device__ __forceinline__ void cp_commit() {
    asm volatile("cp.async.commit_group;" ::: "memory");
}
template <int N>
__device__ __forceinline__ void cp_wait() {
    asm volatile("cp.async.wait_group %0;" :: "n"(N) : "memory");
}
__device__ __forceinline__ void ldm_x4(uint32_t* r, uint32_t addr) {
    asm volatile("ldmatrix.sync.aligned.m8n8.x4.shared.b16 {%0,%1,%2,%3}, [%4];"
                 : "=r"(r[0]), "=r"(r[1]), "=r"(r[2]), "=r"(r[3]) : "r"(addr));
}
__device__ __forceinline__ void mma16816(float* d, const uint32_t* a, const uint32_t* b) {
    asm volatile(
        "mma.sync.aligned.m16n8k16.row.col.f32.bf16.bf16.f32 "
        "{%0,%1,%2,%3},{%4,%5,%6,%7},{%8,%9},{%0,%1,%2,%3};"
        : "+f"(d[0]), "+f"(d[1]), "+f"(d[2]), "+f"(d[3])
        : "r"(a[0]), "r"(a[1]), "r"(a[2]), "r"(a[3]), "r"(b[0]), "r"(b[1]));
}

// ---- bf16 split stores ----
__device__ __forceinline__ void split_store_pair(unsigned char* st, int nCh, int blk,
                                                 int row, int kp, float v0, float v1) {
    int chunk = kp >> 6, kin = kp & 63;
    size_t base = ((size_t)(blk * nCh + chunk)) * PAIR_BYTES;
    unsigned so = swz((unsigned)(row * 128 + kin * 2));
    __nv_bfloat16 h0 = __float2bfloat16(v0), h1 = __float2bfloat16(v1);
    __nv_bfloat16 l0 = __float2bfloat16(v0 - __bfloat162float(h0));
    __nv_bfloat16 l1 = __float2bfloat16(v1 - __bfloat162float(h1));
    *(unsigned*)(st + base + so) =
        (unsigned)__bfloat16_as_ushort(h0) | ((unsigned)__bfloat16_as_ushort(h1) << 16);
    *(unsigned*)(st + base + TILE_BYTES + so) =
        (unsigned)__bfloat16_as_ushort(l0) | ((unsigned)__bfloat16_as_ushort(l1) << 16);
}
__device__ __forceinline__ void split_store_half(unsigned char* tileBase, int row, int kin,
                                                 float v) {
    unsigned so = swz((unsigned)(row * 128 + kin * 2));
    __nv_bfloat16 hi = __float2bfloat16(v);
    __nv_bfloat16 lo = __float2bfloat16(v - __bfloat162float(hi));
    *(unsigned short*)(tileBase + so) = __bfloat16_as_ushort(hi);
    *(unsigned short*)(tileBase + TILE_BYTES + so) = __bfloat16_as_ushort(lo);
}

// ---- prep ----
__device__ __forceinline__ void pack_region(const float* Wh, float* out, int H, long r) {
    long per = 4L * H * H;
    int dir = (int)(r / per);
    long s = r % per;
    int g = (int)(s & 3), jj = (int)((s >> 2) % H), k = (int)(s / (4 * H));
    out[dir * per + s] = Wh[dir * per + (size_t)(g * H + jj) * H + k];
}
#define R_SWH 524288L
#define R_DWS 2097152L
#define R_WB 2097152L
#define R_BW0 1179648L
#define R_BW1 2097152L
#define R_BQ 262144L
#define R_BDEC 3276800L
#define R_CEMB 131072L
#define R_PAD 131072L
#define R_EMB 153600L
#define R_DLAB 262144L
#define R_CLS 15360L
#define PREP_BLOCKS 49812

__global__ void prep_kernel(const float* __restrict__ sWh0, const float* __restrict__ sWh1,
                            const float* __restrict__ wWh0, const float* __restrict__ wWh1,
                            const float* __restrict__ dWh, const float* __restrict__ wWx0,
                            const float* __restrict__ wWx1, const float* __restrict__ Wq,
                            const float* __restrict__ dWx, const int* __restrict__ words,
                            const float* __restrict__ char_table, const int* __restrict__ sents,
                            const float* __restrict__ word_embs, const int* __restrict__ labels,
                            const float* __restrict__ clsW) {
    if (blockIdx.x == 0 && threadIdx.x == 0) { g_bar = 0u; g_bar2 = 0u; g_bar3 = 0u; }
    long idx = (long)blockIdx.x * 256 + threadIdx.x;
    if (idx < R_SWH) { pack_region(sWh0, g_sWh0P, SH_, idx); return; }
    idx -= R_SWH;
    if (idx < R_SWH) { pack_region(sWh1, g_sWh1P, SH_, idx); return; }
    idx -= R_SWH;
    if (idx < R_DWS) {
        int n = (int)(idx / 512), kp = 2 * (int)(idx % 512);
        split_store_pair(g_stDWr, 16, n >> 7, n & 127, kp,
                         dWh[(size_t)n * 1024 + kp], dWh[(size_t)n * 1024 + kp + 1]);
        return;
    }
    idx -= R_DWS;
    if (idx < R_WB) {
        int ld = (int)(idx >> 19);
        long e = idx & ((1L << 19) - 1);
        int r = (int)(e >> 8);
        int kp = 2 * (int)(e & 255);
        int g = r & 3, j = r >> 2;
        const float* Ws = (ld >> 1) ? wWh1 : wWh0;
        const float* w = Ws + (size_t)(ld & 1) * 4 * 512 * 512 + (size_t)(g * 512 + j) * 512;
        split_store_pair(g_stWw + (size_t)ld * 16 * 8 * PAIR_BYTES, 8, r >> 7, r & 127, kp,
                         w[kp], w[kp + 1]);
        return;
    }
    idx -= R_WB;
    if (idx < R_BW0) {
        int n = (int)(idx / 288), kp = 2 * (int)(idx % 288);
        float v0 = (kp < 544) ? wWx0[(size_t)n * 544 + kp] : 0.f;
        float v1 = (kp + 1 < 544) ? wWx0[(size_t)n * 544 + kp + 1] : 0.f;
        split_store_pair(g_stB_w0, NCH_W0, n >> 7, n & 127, kp, v0, v1);
        return;
    }
    idx -= R_BW0;
    if (idx < R_BW1) {
        int n = (int)(idx / 512), kp = 2 * (int)(idx % 512);
        split_store_pair(g_stB_w1, NCH_W1, n >> 7, n & 127, kp,
                         wWx1[(size_t)n * 1024 + kp], wWx1[(size_t)n * 1024 + kp + 1]);
        return;
    }
    idx -= R_BW1;
    if (idx < R_BQ) {
        int n = (int)(idx / 512), kp = 2 * (int)(idx % 512);
        split_store_pair(g_stB_q, NCH_Q, n >> 7, n & 127, kp,
                         Wq[(size_t)kp * 512 + n], Wq[(size_t)(kp + 1) * 512 + n]);
        return;
    }
    idx -= R_BQ;
    if (idx < R_BDEC) {
        int n = (int)(idx / 800), kp = 2 * (int)(idx % 800);
        float v0 = (kp < 1544) ? dWx[(size_t)n * 1544 + kp] : 0.f;
        float v1 = (kp + 1 < 1544) ? dWx[(size_t)n * 1544 + kp + 1] : 0.f;
        split_store_pair(g_stB_dec, NCH_DEC, n >> 7, n & 127, kp, v0, v1);
        return;
    }
    idx -= R_BDEC;
    if (idx < R_CEMB) {
        int r = (int)(idx / 16), kp = 2 * (int)(idx % 16);
        int w = words[r];
        split_store_pair(g_stageA, NCH_W0, r >> 7, r & 127, kp,
                         char_table[w * 32 + kp], char_table[w * 32 + kp + 1]);
        return;
    }
    idx -= R_CEMB;
    if (idx < R_PAD) {
        int r = (int)(idx / 16), kp = 544 + 2 * (int)(idx % 16);
        split_store_pair(g_stageA, NCH_W0, r >> 7, r & 127, kp, 0.f, 0.f);
        return;
    }
    idx -= R_PAD;
    if (idx < R_EMB) {
        int r = (int)(idx / 300), d = (int)(idx % 300);
        g_wembs[r * 300 + d] = word_embs[(size_t)sents[r] * 300 + d];
        return;
    }
    idx -= R_EMB;
    if (idx < R_DLAB) {
        int r = (int)(idx / 32), kp = 1536 + 2 * (int)(idx % 32);
        float v0 = (kp < 1544) ? (float)labels[r * 8 + (kp - 1536)] : 0.f;
        float v1 = (kp + 1 < 1544) ? (float)labels[r * 8 + (kp + 1 - 1536)] : 0.f;
        split_store_pair(g_stageD, NCH_DEC, r >> 7, r & 127, kp, v0, v1);
        return;
    }
    idx -= R_DLAB;
    if (idx < R_CLS) {
        int n = (int)(idx / 1024), k = (int)(idx % 1024);
        g_clsWT[n * 1024 + k] = clsW[(size_t)k * 15 + n];
    }
}

// ---- HMMA GEMM ----
__global__ void __launch_bounds__(256) tgemm_kernel(
    const unsigned char* __restrict__ stA, const unsigned char* __restrict__ stB,
    const float* __restrict__ bias, float* __restrict__ C, int N, int nCh) {
    extern __shared__ unsigned char smraw[];
    uint32_t smb = smem_u32(smraw);
    uint32_t ab = (smb + 1023) & ~1023u;
    int tid = threadIdx.x, lane = tid & 31, wid = tid >> 5;
    int wm = wid & 1, wn = wid >> 1;
    int nb = blockIdx.x, mb = blockIdx.y;

    float acc[4][4][4];
#pragma unroll
    for (int i = 0; i < 4; ++i)
#pragma unroll
        for (int j = 0; j < 4; ++j)
#pragma unroll
            for (int k = 0; k < 4; ++k) acc[i][j][k] = 0.f;

    int ar = (lane & 7) + ((lane >> 3) & 1) * 8;
    int ac = (lane >> 4) * 16;
    int br = (lane & 7) + ((lane >> 4) & 1) * 8;
    int bc = ((lane >> 3) & 1) * 16;

    auto issue = [&](int c) {
        uint32_t dst = ab + (c & 1) * 65536;
        const unsigned char* sA = stA + ((size_t)mb * nCh + c) * PAIR_BYTES;
        const unsigned char* sB = stB + ((size_t)nb * nCh + c) * PAIR_BYTES;
#pragma unroll
        for (int i = 0; i < 8; ++i)
            cp_async16(dst + (tid + i * 256) * 16, sA + (tid + i * 256) * 16);
#pragma unroll
        for (int i = 0; i < 8; ++i)
            cp_async16(dst + 32768 + (tid + i * 256) * 16, sB + (tid + i * 256) * 16);
        cp_commit();
    };

    issue(0);
    for (int c = 0; c < nCh; ++c) {
        if (c + 1 < nCh) { issue(c + 1); cp_wait<1>(); }
        else             { cp_wait<0>(); }
        __syncthreads();
        uint32_t base = ab + (c & 1) * 65536;
#pragma unroll
        for (int ks = 0; ks < 4; ++ks) {
            uint32_t ah[4][4], al[4][4], bh[2][4], bl[2][4];
#pragma unroll
            for (int mf = 0; mf < 4; ++mf) {
                uint32_t off = swz((unsigned)((wm * 64 + mf * 16 + ar) * 128 + ac + ks * 32));
                ldm_x4(ah[mf], base + off);
                ldm_x4(al[mf], base + 16384 + off);
            }
#pragma unroll
            for (int nf2 = 0; nf2 < 2; ++nf2) {
                uint32_t off = swz((unsigned)((wn * 32 + nf2 * 16 + br) * 128 + bc + ks * 32));
                ldm_x4(bh[nf2], base + 32768 + off);
                ldm_x4(bl[nf2], base + 49152 + off);
            }
#pragma unroll
            for (int mf = 0; mf < 4; ++mf)
#pragma unroll
                for (int nf = 0; nf < 4; ++nf) {
                    mma16816(acc[mf][nf], ah[mf], &bh[nf >> 1][(nf & 1) * 2]);
                    mma16816(acc[mf][nf], ah[mf], &bl[nf >> 1][(nf & 1) * 2]);
                    mma16816(acc[mf][nf], al[mf], &bh[nf >> 1][(nf & 1) * 2]);
                }
        }
        __syncthreads();
    }
#pragma unroll
    for (int mf = 0; mf < 4; ++mf) {
#pragma unroll
        for (int nf = 0; nf < 4; ++nf) {
            int row = mb * 128 + wm * 64 + mf * 16 + (lane >> 2);
            int col = nb * 128 + wn * 32 + nf * 8 + (lane & 3) * 2;
            float b0 = bias ? bias[col] : 0.f;
            float b1 = bias ? bias[col + 1] : 0.f;
            float2 v0 = make_float2(acc[mf][nf][0] + b0, acc[mf][nf][1] + b1);
            float2 v1 = make_float2(acc[mf][nf][2] + b0, acc[mf][nf][3] + b1);
            *(float2*)(C + (size_t)row * N + col) = v0;
            *(float2*)(C + (size_t)(row + 8) * N + col) = v1;
        }
    }
}

// ---- persistent HMMA word-LSTM recurrence ----
__global__ void __launch_bounds__(256) wordrec_kernel(
    const unsigned char* __restrict__ stW, const float* __restrict__ pre,
    int writeDec, int base) {
    extern __shared__ unsigned char dsm[];
    uint32_t smb = smem_u32(dsm);
    int tid = threadIdx.x, lane = tid & 31, wid = tid >> 5;
    int wm = wid & 1, wn = wid >> 1;
    int bid = blockIdx.x;
    int dir = bid >> 6, r6 = bid & 63, mb = r6 >> 4, nt = r6 & 15;

    {
        const unsigned char* wb = stW + ((size_t)(dir * 16 + nt)) * 8 * PAIR_BYTES;
        uint4* dst = (uint4*)dsm;
#pragma unroll 4
        for (int i = tid; i < 8192; i += 256) {
            int c = i >> 10, w = i & 1023;
            dst[i] = *(const uint4*)(wb + (size_t)c * PAIR_BYTES + w * 16);
        }
    }
    __syncthreads();

    int ar = (lane & 7) + ((lane >> 3) & 1) * 8;
    int ac = (lane >> 4) * 16;
    int br = (lane & 7) + ((lane >> 4) & 1) * 8;
    int bc = ((lane >> 3) & 1) * 16;

    float cacc[4][4][2];
#pragma unroll
    for (int a = 0; a < 4; ++a)
#pragma unroll
        for (int b = 0; b < 4; ++b) { cacc[a][b][0] = 0.f; cacc[a][b][1] = 0.f; }

    for (int t = 0; t < 16; ++t) {
        int rb = t & 1, wbuf = rb ^ 1;
        int tdir = dir ? (15 - t) : t;

        auto issueW = [&](int c) {
            uint32_t dst = smb + 131072 + (c & 1) * 49152;
            const unsigned char* aSrc =
                g_hstage + (((size_t)((dir * 2 + rb) * 4 + mb)) * 8 + c) * PAIR_BYTES;
            const unsigned char* bSrc =
                stW + (((size_t)(dir * 16 + nt)) * 8 + c) * PAIR_BYTES + TILE_BYTES;
#pragma unroll
            for (int i = 0; i < 8; ++i)
                cp_async16(dst + (tid + i * 256) * 16, aSrc + (tid + i * 256) * 16);
#pragma unroll
            for (int i = 0; i < 4; ++i)
                cp_async16(dst + 32768 + (tid + i * 256) * 16, bSrc + (tid + i * 256) * 16);
            cp_commit();
        };

        float acc[4][4][4];
#pragma unroll
        for (int a = 0; a < 4; ++a)
#pragma unroll
            for (int b = 0; b < 4; ++b)
#pragma unroll
                for (int k = 0; k < 4; ++k) acc[a][b][k] = 0.f;

        if (t > 0) {
            issueW(0);
            for (int c = 0; c < 8; ++c) {
                if (c + 1 < 8) { issueW(c + 1); cp_wait<1>(); }
                else           { cp_wait<0>(); }
                __syncthreads();
                uint32_t sb = smb + 131072 + (c & 1) * 49152;
                uint32_t bhb = smb + c * 16384;
#pragma unroll
                for (int ks = 0; ks < 4; ++ks) {
                    uint32_t ah[4][4], al[4][4], bh[2][4], bl[2][4];
#pragma unroll
                    for (int mf = 0; mf < 4; ++mf) {
                        uint32_t off = swz((unsigned)((wm * 64 + mf * 16 + ar) * 128 + ac + ks * 32));
                        ldm_x4(ah[mf], sb + off);
                        ldm_x4(al[mf], sb + 16384 + off);
                    }
#pragma unroll
                    for (int nf2 = 0; nf2 < 2; ++nf2) {
                        uint32_t off = swz((unsigned)((wn * 32 + nf2 * 16 + br) * 128 + bc + ks * 32));
                        ldm_x4(bh[nf2], bhb + off);
                        ldm_x4(bl[nf2], sb + 32768 + off);
                    }
#pragma unroll
                    for (int mf = 0; mf < 4; ++mf)
#pragma unroll
                        for (int nf = 0; nf < 4; ++nf) {
                            mma16816(acc[mf][nf], ah[mf], &bh[nf >> 1][(nf & 1) * 2]);
                            mma16816(acc[mf][nf], ah[mf], &bl[nf >> 1][(nf & 1) * 2]);
                            mma16816(acc[mf][nf], al[mf], &bh[nf >> 1][(nf & 1) * 2]);
                        }
                }
                __syncthreads();
            }
        }

#pragma unroll
        for (int mf = 0; mf < 4; ++mf)
#pragma unroll
            for (int nf = 0; nf < 4; ++nf) {
                float p0 = __shfl_xor_sync(0xffffffffu, acc[mf][nf][0], 1);
                float p1 = __shfl_xor_sync(0xffffffffu, acc[mf][nf][1], 1);
                float p2 = __shfl_xor_sync(0xffffffffu, acc[mf][nf][2], 1);
                float p3 = __shfl_xor_sync(0xffffffffu, acc[mf][nf][3], 1);
                if (!(lane & 1)) {
                    int j = nt * 32 + wn * 8 + nf * 2 + ((lane & 3) >> 1);
                    int r0 = wm * 64 + mf * 16 + (lane >> 2);
#pragma unroll
                    for (int rr = 0; rr < 2; ++rr) {
                        int r = r0 + rr * 8;
                        int n = mb * 128 + r;
                        size_t pb = (size_t)(n * 16 + tdir) * 4096 + dir * 2048 + j;
                        float ai = (rr ? acc[mf][nf][2] : acc[mf][nf][0]) + pre[pb];
                        float af = (rr ? acc[mf][nf][3] : acc[mf][nf][1]) + pre[pb + 512];
                        float ag = (rr ? p2 : p0) + pre[pb + 1024];
                        float ao = (rr ? p3 : p1) + pre[pb + 1536];
                        float cv = cacc[mf][nf][rr];
                        cv = sigm(af) * cv + sigm(ai) * tanhf(ag);
                        float hn = sigm(ao) * tanhf(cv);
                        cacc[mf][nf][rr] = cv;
                        split_store_half(
                            g_hstage + (((size_t)((dir * 2 + wbuf) * 4 + mb)) * 8 + (j >> 6)) * PAIR_BYTES,
                            r, j & 63, hn);
                        int rA = n * 16 + tdir, kp = dir * 512 + j;
                        split_store_half(
                            g_stageA + (((size_t)(rA >> 7) * 16 + (kp >> 6))) * PAIR_BYTES,
                            rA & 127, kp & 63, hn);
                        if (writeDec) {
                            int kp2 = 512 + kp;
                            split_store_half(
                                g_stageD + (((size_t)(rA >> 7) * 25 + (kp2 >> 6))) * PAIR_BYTES,
                                rA & 127, kp2 & 63, hn);
                        }
                    }
                }
            }
        __threadfence();
        __syncthreads();
        if (tid == 0) {
            atomicAdd(&g_bar2, 1u);
            unsigned tgt = (unsigned)(base + t + 1) * 128u;
            while (*(volatile unsigned*)&g_bar2 < tgt) {}
        }
        __syncthreads();
    }
}

// ---- persistent HMMA decoder ----
__global__ void __launch_bounds__(256) dec_persist_kernel(
    const float* __restrict__ pre, float* __restrict__ dout) {
    extern __shared__ unsigned char dsm[];
    uint32_t smb = smem_u32(dsm);
    int tid = threadIdx.x, lane = tid & 31, w = tid >> 5;
    int bid = blockIdx.x;
    {
        const uint4* src = (const uint4*)g_stDWr;
        uint4* dst = (uint4*)dsm;
#pragma unroll 4
        for (int it = 0; it < 32; ++it) {
            int flat = tid + it * 256;
            int q = flat & 7;
            int ru = flat >> 3;
            int i = ru & 7;
            int hl = (ru >> 3) & 1;
            int g = (ru >> 4) & 3;
            int c = ru >> 6;
            size_t sb = ((((size_t)(g * 8 + (bid >> 4)) * 16 + c) * PAIR_BYTES
                         + (size_t)hl * TILE_BYTES
                         + (size_t)((bid & 15) * 8 + i) * 128) >> 4) + q;
            int db = ((c * 8192 + hl * 4096 + (g * 8 + i) * 128) >> 4) + q;
            dst[db] = src[sb];
        }
    }
    __syncthreads();

    float* red = (float*)(dsm + 131072);
    const unsigned* hHr[2] = {(const unsigned*)&g_hsplitH[0][0], (const unsigned*)&g_hsplitH[1][0]};
    const unsigned* hLr[2] = {(const unsigned*)&g_hsplitL[0][0], (const unsigned*)&g_hsplitL[1][0]};

    int bb = tid >> 3, hh = tid & 7;
    int j = bid * 8 + hh;
    float cc = 0.f;

    int br = (lane & 7) + ((lane >> 4) & 1) * 8;
    int bc = ((lane >> 3) & 1) * 16;
    int k0base = w * 128;

    for (int t = 0; t < 256; ++t) {
        int rb = t & 1;
        float acc[2][4][4];
#pragma unroll
        for (int m = 0; m < 2; ++m)
#pragma unroll
            for (int g = 0; g < 4; ++g)
#pragma unroll
                for (int r4 = 0; r4 < 4; ++r4) acc[m][g][r4] = 0.f;

        if (t > 0) {
#pragma unroll 2
            for (int kf = 0; kf < 8; ++kf) {
                int k0 = k0base + kf * 16;
                uint32_t ah[2][4], al[2][4];
#pragma unroll
                for (int m = 0; m < 2; ++m) {
                    int base2 = ((m * 16 + (lane >> 2)) * 1024 + k0) / 2 + (lane & 3);
                    ah[m][0] = __ldcg(hHr[rb] + base2);
                    ah[m][1] = __ldcg(hHr[rb] + base2 + 4096);
                    ah[m][2] = __ldcg(hHr[rb] + base2 + 4);
                    ah[m][3] = __ldcg(hHr[rb] + base2 + 4100);
                    al[m][0] = __ldcg(hLr[rb] + base2);
                    al[m][1] = __ldcg(hLr[rb] + base2 + 4096);
                    al[m][2] = __ldcg(hLr[rb] + base2 + 4);
                    al[m][3] = __ldcg(hLr[rb] + base2 + 4100);
                }
                int chunk = k0 >> 6, kin = k0 & 63;
                uint32_t cbs = smb + chunk * 8192;
                uint32_t bh[2][4], bl[2][4];
#pragma unroll
                for (int nt = 0; nt < 2; ++nt) {
                    uint32_t off = swz((unsigned)((nt * 16 + br) * 128 + bc + kin * 2));
                    ldm_x4(bh[nt], cbs + off);
                    ldm_x4(bl[nt], cbs + 4096 + off);
                }
#pragma unroll
                for (int m = 0; m < 2; ++m)
#pragma unroll
                    for (int g = 0; g < 4; ++g) {
                        mma16816(acc[m][g], ah[m], &bh[g >> 1][(g & 1) * 2]);
                        mma16816(acc[m][g], ah[m], &bl[g >> 1][(g & 1) * 2]);
                        mma16816(acc[m][g], al[m], &bh[g >> 1][(g & 1) * 2]);
                    }
            }
        }
#pragma unroll
        for (int m = 0; m < 2; ++m)
#pragma unroll
            for (int g = 0; g < 4; ++g)
#pragma unroll
                for (int r4 = 0; r4 < 4; ++r4)
                    red[((w * 2 + m) * 4 + g) * 128 + lane * 4 + r4] = acc[m][g][r4];
        __syncthreads();
        {
            int r = bb & 15, m = bb >> 4;
            int gl = ((r & 7) << 2) | (hh >> 1);
            int rg = (hh & 1) + 2 * ((r >> 3) & 1);
            float gv[4] = {0.f, 0.f, 0.f, 0.f};
#pragma unroll
            for (int w2 = 0; w2 < 8; ++w2)
#pragma unroll
                for (int g = 0; g < 4; ++g)
                    gv[g] += red[((w2 * 2 + m) * 4 + g) * 128 + gl * 4 + rg];
            const float* p = pre + ((size_t)bb * 256 + t) * 4096 + j;
            float ai = gv[0] + p[0];
            float af = gv[1] + p[1024];
            float agg = gv[2] + p[2048];
            float ao = gv[3] + p[3072];
            cc = sigm(af) * cc + sigm(ai) * tanhf(agg);
            float hn = sigm(ao) * tanhf(cc);
            dout[((size_t)bb * 256 + t) * 1024 + j] = hn;
            __nv_bfloat16 hi = __float2bfloat16(hn);
            __nv_bfloat16 lo = __float2bfloat16(hn - __bfloat162float(hi));
            g_hsplitH[rb ^ 1][bb * 1024 + j] = hi;
            g_hsplitL[rb ^ 1][bb * 1024 + j] = lo;
        }
        __threadfence();
        __syncthreads();
        if (tid == 0) {
            atomicAdd(&g_bar, 1u);
            unsigned tgt = (unsigned)(t + 1) * 128u;
            while (*(volatile unsigned*)&g_bar < tgt) {}
        }
        __syncthreads();
    }
}

// ---- SIMT SGEMM (sentence pre-gates) ----
__global__ void __launch_bounds__(256) sgemm128_kernel(
    const float* __restrict__ A, const float* __restrict__ W,
    const float* __restrict__ bias, float* __restrict__ C, int M, int N, int K) {
    __shared__ __align__(16) float As[2][8][132];
    __shared__ __align__(16) float Bs[2][8][132];
    int tid = threadIdx.x;
    int m0 = blockIdx.y * 128, n0 = blockIdx.x * 128;
    int grow = tid >> 1, gk = (tid & 1) * 4;
    const float* Ap = A + (size_t)(m0 + grow) * K + gk;
    const float* Wp = W + (size_t)(n0 + grow) * K + gk;
    int tm4 = (tid >> 4) * 4, tn4 = (tid & 15) * 4;
    float acc[8][8];
#pragma unroll
    for (int i = 0; i < 8; ++i)
#pragma unroll
        for (int j = 0; j < 8; ++j) acc[i][j] = 0.f;
    int nk = (K + 7) / 8;
    float4 pa, pb;
    pa = (gk < K) ? *(const float4*)Ap : make_float4(0, 0, 0, 0);
    pb = (gk < K) ? *(const float4*)Wp : make_float4(0, 0, 0, 0);
    As[0][gk + 0][grow] = pa.x; As[0][gk + 1][grow] = pa.y;
    As[0][gk + 2][grow] = pa.z; As[0][gk + 3][grow] = pa.w;
    Bs[0][gk + 0][grow] = pb.x; Bs[0][gk + 1][grow] = pb.y;
    Bs[0][gk + 2][grow] = pb.z; Bs[0][gk + 3][grow] = pb.w;
    __syncthreads();
    for (int it = 0; it < nk; ++it) {
        int buf = it & 1;
        bool more = (it + 1) < nk;
        if (more) {
            int kt = (it + 1) * 8;
            pa = (kt + gk < K) ? *(const float4*)(Ap + kt) : make_float4(0, 0, 0, 0);
            pb = (kt + gk < K) ? *(const float4*)(Wp + kt) : make_float4(0, 0, 0, 0);
        }
#pragma unroll
        for (int kk = 0; kk < 8; ++kk) {
            float4 a0 = *(const float4*)&As[buf][kk][tm4];
            float4 a1 = *(const float4*)&As[buf][kk][tm4 + 64];
            float4 b0 = *(const float4*)&Bs[buf][kk][tn4];
            float4 b1 = *(const float4*)&Bs[buf][kk][tn4 + 64];
            float av[8] = {a0.x, a0.y, a0.z, a0.w, a1.x, a1.y, a1.z, a1.w};
            float bv[8] = {b0.x, b0.y, b0.z, b0.w, b1.x, b1.y, b1.z, b1.w};
#pragma unroll
            for (int i = 0; i < 8; ++i)
#pragma unroll
                for (int j = 0; j < 8; ++j) acc[i][j] += av[i] * bv[j];
        }
        if (more) {
            int nb2 = buf ^ 1;
            As[nb2][gk + 0][grow] = pa.x; As[nb2][gk + 1][grow] = pa.y;
            As[nb2][gk + 2][grow] = pa.z; As[nb2][gk + 3][grow] = pa.w;
            Bs[nb2][gk + 0][grow] = pb.x; Bs[nb2][gk + 1][grow] = pb.y;
            Bs[nb2][gk + 2][grow] = pb.z; Bs[nb2][gk + 3][grow] = pb.w;
        }
        __syncthreads();
    }
    float bb0[4] = {0, 0, 0, 0}, bb1[4] = {0, 0, 0, 0};
    if (bias) {
#pragma unroll
        for (int j = 0; j < 4; ++j) { bb0[j] = bias[n0 + tn4 + j]; bb1[j] = bias[n0 + tn4 + 64 + j]; }
    }
#pragma unroll
    for (int i = 0; i < 8; ++i) {
        int r = m0 + tm4 + (i & 3) + ((i >> 2) << 6);
        float4 v0 = make_float4(acc[i][0] + bb0[0], acc[i][1] + bb0[1], acc[i][2] + bb0[2], acc[i][3] + bb0[3]);
        float4 v1 = make_float4(acc[i][4] + bb1[0], acc[i][5] + bb1[1], acc[i][6] + bb1[2], acc[i][7] + bb1[3]);
        *(float4*)(C + (size_t)r * N + n0 + tn4) = v0;
        *(float4*)(C + (size_t)r * N + n0 + tn4 + 64) = v1;
    }
}

// ---- persistent sentence BiLSTM recurrence (smem-resident weights) ----
// 64 blocks: dir(2) x jb(16 of 16 j) x sb(2 of 16 seqs). Thread owns (seq, j).
template <bool STAGE>
__global__ void __launch_bounds__(256) sentrec_kernel(
    const float* __restrict__ pre, const float* __restrict__ WhP,
    float* __restrict__ out, const int* __restrict__ words, int base) {
    extern __shared__ unsigned char sms[];
    float4* wS = (float4*)sms;                     // 64 KB
    float* hsm = (float*)(sms + 65536);            // 16 KB
    float* wm = (float*)(sms + 65536 + 16384);     // 16 KB
    int tid = threadIdx.x, bid = blockIdx.x;
    int dir = bid >> 5, jb = (bid >> 1) & 15, sb = bid & 1;
    int jl = tid & 15, sq = tid >> 4;
    int s = sb * 16 + sq;
    int j = jb * 16 + jl;

    const float4* Wsrc = (const float4*)(WhP + (size_t)dir * (256 * 256 * 4));
    for (int i = tid; i < 4096; i += 256) {
        int k = i >> 4;
        wS[i] = Wsrc[k * 256 + jb * 16 + (i & 15)];
    }
    if (STAGE) {
        for (int x = tid; x < 4096; x += 256)
            wm[x] = (words[(sb * 16 + (x >> 8)) * 256 + (x & 255)] != 0) ? 1.f : 0.f;
    }
    float cc = 0.f;
    __syncthreads();

    for (int tt = 0; tt < 16; ++tt) {
        int rb = tt & 1;
        int t = dir ? (15 - tt) : tt;
        if (tt > 0) {
            const float4* src = (const float4*)(g_shs + ((rb * 2 + dir) * 32 + sb * 16) * 256);
            float4* dst = (float4*)hsm;
#pragma unroll
            for (int i = 0; i < 4; ++i) dst[tid + i * 256] = __ldcg(src + tid + i * 256);
            __syncthreads();
        }
        size_t pb = ((size_t)(s * 16 + t) * 2 + dir) * 1024 + j;
        float ai = pre[pb], af = pre[pb + 256], ag = pre[pb + 512], ao = pre[pb + 768];
        if (tt > 0) {
#pragma unroll 8
            for (int k = 0; k < 256; ++k) {
                float4 w = wS[k * 16 + jl];
                float hk = hsm[sq * 256 + k];
                ai += hk * w.x; af += hk * w.y; ag += hk * w.z; ao += hk * w.w;
            }
        }
        float cv = sigm(af) * cc + sigm(ai) * tanhf(ag);
        float hn = sigm(ao) * tanhf(cv);
        cc = cv;
        out[((size_t)s * 16 + t) * 512 + dir * 256 + j] = hn;
        g_shs[(((rb ^ 1) * 2 + dir) * 32 + s) * 256 + j] = hn;
        if (STAGE) {
            float v1 = __shfl_down_sync(0xffffffffu, hn, 1);
            if (!(jl & 1)) {
                int kp = 32 + dir * 256 + j;
                int rbrow = (s * 16 + t) * 16;
                int blk = rbrow >> 7;
#pragma unroll
                for (int tw = 0; tw < 16; ++tw) {
                    float m = wm[sq * 256 + t * 16 + tw];
                    split_store_pair(g_stageA, NCH_W0, blk, (rbrow & 127) + tw, kp, hn * m, v1 * m);
                }
            }
        }
        __threadfence();
        __syncthreads();
        if (tid == 0) {
            atomicAdd(&g_bar3, 1u);
            unsigned tgt = (unsigned)(base + tt + 1) * 64u;
            while (*(volatile unsigned*)&g_bar3 < tgt) {}
        }
        __syncthreads();
    }
}

// ---- attention (writes attn split directly into decoder staging) ----
__global__ void attention_kernel(const float* __restrict__ q, const float* __restrict__ sent_enc,
                                 const int* __restrict__ words, float* __restrict__ map_out) {
    int bi = blockIdx.x, b = bi >> 4, i = bi & 15;
    __shared__ float se[16 * 513];
    __shared__ float sc[16][16];
    __shared__ float mp[16][16];
    __shared__ int kv[16];
    for (int x = threadIdx.x; x < 16 * 512; x += 256) {
        int jj = x >> 9, d = x & 511;
        se[jj * 513 + d] = sent_enc[((size_t)b * 16 + jj) * 512 + d];
    }
    if (threadIdx.x < 16) {
        int jj = threadIdx.x, any = 0;
        for (int tw = 0; tw < 16; ++tw) any |= (words[(b * 16 + jj) * 16 + tw] != 0);
        kv[jj] = any;
    }
    __syncthreads();
    {
        int cdx = threadIdx.x >> 4, jj = threadIdx.x & 15;
        const float* qr = q + ((size_t)bi * 16 + cdx) * 512;
        const float* ser = se + jj * 513;
        float s = 0.f;
#pragma unroll 4
        for (int d = 0; d < 512; ++d) s += qr[d] * ser[d];
        sc[cdx][jj] = s;
    }
    __syncthreads();
    if (threadIdx.x < 16) {
        int cdx = threadIdx.x;
        float v[16], m = -1e30f;
#pragma unroll
        for (int jj = 0; jj < 16; ++jj) {
            bool valid = (kv[jj] != 0) && (jj != i);
            v[jj] = valid ? sc[cdx][jj] : -1e9f;
            m = fmaxf(m, v[jj]);
        }
        float sum = 0.f;
#pragma unroll
        for (int jj = 0; jj < 16; ++jj) { v[jj] = expf(v[jj] - m); sum += v[jj]; }
        float inv = 1.f / sum;
#pragma unroll
        for (int jj = 0; jj < 16; ++jj) mp[cdx][jj] = v[jj] * inv;
    }
    __syncthreads();
    if (map_out != nullptr && threadIdx.x < 256) {
        int x = threadIdx.x;
        map_out[(size_t)bi * 256 + x] = mp[x >> 4][x & 15];
    }
    for (int x = threadIdx.x; x < 16 * 512; x += 256) {
        int cdx = x >> 9, d = x & 511;
        float s = 0.f;
#pragma unroll
        for (int jj = 0; jj < 16; ++jj) s += mp[cdx][jj] * se[jj * 513 + d];
        int r = bi * 16 + cdx;
        split_store_half(g_stageD + ((size_t)(r >> 7) * 25 + (d >> 6)) * PAIR_BYTES,
                         r & 127, d & 63, s);
    }
}

__global__ void classifier_kernel(const float* __restrict__ dec_out,
                                  const float* __restrict__ Wt,
                                  const float* __restrict__ bias, float* __restrict__ out) {
    int m = blockIdx.x * 16 + (threadIdx.x >> 4);
    int n = threadIdx.x & 15;
    if (n >= 15) return;
    const float4* x = (const float4*)(dec_out + (size_t)m * 1024);
    const float4* w = (const float4*)(Wt + n * 1024);
    float s = bias[n];
#pragma unroll 8
    for (int k = 0; k < 256; ++k) {
        float4 a = x[k], b = w[k];
        s += a.x * b.x + a.y * b.y + a.z * b.z + a.w * b.w;
    }
    out[(size_t)m * 15 + n] = s;
}

// ---- host ----
static void* symp(const void* s) { void* p = nullptr; cudaGetSymbolAddress(&p, s); return p; }

extern "C" void kernel_launch(void* const* d_in, const int* in_sizes, int n_in,
                              void* d_out, int out_size) {
    (void)in_sizes; (void)n_in;
    const int* sents = (const int*)d_in[0];
    const int* words = (const int*)d_in[1];
    const int* labels = (const int*)d_in[2];
    const float* word_embs = (const float*)d_in[3];
    const float* char_table = (const float*)d_in[4];
    const float* sWx0 = (const float*)d_in[5];
    const float* sWh0 = (const float*)d_in[6];
    const float* sb0 = (const float*)d_in[7];
    const float* sWx1 = (const float*)d_in[8];
    const float* sWh1 = (const float*)d_in[9];
    const float* sb1 = (const float*)d_in[10];
    const float* wWx0 = (const float*)d_in[11];
    const float* wWh0 = (const float*)d_in[12];
    const float* wb0 = (const float*)d_in[13];
    const float* wWx1 = (const float*)d_in[14];
    const float* wWh1 = (const float*)d_in[15];
    const float* wb1 = (const float*)d_in[16];
    const float* Wq = (const float*)d_in[17];
    const float* dWx = (const float*)d_in[18];
    const float* dWh = (const float*)d_in[19];
    const float* db = (const float*)d_in[20];
    const float* clsW = (const float*)d_in[21];
    const float* clsb = (const float*)d_in[22];
    float* out = (float*)d_out;

    float* wembs = (float*)symp(g_wembs);
    float* pre_s = (float*)symp(g_pre_s);
    float* sent_h0 = (float*)symp(g_sent_h0);
    float* sent_enc = (float*)symp(g_sent_enc);
    float* pre_w = (float*)symp(g_pre_w);
    float* qbuf = (float*)symp(g_q);
    float* pre_d = (float*)symp(g_pre_d);
    float* dec_out = (float*)symp(g_dec_out);
    float* sWh0P = (float*)symp(g_sWh0P);
    float* sWh1P = (float*)symp(g_sWh1P);
    float* clsWT = (float*)symp(g_clsWT);
    const unsigned char* stA = (const unsigned char*)symp(g_stageA);
    const unsigned char* stD = (const unsigned char*)symp(g_stageD);
    const unsigned char* stBw0 = (const unsigned char*)symp(g_stB_w0);
    const unsigned char* stBw1 = (const unsigned char*)symp(g_stB_w1);
    const unsigned char* stBq = (const unsigned char*)symp(g_stB_q);
    const unsigned char* stBdec = (const unsigned char*)symp(g_stB_dec);
    const unsigned char* stWw = (const unsigned char*)symp(g_stWw);

    cudaFuncSetAttribute(tgemm_kernel, cudaFuncAttributeMaxDynamicSharedMemorySize, TG_SMEM);
    cudaFuncSetAttribute(dec_persist_kernel, cudaFuncAttributeMaxDynamicSharedMemorySize, DEC_SMEM);
    cudaFuncSetAttribute(wordrec_kernel, cudaFuncAttributeMaxDynamicSharedMemorySize, WR_SMEM);
    cudaFuncSetAttribute(sentrec_kernel<false>, cudaFuncAttributeMaxDynamicSharedMemorySize, SR_SMEM);
    cudaFuncSetAttribute(sentrec_kernel<true>, cudaFuncAttributeMaxDynamicSharedMemorySize, SR_SMEM);

    const size_t wwLayer = 2ul * 16 * 8 * PAIR_BYTES;

    prep_kernel<<<PREP_BLOCKS, 256>>>(sWh0, sWh1, wWh0, wWh1, dWh, wWx0, wWx1, Wq, dWx,
                                      words, char_table, sents, word_embs, labels, clsW);
    sgemm128_kernel<<<dim3(16, 4), 256>>>(wembs, sWx0, sb0, pre_s, 512, 2048, 300);
    sentrec_kernel<false><<<64, 256, SR_SMEM>>>(pre_s, sWh0P, sent_h0, nullptr, 0);
    sgemm128_kernel<<<dim3(16, 4), 256>>>(sent_h0, sWx1, sb1, pre_s, 512, 2048, 512);
    sentrec_kernel<true><<<64, 256, SR_SMEM>>>(pre_s, sWh1P, sent_enc, words, 16);
    // word layer 0
    tgemm_kernel<<<dim3(32, 64), 256, TG_SMEM>>>(stA, stBw0, wb0, pre_w, 4096, NCH_W0);
    wordrec_kernel<<<128, 256, WR_SMEM>>>(stWw, pre_w, 0, 0);
    // word layer 1
    tgemm_kernel<<<dim3(32, 64), 256, TG_SMEM>>>(stA, stBw1, wb1, pre_w, 4096, NCH_W1);
    wordrec_kernel<<<128, 256, WR_SMEM>>>(stWw + wwLayer, pre_w, 1, 16);
    // attention
    tgemm_kernel<<<dim3(4, 64), 256, TG_SMEM>>>(stA, stBq, nullptr, qbuf, 512, NCH_Q);
    float* map_out = (out_size >= (NR_ * 15 + 131072)) ? (out + NR_ * 15) : nullptr;
    attention_kernel<<<NSEQ_, 256>>>(qbuf, sent_enc, words, map_out);
    // decoder
    tgemm_kernel<<<dim3(32, 64), 256, TG_SMEM>>>(stD, stBdec, db, pre_d, 4096, NCH_DEC);
    dec_persist_kernel<<<128, 256, DEC_SMEM>>>(pre_d, dec_out);
    classifier_kernel<<<NR_ / 16, 256>>>(dec_out, clsWT, clsb, out);
}

// round 10
// speedup vs baseline: 6.3013x; 1.0248x over previous
#include <cuda_runtime.h>
#include <cuda_bf16.h>
#include <math.h>
#include <stdint.h>

#define B_ 32
#define SH_ 256
#define WH_ 512
#define DH_ 1024
#define NSEQ_ 512
#define NR_ 8192
#define NCH_W0 9
#define NCH_W1 16
#define NCH_Q 16
#define NCH_DEC 25
#define TILE_BYTES 16384
#define PAIR_BYTES 32768
#define TG_SMEM 131072
#define DEC_SMEM (131072 + 32768)
#define WR_SMEM (131072 + 2 * 49152)
#define SR_SMEM (65536 + 16384 + 16384)

#define DEVBUF __device__ __align__(16)
DEVBUF float g_pre_s[NSEQ_ * 2048];
DEVBUF float g_sent_enc[NSEQ_ * 512];
DEVBUF float g_pre_w[NR_ * 4096];
DEVBUF float g_q[NR_ * 512];
DEVBUF float g_pre_d[NR_ * 4096];
DEVBUF float g_dec_out[NR_ * 1024];
DEVBUF float g_sWh0P[2 * SH_ * SH_ * 4];
DEVBUF float g_sWh1P[2 * SH_ * SH_ * 4];
DEVBUF float g_clsWT[15 * 1024];
DEVBUF float g_shs[2 * 2 * 32 * 256];
DEVBUF unsigned char g_stageA[64ul * 16 * PAIR_BYTES];
DEVBUF unsigned char g_stageD[64ul * 25 * PAIR_BYTES];
DEVBUF unsigned char g_stageS[4ul * 5 * PAIR_BYTES];
DEVBUF unsigned char g_stageS2[4ul * 8 * PAIR_BYTES];
DEVBUF unsigned char g_stB_s0[16ul * 5 * PAIR_BYTES];
DEVBUF unsigned char g_stB_s1[16ul * 8 * PAIR_BYTES];
DEVBUF unsigned char g_stB_w0[32ul * NCH_W0 * PAIR_BYTES];
DEVBUF unsigned char g_stB_w1[32ul * NCH_W1 * PAIR_BYTES];
DEVBUF unsigned char g_stB_q[4ul * NCH_Q * PAIR_BYTES];
DEVBUF unsigned char g_stB_dec[32ul * NCH_DEC * PAIR_BYTES];
DEVBUF unsigned char g_stDWr[32ul * 16 * PAIR_BYTES];
DEVBUF unsigned char g_stWw[4ul * 16 * 8 * PAIR_BYTES];
DEVBUF unsigned char g_hstage[128ul * PAIR_BYTES];
DEVBUF __nv_bfloat16 g_hsplitH[2][B_ * DH_];
DEVBUF __nv_bfloat16 g_hsplitL[2][B_ * DH_];
// tree barriers: 8 counters each, 128B apart
DEVBUF unsigned g_barT[8 * 32];
DEVBUF unsigned g_barT2[8 * 32];
DEVBUF unsigned g_barT3[8 * 32];

__device__ __forceinline__ float sigm(float x) { return 1.f / (1.f + expf(-x)); }
__device__ __forceinline__ unsigned swz(unsigned o) { return o ^ ((o >> 3) & 0x70); }

__device__ __forceinline__ uint32_t smem_u32(const void* p) {
    uint32_t a;
    asm("{ .reg .u64 t; cvta.to.shared.u64 t, %1; cvt.u32.u64 %0, t; }" : "=r"(a) : "l"(p));
    return a;
}
__device__ __forceinline__ void cp_async16(uint32_t dst, const void* src) {
    asm volatile("cp.async.cg.shared.global [%0], [%1], 16;" :: "r"(dst), "l"(src) : "memory");
}
__device__ __forceinline__ void cp_commit() {
    asm volatile("cp.async.commit_group;" ::: "memory");
}
template <int N>
__device__ __forceinline__ void cp_wait() {
    asm volatile("cp.async.wait_group %0;" :: "n"(N) : "memory");
}
__device__ __forceinline__ void ldm_x4(uint32_t* r, uint32_t addr) {
    asm volatile("ldmatrix.sync.aligned.m8n8.x4.shared.b16 {%0,%1,%2,%3}, [%4];"
                 : "=r"(r[0]), "=r"(r[1]), "=r"(r[2]), "=r"(r[3]) : "r"(addr));
}
__device__ __forceinline__ void mma16816(float* d, const uint32_t* a, const uint32_t* b) {
    asm volatile(
        "mma.sync.aligned.m16n8k16.row.col.f32.bf16.bf16.f32 "
        "{%0,%1,%2,%3},{%4,%5,%6,%7},{%8,%9},{%0,%1,%2,%3};"
        : "+f"(d[0]), "+f"(d[1]), "+f"(d[2]), "+f"(d[3])
        : "r"(a[0]), "r"(a[1]), "r"(a[2]), "r"(a[3]), "r"(b[0]), "r"(b[1]));
}

// tree barrier: 128-block (per16) or 64-block (per8) variants
__device__ __forceinline__ void tree_barrier(unsigned* bar, int bid, int tid,
                                             unsigned step1, unsigned perCtr) {
    if (tid == 0) atomicAdd(&bar[(bid & 7) * 32], 1u);
    if (tid < 8) {
        unsigned tgt = step1 * perCtr;
        while (*(volatile unsigned*)&bar[tid * 32] < tgt) {}
    }
    __syncthreads();
}

// ---- bf16 split stores ----
__device__ __forceinline__ void split_store_pair(unsigned char* st, int nCh, int blk,
                                                 int row, int kp, float v0, float v1) {
    int chunk = kp >> 6, kin = kp & 63;
    size_t base = ((size_t)(blk * nCh + chunk)) * PAIR_BYTES;
    unsigned so = swz((unsigned)(row * 128 + kin * 2));
    __nv_bfloat16 h0 = __float2bfloat16(v0), h1 = __float2bfloat16(v1);
    __nv_bfloat16 l0 = __float2bfloat16(v0 - __bfloat162float(h0));
    __nv_bfloat16 l1 = __float2bfloat16(v1 - __bfloat162float(h1));
    *(unsigned*)(st + base + so) =
        (unsigned)__bfloat16_as_ushort(h0) | ((unsigned)__bfloat16_as_ushort(h1) << 16);
    *(unsigned*)(st + base + TILE_BYTES + so) =
        (unsigned)__bfloat16_as_ushort(l0) | ((unsigned)__bfloat16_as_ushort(l1) << 16);
}
__device__ __forceinline__ void split_store_half(unsigned char* tileBase, int row, int kin,
                                                 float v) {
    unsigned so = swz((unsigned)(row * 128 + kin * 2));
    __nv_bfloat16 hi = __float2bfloat16(v);
    __nv_bfloat16 lo = __float2bfloat16(v - __bfloat162float(hi));
    *(unsigned short*)(tileBase + so) = __bfloat16_as_ushort(hi);
    *(unsigned short*)(tileBase + TILE_BYTES + so) = __bfloat16_as_ushort(lo);
}

// ---- prep ----
__device__ __forceinline__ void pack_region(const float* Wh, float* out, int H, long r) {
    long per = 4L * H * H;
    int dir = (int)(r / per);
    long s = r % per;
    int g = (int)(s & 3), jj = (int)((s >> 2) % H), k = (int)(s / (4 * H));
    out[dir * per + s] = Wh[dir * per + (size_t)(g * H + jj) * H + k];
}
#define R_SWH 524288L
#define R_DWS 2097152L
#define R_WB 2097152L
#define R_BW0 1179648L
#define R_BW1 2097152L
#define R_BQ 262144L
#define R_BDEC 3276800L
#define R_CEMB 131072L
#define R_PAD 131072L
#define R_BS0 327680L
#define R_BS1 524288L
#define R_EMBS 81920L
#define R_DLAB 262144L
#define R_CLS 15360L
#define PREP_BLOCKS 52860

__global__ void prep_kernel(const float* __restrict__ sWh0, const float* __restrict__ sWh1,
                            const float* __restrict__ wWh0, const float* __restrict__ wWh1,
                            const float* __restrict__ dWh, const float* __restrict__ wWx0,
                            const float* __restrict__ wWx1, const float* __restrict__ Wq,
                            const float* __restrict__ dWx, const int* __restrict__ words,
                            const float* __restrict__ char_table, const int* __restrict__ sents,
                            const float* __restrict__ word_embs, const int* __restrict__ labels,
                            const float* __restrict__ clsW, const float* __restrict__ sWx0,
                            const float* __restrict__ sWx1) {
    if (blockIdx.x == 0 && threadIdx.x < 8) {
        g_barT[threadIdx.x * 32] = 0u;
        g_barT2[threadIdx.x * 32] = 0u;
        g_barT3[threadIdx.x * 32] = 0u;
    }
    long idx = (long)blockIdx.x * 256 + threadIdx.x;
    if (idx < R_SWH) { pack_region(sWh0, g_sWh0P, SH_, idx); return; }
    idx -= R_SWH;
    if (idx < R_SWH) { pack_region(sWh1, g_sWh1P, SH_, idx); return; }
    idx -= R_SWH;
    if (idx < R_DWS) {
        int n = (int)(idx / 512), kp = 2 * (int)(idx % 512);
        split_store_pair(g_stDWr, 16, n >> 7, n & 127, kp,
                         dWh[(size_t)n * 1024 + kp], dWh[(size_t)n * 1024 + kp + 1]);
        return;
    }
    idx -= R_DWS;
    if (idx < R_WB) {
        int ld = (int)(idx >> 19);
        long e = idx & ((1L << 19) - 1);
        int r = (int)(e >> 8);
        int kp = 2 * (int)(e & 255);
        int g = r & 3, j = r >> 2;
        const float* Ws = (ld >> 1) ? wWh1 : wWh0;
        const float* w = Ws + (size_t)(ld & 1) * 4 * 512 * 512 + (size_t)(g * 512 + j) * 512;
        split_store_pair(g_stWw + (size_t)ld * 16 * 8 * PAIR_BYTES, 8, r >> 7, r & 127, kp,
                         w[kp], w[kp + 1]);
        return;
    }
    idx -= R_WB;
    if (idx < R_BW0) {
        int n = (int)(idx / 288), kp = 2 * (int)(idx % 288);
        float v0 = (kp < 544) ? wWx0[(size_t)n * 544 + kp] : 0.f;
        float v1 = (kp + 1 < 544) ? wWx0[(size_t)n * 544 + kp + 1] : 0.f;
        split_store_pair(g_stB_w0, NCH_W0, n >> 7, n & 127, kp, v0, v1);
        return;
    }
    idx -= R_BW0;
    if (idx < R_BW1) {
        int n = (int)(idx / 512), kp = 2 * (int)(idx % 512);
        split_store_pair(g_stB_w1, NCH_W1, n >> 7, n & 127, kp,
                         wWx1[(size_t)n * 1024 + kp], wWx1[(size_t)n * 1024 + kp + 1]);
        return;
    }
    idx -= R_BW1;
    if (idx < R_BQ) {
        int n = (int)(idx / 512), kp = 2 * (int)(idx % 512);
        split_store_pair(g_stB_q, NCH_Q, n >> 7, n & 127, kp,
                         Wq[(size_t)kp * 512 + n], Wq[(size_t)(kp + 1) * 512 + n]);
        return;
    }
    idx -= R_BQ;
    if (idx < R_BDEC) {
        int n = (int)(idx / 800), kp = 2 * (int)(idx % 800);
        float v0 = (kp < 1544) ? dWx[(size_t)n * 1544 + kp] : 0.f;
        float v1 = (kp + 1 < 1544) ? dWx[(size_t)n * 1544 + kp + 1] : 0.f;
        split_store_pair(g_stB_dec, NCH_DEC, n >> 7, n & 127, kp, v0, v1);
        return;
    }
    idx -= R_BDEC;
    if (idx < R_CEMB) {
        int r = (int)(idx / 16), kp = 2 * (int)(idx % 16);
        int w = words[r];
        split_store_pair(g_stageA, NCH_W0, r >> 7, r & 127, kp,
                         char_table[w * 32 + kp], char_table[w * 32 + kp + 1]);
        return;
    }
    idx -= R_CEMB;
    if (idx < R_PAD) {
        int r = (int)(idx / 16), kp = 544 + 2 * (int)(idx % 16);
        split_store_pair(g_stageA, NCH_W0, r >> 7, r & 127, kp, 0.f, 0.f);
        return;
    }
    idx -= R_PAD;
    if (idx < R_BS0) {
        int n = (int)(idx / 160), kp = 2 * (int)(idx % 160);
        int dir = n >> 10, j = n & 1023;
        const float* w = sWx0 + (size_t)dir * 1024 * 300 + (size_t)j * 300;
        float v0 = (kp < 300) ? w[kp] : 0.f;
        float v1 = (kp + 1 < 300) ? w[kp + 1] : 0.f;
        split_store_pair(g_stB_s0, 5, n >> 7, n & 127, kp, v0, v1);
        return;
    }
    idx -= R_BS0;
    if (idx < R_BS1) {
        int n = (int)(idx / 256), kp = 2 * (int)(idx % 256);
        int dir = n >> 10, j = n & 1023;
        const float* w = sWx1 + (size_t)dir * 1024 * 512 + (size_t)j * 512;
        split_store_pair(g_stB_s1, 8, n >> 7, n & 127, kp, w[kp], w[kp + 1]);
        return;
    }
    idx -= R_BS1;
    if (idx < R_EMBS) {
        int r = (int)(idx / 160), kp = 2 * (int)(idx % 160);
        const float* e = word_embs + (size_t)sents[r] * 300;
        float v0 = (kp < 300) ? e[kp] : 0.f;
        float v1 = (kp + 1 < 300) ? e[kp + 1] : 0.f;
        split_store_pair(g_stageS, 5, r >> 7, r & 127, kp, v0, v1);
        return;
    }
    idx -= R_EMBS;
    if (idx < R_DLAB) {
        int r = (int)(idx / 32), kp = 1536 + 2 * (int)(idx % 32);
        float v0 = (kp < 1544) ? (float)labels[r * 8 + (kp - 1536)] : 0.f;
        float v1 = (kp + 1 < 1544) ? (float)labels[r * 8 + (kp + 1 - 1536)] : 0.f;
        split_store_pair(g_stageD, NCH_DEC, r >> 7, r & 127, kp, v0, v1);
        return;
    }
    idx -= R_DLAB;
    if (idx < R_CLS) {
        int n = (int)(idx / 1024), k = (int)(idx % 1024);
        g_clsWT[n * 1024 + k] = clsW[(size_t)k * 15 + n];
    }
}

// ---- HMMA GEMM ----
__global__ void __launch_bounds__(256) tgemm_kernel(
    const unsigned char* __restrict__ stA, const unsigned char* __restrict__ stB,
    const float* __restrict__ bias, float* __restrict__ C, int N, int nCh) {
    extern __shared__ unsigned char smraw[];
    uint32_t smb = smem_u32(smraw);
    uint32_t ab = (smb + 1023) & ~1023u;
    int tid = threadIdx.x, lane = tid & 31, wid = tid >> 5;
    int wm = wid & 1, wn = wid >> 1;
    int nb = blockIdx.x, mb = blockIdx.y;

    float acc[4][4][4];
#pragma unroll
    for (int i = 0; i < 4; ++i)
#pragma unroll
        for (int j = 0; j < 4; ++j)
#pragma unroll
            for (int k = 0; k < 4; ++k) acc[i][j][k] = 0.f;

    int ar = (lane & 7) + ((lane >> 3) & 1) * 8;
    int ac = (lane >> 4) * 16;
    int br = (lane & 7) + ((lane >> 4) & 1) * 8;
    int bc = ((lane >> 3) & 1) * 16;

    auto issue = [&](int c) {
        uint32_t dst = ab + (c & 1) * 65536;
        const unsigned char* sA = stA + ((size_t)mb * nCh + c) * PAIR_BYTES;
        const unsigned char* sB = stB + ((size_t)nb * nCh + c) * PAIR_BYTES;
#pragma unroll
        for (int i = 0; i < 8; ++i)
            cp_async16(dst + (tid + i * 256) * 16, sA + (tid + i * 256) * 16);
#pragma unroll
        for (int i = 0; i < 8; ++i)
            cp_async16(dst + 32768 + (tid + i * 256) * 16, sB + (tid + i * 256) * 16);
        cp_commit();
    };

    issue(0);
    for (int c = 0; c < nCh; ++c) {
        if (c + 1 < nCh) { issue(c + 1); cp_wait<1>(); }
        else             { cp_wait<0>(); }
        __syncthreads();
        uint32_t base = ab + (c & 1) * 65536;
#pragma unroll
        for (int ks = 0; ks < 4; ++ks) {
            uint32_t ah[4][4], al[4][4], bh[2][4], bl[2][4];
#pragma unroll
            for (int mf = 0; mf < 4; ++mf) {
                uint32_t off = swz((unsigned)((wm * 64 + mf * 16 + ar) * 128 + ac + ks * 32));
                ldm_x4(ah[mf], base + off);
                ldm_x4(al[mf], base + 16384 + off);
            }
#pragma unroll
            for (int nf2 = 0; nf2 < 2; ++nf2) {
                uint32_t off = swz((unsigned)((wn * 32 + nf2 * 16 + br) * 128 + bc + ks * 32));
                ldm_x4(bh[nf2], base + 32768 + off);
                ldm_x4(bl[nf2], base + 49152 + off);
            }
#pragma unroll
            for (int mf = 0; mf < 4; ++mf)
#pragma unroll
                for (int nf = 0; nf < 4; ++nf) {
                    mma16816(acc[mf][nf], ah[mf], &bh[nf >> 1][(nf & 1) * 2]);
                    mma16816(acc[mf][nf], ah[mf], &bl[nf >> 1][(nf & 1) * 2]);
                    mma16816(acc[mf][nf], al[mf], &bh[nf >> 1][(nf & 1) * 2]);
                }
        }
        __syncthreads();
    }
#pragma unroll
    for (int mf = 0; mf < 4; ++mf) {
#pragma unroll
        for (int nf = 0; nf < 4; ++nf) {
            int row = mb * 128 + wm * 64 + mf * 16 + (lane >> 2);
            int col = nb * 128 + wn * 32 + nf * 8 + (lane & 3) * 2;
            float b0 = bias ? bias[col] : 0.f;
            float b1 = bias ? bias[col + 1] : 0.f;
            float2 v0 = make_float2(acc[mf][nf][0] + b0, acc[mf][nf][1] + b1);
            float2 v1 = make_float2(acc[mf][nf][2] + b0, acc[mf][nf][3] + b1);
            *(float2*)(C + (size_t)row * N + col) = v0;
            *(float2*)(C + (size_t)(row + 8) * N + col) = v1;
        }
    }
}

// ---- persistent HMMA word-LSTM recurrence ----
__global__ void __launch_bounds__(256) wordrec_kernel(
    const unsigned char* __restrict__ stW, const float* __restrict__ pre,
    int writeDec, int base) {
    extern __shared__ unsigned char dsm[];
    uint32_t smb = smem_u32(dsm);
    int tid = threadIdx.x, lane = tid & 31, wid = tid >> 5;
    int wm = wid & 1, wn = wid >> 1;
    int bid = blockIdx.x;
    int dir = bid >> 6, r6 = bid & 63, mb = r6 >> 4, nt = r6 & 15;

    {
        const unsigned char* wb = stW + ((size_t)(dir * 16 + nt)) * 8 * PAIR_BYTES;
        uint4* dst = (uint4*)dsm;
#pragma unroll 4
        for (int i = tid; i < 8192; i += 256) {
            int c = i >> 10, w = i & 1023;
            dst[i] = *(const uint4*)(wb + (size_t)c * PAIR_BYTES + w * 16);
        }
    }
    __syncthreads();

    int ar = (lane & 7) + ((lane >> 3) & 1) * 8;
    int ac = (lane >> 4) * 16;
    int br = (lane & 7) + ((lane >> 4) & 1) * 8;
    int bc = ((lane >> 3) & 1) * 16;

    float cacc[4][4][2];
#pragma unroll
    for (int a = 0; a < 4; ++a)
#pragma unroll
        for (int b = 0; b < 4; ++b) { cacc[a][b][0] = 0.f; cacc[a][b][1] = 0.f; }

    for (int t = 0; t < 16; ++t) {
        int rb = t & 1, wbuf = rb ^ 1;
        int tdir = dir ? (15 - t) : t;

        auto issueW = [&](int c) {
            uint32_t dst = smb + 131072 + (c & 1) * 49152;
            const unsigned char* aSrc =
                g_hstage + (((size_t)((dir * 2 + rb) * 4 + mb)) * 8 + c) * PAIR_BYTES;
            const unsigned char* bSrc =
                stW + (((size_t)(dir * 16 + nt)) * 8 + c) * PAIR_BYTES + TILE_BYTES;
#pragma unroll
            for (int i = 0; i < 8; ++i)
                cp_async16(dst + (tid + i * 256) * 16, aSrc + (tid + i * 256) * 16);
#pragma unroll
            for (int i = 0; i < 4; ++i)
                cp_async16(dst + 32768 + (tid + i * 256) * 16, bSrc + (tid + i * 256) * 16);
            cp_commit();
        };

        float acc[4][4][4];
#pragma unroll
        for (int a = 0; a < 4; ++a)
#pragma unroll
            for (int b = 0; b < 4; ++b)
#pragma unroll
                for (int k = 0; k < 4; ++k) acc[a][b][k] = 0.f;

        if (t > 0) {
            issueW(0);
            for (int c = 0; c < 8; ++c) {
                if (c + 1 < 8) { issueW(c + 1); cp_wait<1>(); }
                else           { cp_wait<0>(); }
                __syncthreads();
                uint32_t sb = smb + 131072 + (c & 1) * 49152;
                uint32_t bhb = smb + c * 16384;
#pragma unroll
                for (int ks = 0; ks < 4; ++ks) {
                    uint32_t ah[4][4], al[4][4], bh[2][4], bl[2][4];
#pragma unroll
                    for (int mf = 0; mf < 4; ++mf) {
                        uint32_t off = swz((unsigned)((wm * 64 + mf * 16 + ar) * 128 + ac + ks * 32));
                        ldm_x4(ah[mf], sb + off);
                        ldm_x4(al[mf], sb + 16384 + off);
                    }
#pragma unroll
                    for (int nf2 = 0; nf2 < 2; ++nf2) {
                        uint32_t off = swz((unsigned)((wn * 32 + nf2 * 16 + br) * 128 + bc + ks * 32));
                        ldm_x4(bh[nf2], bhb + off);
                        ldm_x4(bl[nf2], sb + 32768 + off);
                    }
#pragma unroll
                    for (int mf = 0; mf < 4; ++mf)
#pragma unroll
                        for (int nf = 0; nf < 4; ++nf) {
                            mma16816(acc[mf][nf], ah[mf], &bh[nf >> 1][(nf & 1) * 2]);
                            mma16816(acc[mf][nf], ah[mf], &bl[nf >> 1][(nf & 1) * 2]);
                            mma16816(acc[mf][nf], al[mf], &bh[nf >> 1][(nf & 1) * 2]);
                        }
                }
                __syncthreads();
            }
        }

#pragma unroll
        for (int mf = 0; mf < 4; ++mf)
#pragma unroll
            for (int nf = 0; nf < 4; ++nf) {
                float p0 = __shfl_xor_sync(0xffffffffu, acc[mf][nf][0], 1);
                float p1 = __shfl_xor_sync(0xffffffffu, acc[mf][nf][1], 1);
                float p2 = __shfl_xor_sync(0xffffffffu, acc[mf][nf][2], 1);
                float p3 = __shfl_xor_sync(0xffffffffu, acc[mf][nf][3], 1);
                if (!(lane & 1)) {
                    int j = nt * 32 + wn * 8 + nf * 2 + ((lane & 3) >> 1);
                    int r0 = wm * 64 + mf * 16 + (lane >> 2);
#pragma unroll
                    for (int rr = 0; rr < 2; ++rr) {
                        int r = r0 + rr * 8;
                        int n = mb * 128 + r;
                        size_t pb = (size_t)(n * 16 + tdir) * 4096 + dir * 2048 + j;
                        float ai = (rr ? acc[mf][nf][2] : acc[mf][nf][0]) + pre[pb];
                        float af = (rr ? acc[mf][nf][3] : acc[mf][nf][1]) + pre[pb + 512];
                        float ag = (rr ? p2 : p0) + pre[pb + 1024];
                        float ao = (rr ? p3 : p1) + pre[pb + 1536];
                        float cv = cacc[mf][nf][rr];
                        cv = sigm(af) * cv + sigm(ai) * tanhf(ag);
                        float hn = sigm(ao) * tanhf(cv);
                        cacc[mf][nf][rr] = cv;
                        split_store_half(
                            g_hstage + (((size_t)((dir * 2 + wbuf) * 4 + mb)) * 8 + (j >> 6)) * PAIR_BYTES,
                            r, j & 63, hn);
                        int rA = n * 16 + tdir, kp = dir * 512 + j;
                        split_store_half(
                            g_stageA + (((size_t)(rA >> 7) * 16 + (kp >> 6))) * PAIR_BYTES,
                            rA & 127, kp & 63, hn);
                        if (writeDec) {
                            int kp2 = 512 + kp;
                            split_store_half(
                                g_stageD + (((size_t)(rA >> 7) * 25 + (kp2 >> 6))) * PAIR_BYTES,
                                rA & 127, kp2 & 63, hn);
                        }
                    }
                }
            }
        __threadfence();
        __syncthreads();
        tree_barrier(g_barT2, bid, tid, (unsigned)(base + t + 1), 16u);
    }
}

// ---- persistent HMMA decoder ----
__global__ void __launch_bounds__(256) dec_persist_kernel(
    const float* __restrict__ pre, float* __restrict__ dout) {
    extern __shared__ unsigned char dsm[];
    uint32_t smb = smem_u32(dsm);
    int tid = threadIdx.x, lane = tid & 31, w = tid >> 5;
    int bid = blockIdx.x;
    {
        const uint4* src = (const uint4*)g_stDWr;
        uint4* dst = (uint4*)dsm;
#pragma unroll 4
        for (int it = 0; it < 32; ++it) {
            int flat = tid + it * 256;
            int q = flat & 7;
            int ru = flat >> 3;
            int i = ru & 7;
            int hl = (ru >> 3) & 1;
            int g = (ru >> 4) & 3;
            int c = ru >> 6;
            size_t sb = ((((size_t)(g * 8 + (bid >> 4)) * 16 + c) * PAIR_BYTES
                         + (size_t)hl * TILE_BYTES
                         + (size_t)((bid & 15) * 8 + i) * 128) >> 4) + q;
            int db = ((c * 8192 + hl * 4096 + (g * 8 + i) * 128) >> 4) + q;
            dst[db] = src[sb];
        }
    }
    __syncthreads();

    float* red = (float*)(dsm + 131072);
    const unsigned* hHr[2] = {(const unsigned*)&g_hsplitH[0][0], (const unsigned*)&g_hsplitH[1][0]};
    const unsigned* hLr[2] = {(const unsigned*)&g_hsplitL[0][0], (const unsigned*)&g_hsplitL[1][0]};

    int bb = tid >> 3, hh = tid & 7;
    int j = bid * 8 + hh;
    float cc = 0.f;

    int br = (lane & 7) + ((lane >> 4) & 1) * 8;
    int bc = ((lane >> 3) & 1) * 16;
    int k0base = w * 128;

    for (int t = 0; t < 256; ++t) {
        int rb = t & 1;
        // prefetch pre-activations early (independent of h)
        const float* p = pre + ((size_t)bb * 256 + t) * 4096 + j;
        float px0 = p[0], px1 = p[1024], px2 = p[2048], px3 = p[3072];

        float acc[2][4][4];
#pragma unroll
        for (int m = 0; m < 2; ++m)
#pragma unroll
            for (int g = 0; g < 4; ++g)
#pragma unroll
                for (int r4 = 0; r4 < 4; ++r4) acc[m][g][r4] = 0.f;

        if (t > 0) {
#pragma unroll 2
            for (int kf = 0; kf < 8; ++kf) {
                int k0 = k0base + kf * 16;
                uint32_t ah[2][4], al[2][4];
#pragma unroll
                for (int m = 0; m < 2; ++m) {
                    int base2 = ((m * 16 + (lane >> 2)) * 1024 + k0) / 2 + (lane & 3);
                    ah[m][0] = __ldcg(hHr[rb] + base2);
                    ah[m][1] = __ldcg(hHr[rb] + base2 + 4096);
                    ah[m][2] = __ldcg(hHr[rb] + base2 + 4);
                    ah[m][3] = __ldcg(hHr[rb] + base2 + 4100);
                    al[m][0] = __ldcg(hLr[rb] + base2);
                    al[m][1] = __ldcg(hLr[rb] + base2 + 4096);
                    al[m][2] = __ldcg(hLr[rb] + base2 + 4);
                    al[m][3] = __ldcg(hLr[rb] + base2 + 4100);
                }
                int chunk = k0 >> 6, kin = k0 & 63;
                uint32_t cbs = smb + chunk * 8192;
                uint32_t bh[2][4], bl[2][4];
#pragma unroll
                for (int nt = 0; nt < 2; ++nt) {
                    uint32_t off = swz((unsigned)((nt * 16 + br) * 128 + bc + kin * 2));
                    ldm_x4(bh[nt], cbs + off);
                    ldm_x4(bl[nt], cbs + 4096 + off);
                }
#pragma unroll
                for (int m = 0; m < 2; ++m)
#pragma unroll
                    for (int g = 0; g < 4; ++g) {
                        mma16816(acc[m][g], ah[m], &bh[g >> 1][(g & 1) * 2]);
                        mma16816(acc[m][g], ah[m], &bl[g >> 1][(g & 1) * 2]);
                        mma16816(acc[m][g], al[m], &bh[g >> 1][(g & 1) * 2]);
                    }
            }
        }
#pragma unroll
        for (int m = 0; m < 2; ++m)
#pragma unroll
            for (int g = 0; g < 4; ++g)
#pragma unroll
                for (int r4 = 0; r4 < 4; ++r4)
                    red[((w * 2 + m) * 4 + g) * 128 + lane * 4 + r4] = acc[m][g][r4];
        __syncthreads();
        {
            int r = bb & 15, m = bb >> 4;
            int gl = ((r & 7) << 2) | (hh >> 1);
            int rg = (hh & 1) + 2 * ((r >> 3) & 1);
            float gv[4] = {0.f, 0.f, 0.f, 0.f};
#pragma unroll
            for (int w2 = 0; w2 < 8; ++w2)
#pragma unroll
                for (int g = 0; g < 4; ++g)
                    gv[g] += red[((w2 * 2 + m) * 4 + g) * 128 + gl * 4 + rg];
            float ai = gv[0] + px0;
            float af = gv[1] + px1;
            float agg = gv[2] + px2;
            float ao = gv[3] + px3;
            cc = sigm(af) * cc + sigm(ai) * tanhf(agg);
            float hn = sigm(ao) * tanhf(cc);
            dout[((size_t)bb * 256 + t) * 1024 + j] = hn;
            __nv_bfloat16 hi = __float2bfloat16(hn);
            __nv_bfloat16 lo = __float2bfloat16(hn - __bfloat162float(hi));
            g_hsplitH[rb ^ 1][bb * 1024 + j] = hi;
            g_hsplitL[rb ^ 1][bb * 1024 + j] = lo;
        }
        __threadfence();
        __syncthreads();
        tree_barrier(g_barT, bid, tid, (unsigned)(t + 1), 16u);
    }
}

// ---- persistent sentence BiLSTM recurrence ----
// MODE 0: layer0 (stores h split into stageS2); MODE 1: layer1 (fp32 out + char staging)
template <int MODE>
__global__ void __launch_bounds__(256) sentrec_kernel(
    const float* __restrict__ pre, const float* __restrict__ WhP,
    float* __restrict__ out, const int* __restrict__ words, int base) {
    extern __shared__ unsigned char sms[];
    float4* wS = (float4*)sms;
    float* hsm = (float*)(sms + 65536);
    float* wm = (float*)(sms + 65536 + 16384);
    int tid = threadIdx.x, bid = blockIdx.x;
    int dir = bid >> 5, jb = (bid >> 1) & 15, sb = bid & 1;
    int jl = tid & 15, sq = tid >> 4;
    int s = sb * 16 + sq;
    int j = jb * 16 + jl;

    const float4* Wsrc = (const float4*)(WhP + (size_t)dir * (256 * 256 * 4));
    for (int i = tid; i < 4096; i += 256) {
        int k = i >> 4;
        wS[i] = Wsrc[k * 256 + jb * 16 + (i & 15)];
    }
    if (MODE == 1) {
        for (int x = tid; x < 4096; x += 256)
            wm[x] = (words[(sb * 16 + (x >> 8)) * 256 + (x & 255)] != 0) ? 1.f : 0.f;
    }
    float cc = 0.f;
    __syncthreads();

    for (int tt = 0; tt < 16; ++tt) {
        int rb = tt & 1;
        int t = dir ? (15 - tt) : tt;
        if (tt > 0) {
            const float4* src = (const float4*)(g_shs + ((rb * 2 + dir) * 32 + sb * 16) * 256);
            float4* dst = (float4*)hsm;
#pragma unroll
            for (int i = 0; i < 4; ++i) dst[tid + i * 256] = __ldcg(src + tid + i * 256);
            __syncthreads();
        }
        size_t pb = ((size_t)(s * 16 + t) * 2 + dir) * 1024 + j;
        float ai = pre[pb], af = pre[pb + 256], ag = pre[pb + 512], ao = pre[pb + 768];
        if (tt > 0) {
#pragma unroll 8
            for (int k = 0; k < 256; ++k) {
                float4 w = wS[k * 16 + jl];
                float hk = hsm[sq * 256 + k];
                ai += hk * w.x; af += hk * w.y; ag += hk * w.z; ao += hk * w.w;
            }
        }
        float cv = sigm(af) * cc + sigm(ai) * tanhf(ag);
        float hn = sigm(ao) * tanhf(cv);
        cc = cv;
        g_shs[(((rb ^ 1) * 2 + dir) * 32 + s) * 256 + j] = hn;
        if (MODE == 0) {
            int r = s * 16 + t, kp = dir * 256 + j;
            split_store_half(g_stageS2 + ((size_t)((r >> 7) * 8 + (kp >> 6))) * PAIR_BYTES,
                             r & 127, kp & 63, hn);
        } else {
            out[((size_t)s * 16 + t) * 512 + dir * 256 + j] = hn;
            float v1 = __shfl_down_sync(0xffffffffu, hn, 1);
            if (!(jl & 1)) {
                int kp = 32 + dir * 256 + j;
                int rbrow = (s * 16 + t) * 16;
                int blk = rbrow >> 7;
#pragma unroll
                for (int tw = 0; tw < 16; ++tw) {
                    float m = wm[sq * 256 + t * 16 + tw];
                    split_store_pair(g_stageA, NCH_W0, blk, (rbrow & 127) + tw, kp, hn * m, v1 * m);
                }
            }
        }
        __threadfence();
        __syncthreads();
        tree_barrier(g_barT3, bid, tid, (unsigned)(base + tt + 1), 8u);
    }
}

// ---- attention ----
__global__ void attention_kernel(const float* __restrict__ q, const float* __restrict__ sent_enc,
                                 const int* __restrict__ words, float* __restrict__ map_out) {
    int bi = blockIdx.x, b = bi >> 4, i = bi & 15;
    __shared__ float se[16 * 513];
    __shared__ float sc[16][16];
    __shared__ float mp[16][16];
    __shared__ int kv[16];
    for (int x = threadIdx.x; x < 16 * 512; x += 256) {
        int jj = x >> 9, d = x & 511;
        se[jj * 513 + d] = sent_enc[((size_t)b * 16 + jj) * 512 + d];
    }
    if (threadIdx.x < 16) {
        int jj = threadIdx.x, any = 0;
        for (int tw = 0; tw < 16; ++tw) any |= (words[(b * 16 + jj) * 16 + tw] != 0);
        kv[jj] = any;
    }
    __syncthreads();
    {
        int cdx = threadIdx.x >> 4, jj = threadIdx.x & 15;
        const float* qr = q + ((size_t)bi * 16 + cdx) * 512;
        const float* ser = se + jj * 513;
        float s = 0.f;
#pragma unroll 4
        for (int d = 0; d < 512; ++d) s += qr[d] * ser[d];
        sc[cdx][jj] = s;
    }
    __syncthreads();
    if (threadIdx.x < 16) {
        int cdx = threadIdx.x;
        float v[16], m = -1e30f;
#pragma unroll
        for (int jj = 0; jj < 16; ++jj) {
            bool valid = (kv[jj] != 0) && (jj != i);
            v[jj] = valid ? sc[cdx][jj] : -1e9f;
            m = fmaxf(m, v[jj]);
        }
        float sum = 0.f;
#pragma unroll
        for (int jj = 0; jj < 16; ++jj) { v[jj] = expf(v[jj] - m); sum += v[jj]; }
        float inv = 1.f / sum;
#pragma unroll
        for (int jj = 0; jj < 16; ++jj) mp[cdx][jj] = v[jj] * inv;
    }
    __syncthreads();
    if (map_out != nullptr && threadIdx.x < 256) {
        int x = threadIdx.x;
        map_out[(size_t)bi * 256 + x] = mp[x >> 4][x & 15];
    }
    for (int x = threadIdx.x; x < 16 * 512; x += 256) {
        int cdx = x >> 9, d = x & 511;
        float s = 0.f;
#pragma unroll
        for (int jj = 0; jj < 16; ++jj) s += mp[cdx][jj] * se[jj * 513 + d];
        int r = bi * 16 + cdx;
        split_store_half(g_stageD + ((size_t)(r >> 7) * 25 + (d >> 6)) * PAIR_BYTES,
                         r & 127, d & 63, s);
    }
}

// ---- classifier: warp per row ----
__global__ void __launch_bounds__(256) classifier_kernel(
    const float* __restrict__ dec_out, const float* __restrict__ Wt,
    const float* __restrict__ bias, float* __restrict__ out) {
    __shared__ float res[8][16];
    int w = threadIdx.x >> 5, lane = threadIdx.x & 31;
    int m = blockIdx.x * 8 + w;
    const float4* x4 = (const float4*)(dec_out + (size_t)m * 1024);
    float4 xv[8];
#pragma unroll
    for (int i = 0; i < 8; ++i) xv[i] = x4[lane + i * 32];
#pragma unroll
    for (int n = 0; n < 15; ++n) {
        const float4* w4 = (const float4*)(Wt + n * 1024);
        float s = 0.f;
#pragma unroll
        for (int i = 0; i < 8; ++i) {
            float4 b = w4[lane + i * 32];
            s += xv[i].x * b.x + xv[i].y * b.y + xv[i].z * b.z + xv[i].w * b.w;
        }
#pragma unroll
        for (int o = 16; o; o >>= 1) s += __shfl_xor_sync(0xffffffffu, s, o);
        if (lane == 0) res[w][n] = s + bias[n];
    }
    __syncthreads();
    for (int i = threadIdx.x; i < 120; i += 256) {
        int mr = i / 15, n = i % 15;
        out[(size_t)(blockIdx.x * 8 + mr) * 15 + n] = res[mr][n];
    }
}

// ---- host ----
static void* symp(const void* s) { void* p = nullptr; cudaGetSymbolAddress(&p, s); return p; }

extern "C" void kernel_launch(void* const* d_in, const int* in_sizes, int n_in,
                              void* d_out, int out_size) {
    (void)in_sizes; (void)n_in;
    const int* sents = (const int*)d_in[0];
    const int* words = (const int*)d_in[1];
    const int* labels = (const int*)d_in[2];
    const float* word_embs = (const float*)d_in[3];
    const float* char_table = (const float*)d_in[4];
    const float* sWx0 = (const float*)d_in[5];
    const float* sWh0 = (const float*)d_in[6];
    const float* sb0 = (const float*)d_in[7];
    const float* sWx1 = (const float*)d_in[8];
    const float* sWh1 = (const float*)d_in[9];
    const float* sb1 = (const float*)d_in[10];
    const float* wWx0 = (const float*)d_in[11];
    const float* wWh0 = (const float*)d_in[12];
    const float* wb0 = (const float*)d_in[13];
    const float* wWx1 = (const float*)d_in[14];
    const float* wWh1 = (const float*)d_in[15];
    const float* wb1 = (const float*)d_in[16];
    const float* Wq = (const float*)d_in[17];
    const float* dWx = (const float*)d_in[18];
    const float* dWh = (const float*)d_in[19];
    const float* db = (const float*)d_in[20];
    const float* clsW = (const float*)d_in[21];
    const float* clsb = (const float*)d_in[22];
    float* out = (float*)d_out;

    float* pre_s = (float*)symp(g_pre_s);
    float* sent_enc = (float*)symp(g_sent_enc);
    float* pre_w = (float*)symp(g_pre_w);
    float* qbuf = (float*)symp(g_q);
    float* pre_d = (float*)symp(g_pre_d);
    float* dec_out = (float*)symp(g_dec_out);
    float* sWh0P = (float*)symp(g_sWh0P);
    float* sWh1P = (float*)symp(g_sWh1P);
    float* clsWT = (float*)symp(g_clsWT);
    const unsigned char* stA = (const unsigned char*)symp(g_stageA);
    const unsigned char* stD = (const unsigned char*)symp(g_stageD);
    const unsigned char* stS = (const unsigned char*)symp(g_stageS);
    const unsigned char* stS2 = (const unsigned char*)symp(g_stageS2);
    const unsigned char* stBs0 = (const unsigned char*)symp(g_stB_s0);
    const unsigned char* stBs1 = (const unsigned char*)symp(g_stB_s1);
    const unsigned char* stBw0 = (const unsigned char*)symp(g_stB_w0);
    const unsigned char* stBw1 = (const unsigned char*)symp(g_stB_w1);
    const unsigned char* stBq = (const unsigned char*)symp(g_stB_q);
    const unsigned char* stBdec = (const unsigned char*)symp(g_stB_dec);
    const unsigned char* stWw = (const unsigned char*)symp(g_stWw);

    cudaFuncSetAttribute(tgemm_kernel, cudaFuncAttributeMaxDynamicSharedMemorySize, TG_SMEM);
    cudaFuncSetAttribute(dec_persist_kernel, cudaFuncAttributeMaxDynamicSharedMemorySize, DEC_SMEM);
    cudaFuncSetAttribute(wordrec_kernel, cudaFuncAttributeMaxDynamicSharedMemorySize, WR_SMEM);
    cudaFuncSetAttribute(sentrec_kernel<0>, cudaFuncAttributeMaxDynamicSharedMemorySize, SR_SMEM);
    cudaFuncSetAttribute(sentrec_kernel<1>, cudaFuncAttributeMaxDynamicSharedMemorySize, SR_SMEM);

    const size_t wwLayer = 2ul * 16 * 8 * PAIR_BYTES;

    prep_kernel<<<PREP_BLOCKS, 256>>>(sWh0, sWh1, wWh0, wWh1, dWh, wWx0, wWx1, Wq, dWx,
                                      words, char_table, sents, word_embs, labels, clsW,
                                      sWx0, sWx1);
    // sentence encoder (HMMA pre-gates + persistent recurrences)
    tgemm_kernel<<<dim3(16, 4), 256, TG_SMEM>>>(stS, stBs0, sb0, pre_s, 2048, 5);
    sentrec_kernel<0><<<64, 256, SR_SMEM>>>(pre_s, sWh0P, nullptr, nullptr, 0);
    tgemm_kernel<<<dim3(16, 4), 256, TG_SMEM>>>(stS2, stBs1, sb1, pre_s, 2048, 8);
    sentrec_kernel<1><<<64, 256, SR_SMEM>>>(pre_s, sWh1P, sent_enc, words, 16);
    // word layer 0
    tgemm_kernel<<<dim3(32, 64), 256, TG_SMEM>>>(stA, stBw0, wb0, pre_w, 4096, NCH_W0);
    wordrec_kernel<<<128, 256, WR_SMEM>>>(stWw, pre_w, 0, 0);
    // word layer 1
    tgemm_kernel<<<dim3(32, 64), 256, TG_SMEM>>>(stA, stBw1, wb1, pre_w, 4096, NCH_W1);
    wordrec_kernel<<<128, 256, WR_SMEM>>>(stWw + wwLayer, pre_w, 1, 16);
    // attention
    tgemm_kernel<<<dim3(4, 64), 256, TG_SMEM>>>(stA, stBq, nullptr, qbuf, 512, NCH_Q);
    float* map_out = (out_size >= (NR_ * 15 + 131072)) ? (out + NR_ * 15) : nullptr;
    attention_kernel<<<NSEQ_, 256>>>(qbuf, sent_enc, words, map_out);
    // decoder
    tgemm_kernel<<<dim3(32, 64), 256, TG_SMEM>>>(stD, stBdec, db, pre_d, 4096, NCH_DEC);
    dec_persist_kernel<<<128, 256, DEC_SMEM>>>(pre_d, dec_out);
    classifier_kernel<<<NR_ / 8, 256>>>(dec_out, clsWT, clsb, out);
}